// round 1
// baseline (speedup 1.0000x reference)
#include <cuda_runtime.h>
#include <math.h>

// Problem constants
#define BB   32
#define NN   1024          // NQ == NK
#define DD   512           // DQ == DK == DV
#define HH   8
#define HD   64            // DV / H
#define MR   (BB * NN)     // 32768 rows
#define HB   (HH * BB)     // 256 (head,batch) pairs

// ---------------------------------------------------------------------------
// Scratch (device globals — no allocation allowed)
// ---------------------------------------------------------------------------
__device__ float g_q[(size_t)MR * DD];    // Q @ Wq + bq
__device__ float g_k[(size_t)MR * DD];    // K @ Wk + bk
__device__ float g_v[(size_t)MR * DD];    // K @ Wv + bv
__device__ float g_o[(size_t)MR * DD];    // merged attention output (pre-LN0)
__device__ float g_x[(size_t)MR * DD];    // LN0 output
__device__ float g_y[(size_t)MR * DD];    // x @ Wo + bo
__device__ float g_s[(size_t)HB * NN * NN];  // S^T: [hb][k][q]  (1 GiB)
__device__ float g_mx[HB * NN];           // per (hb,k): max over q
__device__ float g_rz[HB * NN];           // per (hb,k): 1 / sum_q exp(s - m)

// ---------------------------------------------------------------------------
// f32x2 packed-FMA helpers (sm_100+ PTX; FFMA2 doubles fp32 throughput)
// ---------------------------------------------------------------------------
__device__ __forceinline__ unsigned long long splat2(float a) {
    unsigned long long r;
    asm("mov.b64 %0, {%1, %1};" : "=l"(r) : "f"(a));
    return r;
}
__device__ __forceinline__ void fma2(unsigned long long& c,
                                     unsigned long long a,
                                     unsigned long long b) {
    asm("fma.rn.f32x2 %0, %1, %2, %0;" : "+l"(c) : "l"(a), "l"(b));
}
__device__ __forceinline__ float2 unpack2(unsigned long long v) {
    float2 f;
    asm("mov.b64 {%0, %1}, %2;" : "=f"(f.x), "=f"(f.y) : "l"(v));
    return f;
}

// ---------------------------------------------------------------------------
// Kernel 1: C[M,512] = A[M,512] @ W[512,512] + bias
//   sel 0 -> g_q (A = Q), 1 -> g_k (A = K), 2 -> g_v (A = K), 3 -> g_y (A = g_x)
//   128x128 tile, BK=16, 256 threads, 8x8 per thread (as 8x4 f32x2 pairs)
// ---------------------------------------------------------------------------
__global__ __launch_bounds__(256, 2)
void gemm512(const float* __restrict__ Ain, const float* __restrict__ W,
             const float* __restrict__ bias, int sel) {
    const float* A = (sel == 3) ? g_x : Ain;
    float* C = (sel == 0) ? g_q : (sel == 1) ? g_k : (sel == 2) ? g_v : g_y;

    const int bm = blockIdx.y * 128;
    const int bn = blockIdx.x * 128;

    __shared__ float As[16][128];   // transposed: As[k][m]
    __shared__ float Bs[16][128];   // Bs[k][n]

    const int tid = threadIdx.x;
    const int ty = tid >> 4;        // 0..15 (M direction, x8)
    const int tx = tid & 15;        // 0..15 (N direction, x8)

    unsigned long long acc[8][4];
    #pragma unroll
    for (int i = 0; i < 8; i++)
        #pragma unroll
        for (int j = 0; j < 4; j++) acc[i][j] = 0ull;

    for (int k0 = 0; k0 < 512; k0 += 16) {
        #pragma unroll
        for (int t = 0; t < 2; t++) {
            int task = tid + t * 256;
            int r = task >> 2;            // 0..127
            int c = (task & 3) * 4;       // 0,4,8,12
            float4 v = *(const float4*)&A[(size_t)(bm + r) * 512 + k0 + c];
            As[c + 0][r] = v.x; As[c + 1][r] = v.y;
            As[c + 2][r] = v.z; As[c + 3][r] = v.w;
        }
        #pragma unroll
        for (int t = 0; t < 2; t++) {
            int task = tid + t * 256;
            int r = task >> 5;            // 0..15
            int c = (task & 31) * 4;      // 0..124
            *(float4*)&Bs[r][c] = *(const float4*)&W[(size_t)(k0 + r) * 512 + bn + c];
        }
        __syncthreads();
        #pragma unroll
        for (int kk = 0; kk < 16; kk++) {
            float4 a0 = *(const float4*)&As[kk][ty * 8];
            float4 a1 = *(const float4*)&As[kk][ty * 8 + 4];
            ulonglong2 b0 = *(const ulonglong2*)&Bs[kk][tx * 8];
            ulonglong2 b1 = *(const ulonglong2*)&Bs[kk][tx * 8 + 4];
            unsigned long long av[8] = {splat2(a0.x), splat2(a0.y), splat2(a0.z), splat2(a0.w),
                                        splat2(a1.x), splat2(a1.y), splat2(a1.z), splat2(a1.w)};
            #pragma unroll
            for (int i = 0; i < 8; i++) {
                fma2(acc[i][0], av[i], b0.x);
                fma2(acc[i][1], av[i], b0.y);
                fma2(acc[i][2], av[i], b1.x);
                fma2(acc[i][3], av[i], b1.y);
            }
        }
        __syncthreads();
    }

    const float4 bi0 = *(const float4*)&bias[bn + tx * 8];
    const float4 bi1 = *(const float4*)&bias[bn + tx * 8 + 4];
    #pragma unroll
    for (int i = 0; i < 8; i++) {
        float2 p0 = unpack2(acc[i][0]);
        float2 p1 = unpack2(acc[i][1]);
        float2 p2 = unpack2(acc[i][2]);
        float2 p3 = unpack2(acc[i][3]);
        float4 o0 = {p0.x + bi0.x, p0.y + bi0.y, p1.x + bi0.z, p1.y + bi0.w};
        float4 o1 = {p2.x + bi1.x, p2.y + bi1.y, p3.x + bi1.z, p3.y + bi1.w};
        size_t row = (size_t)(bm + ty * 8 + i);
        *(float4*)&C[row * 512 + bn + tx * 8]     = o0;
        *(float4*)&C[row * 512 + bn + tx * 8 + 4] = o1;
    }
}

// ---------------------------------------------------------------------------
// Kernel 2: S^T[hb][k][q] = (1/sqrt(512)) * sum_d kh[k][d] * qh[q][d]
//   per (hb): M=1024 (k), N=1024 (q), Kdim=64 (d). Tile 128x128, BK=16.
// ---------------------------------------------------------------------------
__global__ __launch_bounds__(256, 2)
void scores_kernel() {
    const int hb = blockIdx.z;
    const int h = hb >> 5;
    const int b = hb & 31;
    const int kbase = blockIdx.y * 128;
    const int qbase = blockIdx.x * 128;

    const float* Kp = g_k + (size_t)b * NN * 512 + h * 64;
    const float* Qp = g_q + (size_t)b * NN * 512 + h * 64;

    __shared__ float As[16][128];   // [d][k]
    __shared__ float Bs[16][128];   // [d][q]

    const int tid = threadIdx.x;
    const int ty = tid >> 4;
    const int tx = tid & 15;

    unsigned long long acc[8][4];
    #pragma unroll
    for (int i = 0; i < 8; i++)
        #pragma unroll
        for (int j = 0; j < 4; j++) acc[i][j] = 0ull;

    for (int k0 = 0; k0 < 64; k0 += 16) {
        #pragma unroll
        for (int t = 0; t < 2; t++) {
            int task = tid + t * 256;
            int r = task >> 2;
            int c = (task & 3) * 4;
            float4 v = *(const float4*)&Kp[(size_t)(kbase + r) * 512 + k0 + c];
            As[c + 0][r] = v.x; As[c + 1][r] = v.y;
            As[c + 2][r] = v.z; As[c + 3][r] = v.w;
            float4 u = *(const float4*)&Qp[(size_t)(qbase + r) * 512 + k0 + c];
            Bs[c + 0][r] = u.x; Bs[c + 1][r] = u.y;
            Bs[c + 2][r] = u.z; Bs[c + 3][r] = u.w;
        }
        __syncthreads();
        #pragma unroll
        for (int kk = 0; kk < 16; kk++) {
            float4 a0 = *(const float4*)&As[kk][ty * 8];
            float4 a1 = *(const float4*)&As[kk][ty * 8 + 4];
            ulonglong2 b0 = *(const ulonglong2*)&Bs[kk][tx * 8];
            ulonglong2 b1 = *(const ulonglong2*)&Bs[kk][tx * 8 + 4];
            unsigned long long av[8] = {splat2(a0.x), splat2(a0.y), splat2(a0.z), splat2(a0.w),
                                        splat2(a1.x), splat2(a1.y), splat2(a1.z), splat2(a1.w)};
            #pragma unroll
            for (int i = 0; i < 8; i++) {
                fma2(acc[i][0], av[i], b0.x);
                fma2(acc[i][1], av[i], b0.y);
                fma2(acc[i][2], av[i], b1.x);
                fma2(acc[i][3], av[i], b1.y);
            }
        }
        __syncthreads();
    }

    const float scale = 0.04419417382415922f;  // 1/sqrt(512)
    float* Sp = g_s + (size_t)hb * NN * NN;
    #pragma unroll
    for (int i = 0; i < 8; i++) {
        float2 p0 = unpack2(acc[i][0]);
        float2 p1 = unpack2(acc[i][1]);
        float2 p2 = unpack2(acc[i][2]);
        float2 p3 = unpack2(acc[i][3]);
        float4 o0 = {p0.x * scale, p0.y * scale, p1.x * scale, p1.y * scale};
        float4 o1 = {p2.x * scale, p2.y * scale, p3.x * scale, p3.y * scale};
        size_t row = (size_t)(kbase + ty * 8 + i);
        *(float4*)&Sp[row * NN + qbase + tx * 8]     = o0;
        *(float4*)&Sp[row * NN + qbase + tx * 8 + 4] = o1;
    }
}

// ---------------------------------------------------------------------------
// Kernel 3: per (hb,k) row of S^T (1024 contiguous q): max + 1/sum(exp)
//   one warp per row, 8 rows / 256-thread CTA
// ---------------------------------------------------------------------------
__global__ __launch_bounds__(256)
void stats_kernel() {
    const int row = (blockIdx.x * blockDim.x + threadIdx.x) >> 5;  // 0 .. HB*NN-1
    const int lane = threadIdx.x & 31;
    const float4* p = (const float4*)(g_s + (size_t)row * NN);

    float4 v[8];
    float m = -3.4e38f;
    #pragma unroll
    for (int i = 0; i < 8; i++) {
        v[i] = p[lane + i * 32];
        m = fmaxf(m, fmaxf(fmaxf(v[i].x, v[i].y), fmaxf(v[i].z, v[i].w)));
    }
    #pragma unroll
    for (int off = 16; off > 0; off >>= 1)
        m = fmaxf(m, __shfl_xor_sync(0xFFFFFFFFu, m, off));

    float z = 0.0f;
    #pragma unroll
    for (int i = 0; i < 8; i++) {
        z += __expf(v[i].x - m) + __expf(v[i].y - m)
           + __expf(v[i].z - m) + __expf(v[i].w - m);
    }
    #pragma unroll
    for (int off = 16; off > 0; off >>= 1)
        z += __shfl_xor_sync(0xFFFFFFFFu, z, off);

    if (lane == 0) {
        g_mx[row] = m;
        g_rz[row] = 1.0f / z;
    }
}

// ---------------------------------------------------------------------------
// Kernel 4: O[q,d] = qh[q,d] + sum_k softmax_w(k,q) * vh[k,d]
//   weights applied at smem-load: w = exp(S^T[k][q]-m[k]) * rZ[k]
//   per (hb): M=1024 (q), N=64 (d, full), Kdim=1024 (k). Tile 128x64, BK=16.
//   writes merged layout g_o[(b*N+q)*512 + h*64 + d]
// ---------------------------------------------------------------------------
__global__ __launch_bounds__(256, 2)
void attn_kernel() {
    const int hb = blockIdx.z;
    const int h = hb >> 5;
    const int b = hb & 31;
    const int qbase = blockIdx.x * 128;

    const float* Sp = g_s + (size_t)hb * NN * NN;
    const float* Vp = g_v + (size_t)b * NN * 512 + h * 64;
    const float* mp = g_mx + hb * NN;
    const float* rzp = g_rz + hb * NN;

    __shared__ float Ws[16][128];   // softmax weights [k][q]
    __shared__ float Vs[16][64];    // v tile [k][d]

    const int tid = threadIdx.x;
    const int ty = tid >> 4;        // q direction (x8)
    const int tx = tid & 15;        // d direction (x4)

    unsigned long long acc[8][2];
    #pragma unroll
    for (int i = 0; i < 8; i++) { acc[i][0] = 0ull; acc[i][1] = 0ull; }

    for (int k0 = 0; k0 < NN; k0 += 16) {
        #pragma unroll
        for (int t = 0; t < 2; t++) {
            int task = tid + t * 256;
            int r = task >> 5;            // 0..15
            int c = (task & 31) * 4;      // 0..124
            float4 s = *(const float4*)&Sp[(size_t)(k0 + r) * NN + qbase + c];
            float m = mp[k0 + r];
            float rz = rzp[k0 + r];
            float4 w;
            w.x = __expf(s.x - m) * rz;
            w.y = __expf(s.y - m) * rz;
            w.z = __expf(s.z - m) * rz;
            w.w = __expf(s.w - m) * rz;
            *(float4*)&Ws[r][c] = w;
        }
        {
            int r = tid >> 4;             // 0..15
            int c = (tid & 15) * 4;       // 0..60
            *(float4*)&Vs[r][c] = *(const float4*)&Vp[(size_t)(k0 + r) * 512 + c];
        }
        __syncthreads();
        #pragma unroll
        for (int kk = 0; kk < 16; kk++) {
            float4 a0 = *(const float4*)&Ws[kk][ty * 8];
            float4 a1 = *(const float4*)&Ws[kk][ty * 8 + 4];
            ulonglong2 bv = *(const ulonglong2*)&Vs[kk][tx * 4];
            unsigned long long av[8] = {splat2(a0.x), splat2(a0.y), splat2(a0.z), splat2(a0.w),
                                        splat2(a1.x), splat2(a1.y), splat2(a1.z), splat2(a1.w)};
            #pragma unroll
            for (int i = 0; i < 8; i++) {
                fma2(acc[i][0], av[i], bv.x);
                fma2(acc[i][1], av[i], bv.y);
            }
        }
        __syncthreads();
    }

    #pragma unroll
    for (int i = 0; i < 8; i++) {
        size_t idx = (size_t)(b * NN + qbase + ty * 8 + i) * 512 + h * 64 + tx * 4;
        float4 q4 = *(const float4*)&g_q[idx];
        float2 p0 = unpack2(acc[i][0]);
        float2 p1 = unpack2(acc[i][1]);
        float4 o = {p0.x + q4.x, p0.y + q4.y, p1.x + q4.z, p1.y + q4.w};
        *(float4*)&g_o[idx] = o;
    }
}

// ---------------------------------------------------------------------------
// Kernel 5: row LayerNorm over 512 (one warp per row)
//   mode 0: in = g_o                     -> write g_x
//   mode 1: in = g_x + relu(g_y)         -> write out (d_out)
// ---------------------------------------------------------------------------
__global__ __launch_bounds__(256)
void ln_kernel(const float* __restrict__ gamma, const float* __restrict__ beta,
               float* __restrict__ out, int mode) {
    const int row = (blockIdx.x * blockDim.x + threadIdx.x) >> 5;  // 0 .. MR-1
    const int lane = threadIdx.x & 31;

    float4 v[4];
    if (mode == 0) {
        const float4* p = (const float4*)(g_o + (size_t)row * 512);
        #pragma unroll
        for (int i = 0; i < 4; i++) v[i] = p[lane + i * 32];
    } else {
        const float4* px = (const float4*)(g_x + (size_t)row * 512);
        const float4* py = (const float4*)(g_y + (size_t)row * 512);
        #pragma unroll
        for (int i = 0; i < 4; i++) {
            float4 a = px[lane + i * 32];
            float4 b = py[lane + i * 32];
            v[i].x = a.x + fmaxf(b.x, 0.0f);
            v[i].y = a.y + fmaxf(b.y, 0.0f);
            v[i].z = a.z + fmaxf(b.z, 0.0f);
            v[i].w = a.w + fmaxf(b.w, 0.0f);
        }
    }

    float s = 0.0f, ss = 0.0f;
    #pragma unroll
    for (int i = 0; i < 4; i++) {
        s  += v[i].x + v[i].y + v[i].z + v[i].w;
        ss += v[i].x * v[i].x + v[i].y * v[i].y + v[i].z * v[i].z + v[i].w * v[i].w;
    }
    #pragma unroll
    for (int off = 16; off > 0; off >>= 1) {
        s  += __shfl_xor_sync(0xFFFFFFFFu, s, off);
        ss += __shfl_xor_sync(0xFFFFFFFFu, ss, off);
    }
    const float mean = s * (1.0f / 512.0f);
    const float var = ss * (1.0f / 512.0f) - mean * mean;
    const float rstd = rsqrtf(var + 1e-5f);

    float4* dst = (mode == 0) ? (float4*)(g_x + (size_t)row * 512)
                              : (float4*)(out + (size_t)row * 512);
    #pragma unroll
    for (int i = 0; i < 4; i++) {
        int c0 = (lane + i * 32) * 4;
        float4 g4 = *(const float4*)&gamma[c0];
        float4 b4 = *(const float4*)&beta[c0];
        float4 o;
        o.x = (v[i].x - mean) * rstd * g4.x + b4.x;
        o.y = (v[i].y - mean) * rstd * g4.y + b4.y;
        o.z = (v[i].z - mean) * rstd * g4.z + b4.z;
        o.w = (v[i].w - mean) * rstd * g4.w + b4.w;
        dst[lane + i * 32] = o;
    }
}

// ---------------------------------------------------------------------------
// Launch
// ---------------------------------------------------------------------------
extern "C" void kernel_launch(void* const* d_in, const int* in_sizes, int n_in,
                              void* d_out, int out_size) {
    (void)in_sizes; (void)n_in; (void)out_size;
    const float* Q   = (const float*)d_in[0];
    const float* K   = (const float*)d_in[1];
    const float* Wq  = (const float*)d_in[2];
    const float* bq  = (const float*)d_in[3];
    const float* Wk  = (const float*)d_in[4];
    const float* bk  = (const float*)d_in[5];
    const float* Wv  = (const float*)d_in[6];
    const float* bv  = (const float*)d_in[7];
    const float* Wo  = (const float*)d_in[8];
    const float* bo  = (const float*)d_in[9];
    const float* g0  = (const float*)d_in[10];
    const float* be0 = (const float*)d_in[11];
    const float* g1  = (const float*)d_in[12];
    const float* be1 = (const float*)d_in[13];
    float* out = (float*)d_out;

    dim3 gp(4, 256);                         // N/128 x M/128
    gemm512<<<gp, 256>>>(Q, Wq, bq, 0);      // g_q
    gemm512<<<gp, 256>>>(K, Wk, bk, 1);      // g_k
    gemm512<<<gp, 256>>>(K, Wv, bv, 2);      // g_v
    scores_kernel<<<dim3(8, 8, HB), 256>>>();         // S^T into g_s
    stats_kernel<<<(HB * NN) / 8, 256>>>();           // per-column max / 1/Z
    attn_kernel<<<dim3(8, 1, HB), 256>>>();           // g_o = qh + A @ vh (merged)
    ln_kernel<<<MR / 8, 256>>>(g0, be0, out, 0);      // g_x = LN0(g_o)
    gemm512<<<gp, 256>>>(nullptr, Wo, bo, 3);         // g_y = g_x @ Wo + bo
    ln_kernel<<<MR / 8, 256>>>(g1, be1, out, 1);      // out = LN1(g_x + relu(g_y))
}

// round 2
// speedup vs baseline: 1.0005x; 1.0005x over previous
#include <cuda_runtime.h>
#include <math.h>

// Problem constants
#define BB   32
#define NN   1024          // NQ == NK
#define DD   512           // DQ == DK == DV
#define HH   8
#define HD   64            // DV / H
#define MR   (BB * NN)     // 32768 rows
#define HB   (HH * BB)     // 256 (head,batch) pairs

// ---------------------------------------------------------------------------
// Scratch (device globals — no allocation allowed)
// ---------------------------------------------------------------------------
__device__ float g_q[(size_t)MR * DD];    // Q @ Wq + bq
__device__ float g_k[(size_t)MR * DD];    // K @ Wk + bk
__device__ float g_v[(size_t)MR * DD];    // K @ Wv + bv
__device__ float g_o[(size_t)MR * DD];    // merged attention output (pre-LN0)
__device__ float g_x[(size_t)MR * DD];    // LN0 output
__device__ float g_y[(size_t)MR * DD];    // x @ Wo + bo
__device__ float g_s[(size_t)HB * NN * NN];  // S^T: [hb][k][q]  (1 GiB)
__device__ float g_mx[HB * NN];           // per (hb,k): max over q
__device__ float g_rz[HB * NN];           // per (hb,k): 1 / sum_q exp(s - m)

// ---------------------------------------------------------------------------
// f32x2 packed-FMA helpers (sm_100+ PTX; FFMA2 doubles fp32 throughput)
// ---------------------------------------------------------------------------
__device__ __forceinline__ unsigned long long splat2(float a) {
    unsigned long long r;
    asm("mov.b64 %0, {%1, %1};" : "=l"(r) : "f"(a));
    return r;
}
__device__ __forceinline__ void fma2(unsigned long long& c,
                                     unsigned long long a,
                                     unsigned long long b) {
    asm("fma.rn.f32x2 %0, %1, %2, %0;" : "+l"(c) : "l"(a), "l"(b));
}
__device__ __forceinline__ float2 unpack2(unsigned long long v) {
    float2 f;
    asm("mov.b64 {%0, %1}, %2;" : "=f"(f.x), "=f"(f.y) : "l"(v));
    return f;
}

// ---------------------------------------------------------------------------
// Kernel 1: C[M,512] = A[M,512] @ W[512,512] + bias
//   sel 0 -> g_q (A = Q), 1 -> g_k (A = K), 2 -> g_v (A = K), 3 -> g_y (A = g_x)
//   128x128 tile, BK=16, 256 threads, 8x8 per thread (as 8x4 f32x2 pairs)
// ---------------------------------------------------------------------------
__global__ __launch_bounds__(256, 2)
void gemm512(const float* __restrict__ Ain, const float* __restrict__ W,
             const float* __restrict__ bias, int sel) {
    const float* A = (sel == 3) ? g_x : Ain;
    float* C = (sel == 0) ? g_q : (sel == 1) ? g_k : (sel == 2) ? g_v : g_y;

    const int bm = blockIdx.y * 128;
    const int bn = blockIdx.x * 128;

    __shared__ float As[16][128];   // transposed: As[k][m]
    __shared__ float Bs[16][128];   // Bs[k][n]

    const int tid = threadIdx.x;
    const int ty = tid >> 4;        // 0..15 (M direction, x8)
    const int tx = tid & 15;        // 0..15 (N direction, x8)

    unsigned long long acc[8][4];
    #pragma unroll
    for (int i = 0; i < 8; i++)
        #pragma unroll
        for (int j = 0; j < 4; j++) acc[i][j] = 0ull;

    for (int k0 = 0; k0 < 512; k0 += 16) {
        #pragma unroll
        for (int t = 0; t < 2; t++) {
            int task = tid + t * 256;
            int r = task >> 2;            // 0..127
            int c = (task & 3) * 4;       // 0,4,8,12
            float4 v = *(const float4*)&A[(size_t)(bm + r) * 512 + k0 + c];
            As[c + 0][r] = v.x; As[c + 1][r] = v.y;
            As[c + 2][r] = v.z; As[c + 3][r] = v.w;
        }
        #pragma unroll
        for (int t = 0; t < 2; t++) {
            int task = tid + t * 256;
            int r = task >> 5;            // 0..15
            int c = (task & 31) * 4;      // 0..124
            *(float4*)&Bs[r][c] = *(const float4*)&W[(size_t)(k0 + r) * 512 + bn + c];
        }
        __syncthreads();
        #pragma unroll
        for (int kk = 0; kk < 16; kk++) {
            float4 a0 = *(const float4*)&As[kk][ty * 8];
            float4 a1 = *(const float4*)&As[kk][ty * 8 + 4];
            ulonglong2 b0 = *(const ulonglong2*)&Bs[kk][tx * 8];
            ulonglong2 b1 = *(const ulonglong2*)&Bs[kk][tx * 8 + 4];
            unsigned long long av[8] = {splat2(a0.x), splat2(a0.y), splat2(a0.z), splat2(a0.w),
                                        splat2(a1.x), splat2(a1.y), splat2(a1.z), splat2(a1.w)};
            #pragma unroll
            for (int i = 0; i < 8; i++) {
                fma2(acc[i][0], av[i], b0.x);
                fma2(acc[i][1], av[i], b0.y);
                fma2(acc[i][2], av[i], b1.x);
                fma2(acc[i][3], av[i], b1.y);
            }
        }
        __syncthreads();
    }

    const float4 bi0 = *(const float4*)&bias[bn + tx * 8];
    const float4 bi1 = *(const float4*)&bias[bn + tx * 8 + 4];
    #pragma unroll
    for (int i = 0; i < 8; i++) {
        float2 p0 = unpack2(acc[i][0]);
        float2 p1 = unpack2(acc[i][1]);
        float2 p2 = unpack2(acc[i][2]);
        float2 p3 = unpack2(acc[i][3]);
        float4 o0 = {p0.x + bi0.x, p0.y + bi0.y, p1.x + bi0.z, p1.y + bi0.w};
        float4 o1 = {p2.x + bi1.x, p2.y + bi1.y, p3.x + bi1.z, p3.y + bi1.w};
        size_t row = (size_t)(bm + ty * 8 + i);
        *(float4*)&C[row * 512 + bn + tx * 8]     = o0;
        *(float4*)&C[row * 512 + bn + tx * 8 + 4] = o1;
    }
}

// ---------------------------------------------------------------------------
// Kernel 2: S^T[hb][k][q] = (1/sqrt(512)) * sum_d kh[k][d] * qh[q][d]
//   per (hb): M=1024 (k), N=1024 (q), Kdim=64 (d). Tile 128x128, BK=16.
// ---------------------------------------------------------------------------
__global__ __launch_bounds__(256, 2)
void scores_kernel() {
    const int hb = blockIdx.z;
    const int h = hb >> 5;
    const int b = hb & 31;
    const int kbase = blockIdx.y * 128;
    const int qbase = blockIdx.x * 128;

    const float* Kp = g_k + (size_t)b * NN * 512 + h * 64;
    const float* Qp = g_q + (size_t)b * NN * 512 + h * 64;

    __shared__ float As[16][128];   // [d][k]
    __shared__ float Bs[16][128];   // [d][q]

    const int tid = threadIdx.x;
    const int ty = tid >> 4;
    const int tx = tid & 15;

    unsigned long long acc[8][4];
    #pragma unroll
    for (int i = 0; i < 8; i++)
        #pragma unroll
        for (int j = 0; j < 4; j++) acc[i][j] = 0ull;

    for (int k0 = 0; k0 < 64; k0 += 16) {
        #pragma unroll
        for (int t = 0; t < 2; t++) {
            int task = tid + t * 256;
            int r = task >> 2;
            int c = (task & 3) * 4;
            float4 v = *(const float4*)&Kp[(size_t)(kbase + r) * 512 + k0 + c];
            As[c + 0][r] = v.x; As[c + 1][r] = v.y;
            As[c + 2][r] = v.z; As[c + 3][r] = v.w;
            float4 u = *(const float4*)&Qp[(size_t)(qbase + r) * 512 + k0 + c];
            Bs[c + 0][r] = u.x; Bs[c + 1][r] = u.y;
            Bs[c + 2][r] = u.z; Bs[c + 3][r] = u.w;
        }
        __syncthreads();
        #pragma unroll
        for (int kk = 0; kk < 16; kk++) {
            float4 a0 = *(const float4*)&As[kk][ty * 8];
            float4 a1 = *(const float4*)&As[kk][ty * 8 + 4];
            ulonglong2 b0 = *(const ulonglong2*)&Bs[kk][tx * 8];
            ulonglong2 b1 = *(const ulonglong2*)&Bs[kk][tx * 8 + 4];
            unsigned long long av[8] = {splat2(a0.x), splat2(a0.y), splat2(a0.z), splat2(a0.w),
                                        splat2(a1.x), splat2(a1.y), splat2(a1.z), splat2(a1.w)};
            #pragma unroll
            for (int i = 0; i < 8; i++) {
                fma2(acc[i][0], av[i], b0.x);
                fma2(acc[i][1], av[i], b0.y);
                fma2(acc[i][2], av[i], b1.x);
                fma2(acc[i][3], av[i], b1.y);
            }
        }
        __syncthreads();
    }

    const float scale = 0.04419417382415922f;  // 1/sqrt(512)
    float* Sp = g_s + (size_t)hb * NN * NN;
    #pragma unroll
    for (int i = 0; i < 8; i++) {
        float2 p0 = unpack2(acc[i][0]);
        float2 p1 = unpack2(acc[i][1]);
        float2 p2 = unpack2(acc[i][2]);
        float2 p3 = unpack2(acc[i][3]);
        float4 o0 = {p0.x * scale, p0.y * scale, p1.x * scale, p1.y * scale};
        float4 o1 = {p2.x * scale, p2.y * scale, p3.x * scale, p3.y * scale};
        size_t row = (size_t)(kbase + ty * 8 + i);
        *(float4*)&Sp[row * NN + qbase + tx * 8]     = o0;
        *(float4*)&Sp[row * NN + qbase + tx * 8 + 4] = o1;
    }
}

// ---------------------------------------------------------------------------
// Kernel 3: per (hb,k) row of S^T (1024 contiguous q): max + 1/sum(exp)
//   one warp per row, 8 rows / 256-thread CTA
// ---------------------------------------------------------------------------
__global__ __launch_bounds__(256)
void stats_kernel() {
    const int row = (blockIdx.x * blockDim.x + threadIdx.x) >> 5;  // 0 .. HB*NN-1
    const int lane = threadIdx.x & 31;
    const float4* p = (const float4*)(g_s + (size_t)row * NN);

    float4 v[8];
    float m = -3.4e38f;
    #pragma unroll
    for (int i = 0; i < 8; i++) {
        v[i] = p[lane + i * 32];
        m = fmaxf(m, fmaxf(fmaxf(v[i].x, v[i].y), fmaxf(v[i].z, v[i].w)));
    }
    #pragma unroll
    for (int off = 16; off > 0; off >>= 1)
        m = fmaxf(m, __shfl_xor_sync(0xFFFFFFFFu, m, off));

    float z = 0.0f;
    #pragma unroll
    for (int i = 0; i < 8; i++) {
        z += __expf(v[i].x - m) + __expf(v[i].y - m)
           + __expf(v[i].z - m) + __expf(v[i].w - m);
    }
    #pragma unroll
    for (int off = 16; off > 0; off >>= 1)
        z += __shfl_xor_sync(0xFFFFFFFFu, z, off);

    if (lane == 0) {
        g_mx[row] = m;
        g_rz[row] = 1.0f / z;
    }
}

// ---------------------------------------------------------------------------
// Kernel 4: O[q,d] = qh[q,d] + sum_k softmax_w(k,q) * vh[k,d]
//   weights applied at smem-load: w = exp(S^T[k][q]-m[k]) * rZ[k]
//   per (hb): M=1024 (q), N=64 (d, full), Kdim=1024 (k). Tile 128x64, BK=16.
//   writes merged layout g_o[(b*N+q)*512 + h*64 + d]
// ---------------------------------------------------------------------------
__global__ __launch_bounds__(256, 2)
void attn_kernel() {
    const int hb = blockIdx.z;
    const int h = hb >> 5;
    const int b = hb & 31;
    const int qbase = blockIdx.x * 128;

    const float* Sp = g_s + (size_t)hb * NN * NN;
    const float* Vp = g_v + (size_t)b * NN * 512 + h * 64;
    const float* mp = g_mx + hb * NN;
    const float* rzp = g_rz + hb * NN;

    __shared__ float Ws[16][128];   // softmax weights [k][q]
    __shared__ float Vs[16][64];    // v tile [k][d]

    const int tid = threadIdx.x;
    const int ty = tid >> 4;        // q direction (x8)
    const int tx = tid & 15;        // d direction (x4)

    unsigned long long acc[8][2];
    #pragma unroll
    for (int i = 0; i < 8; i++) { acc[i][0] = 0ull; acc[i][1] = 0ull; }

    for (int k0 = 0; k0 < NN; k0 += 16) {
        #pragma unroll
        for (int t = 0; t < 2; t++) {
            int task = tid + t * 256;
            int r = task >> 5;            // 0..15
            int c = (task & 31) * 4;      // 0..124
            float4 s = *(const float4*)&Sp[(size_t)(k0 + r) * NN + qbase + c];
            float m = mp[k0 + r];
            float rz = rzp[k0 + r];
            float4 w;
            w.x = __expf(s.x - m) * rz;
            w.y = __expf(s.y - m) * rz;
            w.z = __expf(s.z - m) * rz;
            w.w = __expf(s.w - m) * rz;
            *(float4*)&Ws[r][c] = w;
        }
        {
            int r = tid >> 4;             // 0..15
            int c = (tid & 15) * 4;       // 0..60
            *(float4*)&Vs[r][c] = *(const float4*)&Vp[(size_t)(k0 + r) * 512 + c];
        }
        __syncthreads();
        #pragma unroll
        for (int kk = 0; kk < 16; kk++) {
            float4 a0 = *(const float4*)&Ws[kk][ty * 8];
            float4 a1 = *(const float4*)&Ws[kk][ty * 8 + 4];
            ulonglong2 bv = *(const ulonglong2*)&Vs[kk][tx * 4];
            unsigned long long av[8] = {splat2(a0.x), splat2(a0.y), splat2(a0.z), splat2(a0.w),
                                        splat2(a1.x), splat2(a1.y), splat2(a1.z), splat2(a1.w)};
            #pragma unroll
            for (int i = 0; i < 8; i++) {
                fma2(acc[i][0], av[i], bv.x);
                fma2(acc[i][1], av[i], bv.y);
            }
        }
        __syncthreads();
    }

    #pragma unroll
    for (int i = 0; i < 8; i++) {
        size_t idx = (size_t)(b * NN + qbase + ty * 8 + i) * 512 + h * 64 + tx * 4;
        float4 q4 = *(const float4*)&g_q[idx];
        float2 p0 = unpack2(acc[i][0]);
        float2 p1 = unpack2(acc[i][1]);
        float4 o = {p0.x + q4.x, p0.y + q4.y, p1.x + q4.z, p1.y + q4.w};
        *(float4*)&g_o[idx] = o;
    }
}

// ---------------------------------------------------------------------------
// Kernel 5: row LayerNorm over 512 (one warp per row)
//   mode 0: in = g_o                     -> write g_x
//   mode 1: in = g_x + relu(g_y)         -> write out (d_out)
// ---------------------------------------------------------------------------
__global__ __launch_bounds__(256)
void ln_kernel(const float* __restrict__ gamma, const float* __restrict__ beta,
               float* __restrict__ out, int mode) {
    const int row = (blockIdx.x * blockDim.x + threadIdx.x) >> 5;  // 0 .. MR-1
    const int lane = threadIdx.x & 31;

    float4 v[4];
    if (mode == 0) {
        const float4* p = (const float4*)(g_o + (size_t)row * 512);
        #pragma unroll
        for (int i = 0; i < 4; i++) v[i] = p[lane + i * 32];
    } else {
        const float4* px = (const float4*)(g_x + (size_t)row * 512);
        const float4* py = (const float4*)(g_y + (size_t)row * 512);
        #pragma unroll
        for (int i = 0; i < 4; i++) {
            float4 a = px[lane + i * 32];
            float4 b = py[lane + i * 32];
            v[i].x = a.x + fmaxf(b.x, 0.0f);
            v[i].y = a.y + fmaxf(b.y, 0.0f);
            v[i].z = a.z + fmaxf(b.z, 0.0f);
            v[i].w = a.w + fmaxf(b.w, 0.0f);
        }
    }

    float s = 0.0f, ss = 0.0f;
    #pragma unroll
    for (int i = 0; i < 4; i++) {
        s  += v[i].x + v[i].y + v[i].z + v[i].w;
        ss += v[i].x * v[i].x + v[i].y * v[i].y + v[i].z * v[i].z + v[i].w * v[i].w;
    }
    #pragma unroll
    for (int off = 16; off > 0; off >>= 1) {
        s  += __shfl_xor_sync(0xFFFFFFFFu, s, off);
        ss += __shfl_xor_sync(0xFFFFFFFFu, ss, off);
    }
    const float mean = s * (1.0f / 512.0f);
    const float var = ss * (1.0f / 512.0f) - mean * mean;
    const float rstd = rsqrtf(var + 1e-5f);

    float4* dst = (mode == 0) ? (float4*)(g_x + (size_t)row * 512)
                              : (float4*)(out + (size_t)row * 512);
    #pragma unroll
    for (int i = 0; i < 4; i++) {
        int c0 = (lane + i * 32) * 4;
        float4 g4 = *(const float4*)&gamma[c0];
        float4 b4 = *(const float4*)&beta[c0];
        float4 o;
        o.x = (v[i].x - mean) * rstd * g4.x + b4.x;
        o.y = (v[i].y - mean) * rstd * g4.y + b4.y;
        o.z = (v[i].z - mean) * rstd * g4.z + b4.z;
        o.w = (v[i].w - mean) * rstd * g4.w + b4.w;
        dst[lane + i * 32] = o;
    }
}

// ---------------------------------------------------------------------------
// Launch
// ---------------------------------------------------------------------------
extern "C" void kernel_launch(void* const* d_in, const int* in_sizes, int n_in,
                              void* d_out, int out_size) {
    (void)in_sizes; (void)n_in; (void)out_size;
    const float* Q   = (const float*)d_in[0];
    const float* K   = (const float*)d_in[1];
    const float* Wq  = (const float*)d_in[2];
    const float* bq  = (const float*)d_in[3];
    const float* Wk  = (const float*)d_in[4];
    const float* bk  = (const float*)d_in[5];
    const float* Wv  = (const float*)d_in[6];
    const float* bv  = (const float*)d_in[7];
    const float* Wo  = (const float*)d_in[8];
    const float* bo  = (const float*)d_in[9];
    const float* g0  = (const float*)d_in[10];
    const float* be0 = (const float*)d_in[11];
    const float* g1  = (const float*)d_in[12];
    const float* be1 = (const float*)d_in[13];
    float* out = (float*)d_out;

    dim3 gp(4, 256);                         // N/128 x M/128
    gemm512<<<gp, 256>>>(Q, Wq, bq, 0);      // g_q
    gemm512<<<gp, 256>>>(K, Wk, bk, 1);      // g_k
    gemm512<<<gp, 256>>>(K, Wv, bv, 2);      // g_v
    scores_kernel<<<dim3(8, 8, HB), 256>>>();         // S^T into g_s
    stats_kernel<<<(HB * NN) / 8, 256>>>();           // per-column max / 1/Z
    attn_kernel<<<dim3(8, 1, HB), 256>>>();           // g_o = qh + A @ vh (merged)
    ln_kernel<<<MR / 8, 256>>>(g0, be0, out, 0);      // g_x = LN0(g_o)
    gemm512<<<gp, 256>>>(nullptr, Wo, bo, 3);         // g_y = g_x @ Wo + bo
    ln_kernel<<<MR / 8, 256>>>(g1, be1, out, 1);      // out = LN1(g_x + relu(g_y))
}

// round 4
// speedup vs baseline: 3.8812x; 3.8792x over previous
#include <cuda_runtime.h>
#include <cuda_fp16.h>
#include <math.h>
#include <stdint.h>

#define BB 32
#define NN 1024
#define DD 512
#define HH 8
#define HD 64
#define MR (BB * NN)
#define HBN (HH * BB)
#define SCALE 0.044194173824159216f
#define LDT 72          // smem row stride in halves (144B, 16B-aligned, padded)

// ---- device-global scratch (no allocation allowed) ------------------------
__device__ float  g_q32[(size_t)MR * DD];
__device__ float  g_o  [(size_t)MR * DD];
__device__ float  g_x32[(size_t)MR * DD];
__device__ float  g_y32[(size_t)MR * DD];
__device__ __half g_x16 [(size_t)MR * DD];
__device__ __half g_qin16[(size_t)MR * DD];
__device__ __half g_kin16[(size_t)MR * DD];
__device__ __half g_q16[(size_t)MR * DD];
__device__ __half g_k16[(size_t)MR * DD];
__device__ __half g_v16[(size_t)MR * DD];
__device__ __half g_vt16[(size_t)MR * DD];   // [(hb*64 + d)][n]
__device__ __half g_wt[4][DD * DD];          // W^T fp16 [n][k]
__device__ float  g_mx[HBN * NN];
__device__ float  g_rz[HBN * NN];

// ---- helpers --------------------------------------------------------------
__device__ __forceinline__ uint32_t s2u(const void* p) {
    uint32_t a;
    asm("{ .reg .u64 t; cvta.to.shared.u64 t, %1; cvt.u32.u64 %0, t; }" : "=r"(a) : "l"(p));
    return a;
}
__device__ __forceinline__ void ldsm4(uint32_t* r, uint32_t a) {
    asm volatile("ldmatrix.sync.aligned.m8n8.x4.shared.b16 {%0,%1,%2,%3}, [%4];"
        : "=r"(r[0]), "=r"(r[1]), "=r"(r[2]), "=r"(r[3]) : "r"(a));
}
__device__ __forceinline__ void mma_(float* c, const uint32_t* a, uint32_t b0, uint32_t b1) {
    asm volatile("mma.sync.aligned.m16n8k16.row.col.f32.f16.f16.f32 "
        "{%0,%1,%2,%3},{%4,%5,%6,%7},{%8,%9},{%0,%1,%2,%3};"
        : "+f"(c[0]), "+f"(c[1]), "+f"(c[2]), "+f"(c[3])
        : "r"(a[0]), "r"(a[1]), "r"(a[2]), "r"(a[3]), "r"(b0), "r"(b1));
}
// FMA-pipe exp (no MUFU): 2^round + deg-5 Taylor on the fraction. rel err ~2e-6.
__device__ __forceinline__ float fexp(float x) {
    x = fmaxf(x, -60.0f);
    float t = fmaf(x, 1.4426950408889634f, 12582912.0f);
    int n = __float_as_int(t) - 0x4B400000;
    float r = t - 12582912.0f;
    float u = fmaf(r, -0.6931471805599453f, x);   // u = x - n*ln2 = f*ln2, |u|<=0.347
    float p = fmaf(u, 1.0f / 120.0f, 1.0f / 24.0f);
    p = fmaf(p, u, 1.0f / 6.0f);
    p = fmaf(p, u, 0.5f);
    p = fmaf(p, u, 1.0f);
    p = fmaf(p, u, 1.0f);
    return __int_as_float(__float_as_int(p) + (n << 23));
}
__device__ __forceinline__ void comb(float& m, float& z, float m2, float z2) {
    float nm = fmaxf(m, m2);
    z = z * fexp(m - nm) + z2 * fexp(m2 - nm);
    m = nm;
}

// ---- small kernels --------------------------------------------------------
__global__ __launch_bounds__(256) void f2h(const float* __restrict__ in, int sel) {
    __half* out = sel ? g_kin16 : g_qin16;
    int i = blockIdx.x * 256 + threadIdx.x;
    float4 v = ((const float4*)in)[i];
    __half2 a = __floats2half2_rn(v.x, v.y), b = __floats2half2_rn(v.z, v.w);
    uint2 u = { *(uint32_t*)&a, *(uint32_t*)&b };
    ((uint2*)out)[i] = u;
}

__global__ __launch_bounds__(256) void wtr(const float* __restrict__ W, int widx) {
    __shared__ float t[32][33];
    const int bx = blockIdx.x * 32, by = blockIdx.y * 32;
    const int tx = threadIdx.x & 31, ty = threadIdx.x >> 5;
    __half* Wt = g_wt[widx];
    #pragma unroll
    for (int i = 0; i < 4; i++)
        t[ty + 8 * i][tx] = W[(size_t)(bx + ty + 8 * i) * DD + by + tx];
    __syncthreads();
    #pragma unroll
    for (int i = 0; i < 4; i++)
        Wt[(size_t)(by + ty + 8 * i) * DD + bx + tx] = __float2half_rn(t[tx][ty + 8 * i]);
}

__global__ __launch_bounds__(256) void vtr() {
    const int hb = blockIdx.y, h = hb >> 5, b = hb & 31, nb = blockIdx.x * 64;
    __shared__ __half t[64][80];
    const int tid = threadIdx.x;
    #pragma unroll
    for (int i = 0; i < 2; i++) {
        int idx = tid + i * 256, r = idx >> 3, cc = (idx & 7) * 8;
        *(float4*)&t[r][cc] = *(const float4*)(g_v16 + (size_t)(b * NN + nb + r) * DD + h * HD + cc);
    }
    __syncthreads();
    #pragma unroll
    for (int i = 0; i < 2; i++) {
        int idx = tid + i * 256, d = idx >> 3, nn = (idx & 7) * 8;
        __half o[8];
        #pragma unroll
        for (int u = 0; u < 8; u++) o[u] = t[nn + u][d];
        *(float4*)(g_vt16 + (size_t)(hb * 64 + d) * NN + nb + nn) = *(float4*)o;
    }
}

// ---- dense GEMM: C[M,512] = A16 @ Wt^T + bias (HMMA) ----------------------
__global__ __launch_bounds__(256, 2)
void gemm_mma(const float* __restrict__ bias, int selA, int selW, int selOut) {
    __shared__ __half sA[128 * LDT];
    __shared__ __half sB[128 * LDT];
    const __half* A  = (selA == 0) ? g_qin16 : (selA == 1) ? g_kin16 : g_x16;
    const __half* Bt = g_wt[selW];
    float*  C32 = (selOut == 0) ? g_q32 : (selOut == 3) ? g_y32 : nullptr;
    __half* C16 = (selOut == 0) ? g_q16 : (selOut == 1) ? g_k16 : (selOut == 2) ? g_v16 : nullptr;

    const int tid = threadIdx.x, wid = tid >> 5, lane = tid & 31;
    const int wm = wid & 1, wn = wid >> 1;
    const int bm = blockIdx.y * 128, bn = blockIdx.x * 128;
    const uint32_t uA = s2u(sA), uB = s2u(sB);
    const int lrA = lane & 15, lcA = (lane >> 4) * 8;
    const int lrB = (lane & 7) + ((lane >> 4) << 3), lcB = ((lane >> 3) & 1) * 8;

    float acc[4][4][4];
    #pragma unroll
    for (int i = 0; i < 4; i++)
        #pragma unroll
        for (int j = 0; j < 4; j++)
            #pragma unroll
            for (int k = 0; k < 4; k++) acc[i][j][k] = 0.0f;

    for (int kc = 0; kc < 8; kc++) {
        #pragma unroll
        for (int t = 0; t < 4; t++) {
            int idx = tid + t * 256, row = idx >> 3, c8 = (idx & 7) * 8;
            *(float4*)&sA[row * LDT + c8] = *(const float4*)&A [(size_t)(bm + row) * DD + kc * 64 + c8];
            *(float4*)&sB[row * LDT + c8] = *(const float4*)&Bt[(size_t)(bn + row) * DD + kc * 64 + c8];
        }
        __syncthreads();
        #pragma unroll
        for (int kk = 0; kk < 4; kk++) {
            uint32_t af[4][4];
            #pragma unroll
            for (int mt = 0; mt < 4; mt++)
                ldsm4(af[mt], uA + ((wm * 64 + mt * 16 + lrA) * LDT + kk * 16 + lcA) * 2);
            #pragma unroll
            for (int p = 0; p < 2; p++) {
                uint32_t bf[4];
                ldsm4(bf, uB + ((wn * 32 + p * 16 + lrB) * LDT + kk * 16 + lcB) * 2);
                #pragma unroll
                for (int mt = 0; mt < 4; mt++) {
                    mma_(acc[mt][p * 2],     af[mt], bf[0], bf[1]);
                    mma_(acc[mt][p * 2 + 1], af[mt], bf[2], bf[3]);
                }
            }
        }
        __syncthreads();
    }
    #pragma unroll
    for (int mt = 0; mt < 4; mt++) {
        int r0 = bm + wm * 64 + mt * 16 + (lane >> 2);
        #pragma unroll
        for (int nt = 0; nt < 4; nt++) {
            int c = bn + wn * 32 + nt * 8 + (lane & 3) * 2;
            float2 bb = *(const float2*)&bias[c];
            float d0 = acc[mt][nt][0] + bb.x, d1 = acc[mt][nt][1] + bb.y;
            float d2 = acc[mt][nt][2] + bb.x, d3 = acc[mt][nt][3] + bb.y;
            if (C32) {
                float2 o0 = {d0, d1}, o1 = {d2, d3};
                *(float2*)&C32[(size_t)r0 * DD + c] = o0;
                *(float2*)&C32[(size_t)(r0 + 8) * DD + c] = o1;
            }
            if (C16) {
                __half2 h0 = __floats2half2_rn(d0, d1), h1 = __floats2half2_rn(d2, d3);
                *(__half2*)&C16[(size_t)r0 * DD + c] = h0;
                *(__half2*)&C16[(size_t)(r0 + 8) * DD + c] = h1;
            }
        }
    }
}

// ---- pass 1: per-(hb,k) softmax stats over q (S^T tiles in registers) -----
__global__ __launch_bounds__(256, 2)
void stats_mma() {
    __shared__ __half sK[128 * LDT];
    __shared__ __half sQ[128 * LDT];
    const int tid = threadIdx.x, wid = tid >> 5, lane = tid & 31;
    const int hb = blockIdx.y, h = hb >> 5, b = hb & 31, kb = blockIdx.x * 128;
    const uint32_t uK = s2u(sK), uQ = s2u(sQ);
    const int lrA = lane & 15, lcA = (lane >> 4) * 8;
    const int lrB = (lane & 7) + ((lane >> 4) << 3), lcB = ((lane >> 3) & 1) * 8;

    #pragma unroll
    for (int t = 0; t < 4; t++) {
        int idx = tid + t * 256, row = idx >> 3, c8 = (idx & 7) * 8;
        *(float4*)&sK[row * LDT + c8] = *(const float4*)&g_k16[(size_t)(b * NN + kb + row) * DD + h * HD + c8];
    }
    __syncthreads();
    uint32_t af[4][4];
    #pragma unroll
    for (int kk = 0; kk < 4; kk++)
        ldsm4(af[kk], uK + ((wid * 16 + lrA) * LDT + kk * 16 + lcA) * 2);

    float m0 = -1e30f, z0 = 0.0f, m1 = -1e30f, z1 = 0.0f;
    for (int qc = 0; qc < 8; qc++) {
        #pragma unroll
        for (int t = 0; t < 4; t++) {
            int idx = tid + t * 256, row = idx >> 3, c8 = (idx & 7) * 8;
            *(float4*)&sQ[row * LDT + c8] = *(const float4*)&g_q16[(size_t)(b * NN + qc * 128 + row) * DD + h * HD + c8];
        }
        __syncthreads();
        float s[16][4];
        #pragma unroll
        for (int i = 0; i < 16; i++)
            #pragma unroll
            for (int j = 0; j < 4; j++) s[i][j] = 0.0f;
        #pragma unroll
        for (int kk = 0; kk < 4; kk++) {
            #pragma unroll
            for (int p = 0; p < 8; p++) {
                uint32_t bf[4];
                ldsm4(bf, uQ + ((p * 16 + lrB) * LDT + kk * 16 + lcB) * 2);
                mma_(s[2 * p],     af[kk], bf[0], bf[1]);
                mma_(s[2 * p + 1], af[kk], bf[2], bf[3]);
            }
        }
        float cm0 = -1e30f, cm1 = -1e30f;
        #pragma unroll
        for (int nt = 0; nt < 16; nt++) {
            cm0 = fmaxf(cm0, fmaxf(s[nt][0], s[nt][1]));
            cm1 = fmaxf(cm1, fmaxf(s[nt][2], s[nt][3]));
        }
        cm0 *= SCALE; cm1 *= SCALE;
        float nm0 = fmaxf(m0, cm0), nm1 = fmaxf(m1, cm1);
        float zz0 = 0.0f, zz1 = 0.0f;
        #pragma unroll
        for (int nt = 0; nt < 16; nt++) {
            zz0 += fexp(fmaf(s[nt][0], SCALE, -nm0)) + fexp(fmaf(s[nt][1], SCALE, -nm0));
            zz1 += fexp(fmaf(s[nt][2], SCALE, -nm1)) + fexp(fmaf(s[nt][3], SCALE, -nm1));
        }
        z0 = z0 * fexp(m0 - nm0) + zz0; m0 = nm0;
        z1 = z1 * fexp(m1 - nm1) + zz1; m1 = nm1;
        __syncthreads();
    }
    #pragma unroll
    for (int d = 1; d <= 2; d <<= 1) {
        float mo = __shfl_xor_sync(0xFFFFFFFFu, m0, d);
        float zo = __shfl_xor_sync(0xFFFFFFFFu, z0, d);
        comb(m0, z0, mo, zo);
        mo = __shfl_xor_sync(0xFFFFFFFFu, m1, d);
        zo = __shfl_xor_sync(0xFFFFFFFFu, z1, d);
        comb(m1, z1, mo, zo);
    }
    if ((lane & 3) == 0) {
        int k = kb + wid * 16 + (lane >> 2);
        g_mx[hb * NN + k] = m0;     g_rz[hb * NN + k] = 1.0f / z0;
        g_mx[hb * NN + k + 8] = m1; g_rz[hb * NN + k + 8] = 1.0f / z1;
    }
}

// ---- pass 2: O = qh + softmax(S) @ V (P stays in registers) ---------------
__global__ __launch_bounds__(256)
void attn_mma() {
    __shared__ __half sQ[128 * LDT];
    __shared__ __half sK[64 * LDT];
    __shared__ __half sV[64 * LDT];
    __shared__ float sM[64], sRz[64];
    const int tid = threadIdx.x, wid = tid >> 5, lane = tid & 31;
    const int hb = blockIdx.y, h = hb >> 5, b = hb & 31, qb = blockIdx.x * 128;
    const uint32_t uQ = s2u(sQ), uK = s2u(sK), uV = s2u(sV);
    const int lrA = lane & 15, lcA = (lane >> 4) * 8;
    const int lrB = (lane & 7) + ((lane >> 4) << 3), lcB = ((lane >> 3) & 1) * 8;

    #pragma unroll
    for (int t = 0; t < 4; t++) {
        int idx = tid + t * 256, row = idx >> 3, c8 = (idx & 7) * 8;
        *(float4*)&sQ[row * LDT + c8] = *(const float4*)&g_q16[(size_t)(b * NN + qb + row) * DD + h * HD + c8];
    }
    __syncthreads();
    uint32_t af[4][4];
    #pragma unroll
    for (int kk = 0; kk < 4; kk++)
        ldsm4(af[kk], uQ + ((wid * 16 + lrA) * LDT + kk * 16 + lcA) * 2);

    float o[8][4];
    #pragma unroll
    for (int i = 0; i < 8; i++)
        #pragma unroll
        for (int j = 0; j < 4; j++) o[i][j] = 0.0f;

    for (int kt = 0; kt < 16; kt++) {
        #pragma unroll
        for (int t = 0; t < 2; t++) {
            int idx = tid + t * 256, row = idx >> 3, c8 = (idx & 7) * 8;
            *(float4*)&sK[row * LDT + c8] = *(const float4*)&g_k16[(size_t)(b * NN + kt * 64 + row) * DD + h * HD + c8];
            *(float4*)&sV[row * LDT + c8] = *(const float4*)&g_vt16[(size_t)(hb * 64 + row) * NN + kt * 64 + c8];
        }
        if (tid < 64) { sM[tid] = g_mx[hb * NN + kt * 64 + tid]; sRz[tid] = g_rz[hb * NN + kt * 64 + tid]; }
        __syncthreads();

        float s[8][4];
        #pragma unroll
        for (int i = 0; i < 8; i++)
            #pragma unroll
            for (int j = 0; j < 4; j++) s[i][j] = 0.0f;
        #pragma unroll
        for (int kk = 0; kk < 4; kk++) {
            #pragma unroll
            for (int p = 0; p < 4; p++) {
                uint32_t bf[4];
                ldsm4(bf, uK + ((p * 16 + lrB) * LDT + kk * 16 + lcB) * 2);
                mma_(s[2 * p],     af[kk], bf[0], bf[1]);
                mma_(s[2 * p + 1], af[kk], bf[2], bf[3]);
            }
        }
        uint32_t aw[4][4];
        #pragma unroll
        for (int nt = 0; nt < 8; nt++) {
            int kl = nt * 8 + (lane & 3) * 2;
            float mk0 = sM[kl], rz0 = sRz[kl];
            float mk1 = sM[kl + 1], rz1 = sRz[kl + 1];
            float w0 = fexp(fmaf(s[nt][0], SCALE, -mk0)) * rz0;
            float w1 = fexp(fmaf(s[nt][1], SCALE, -mk1)) * rz1;
            float w2 = fexp(fmaf(s[nt][2], SCALE, -mk0)) * rz0;
            float w3 = fexp(fmaf(s[nt][3], SCALE, -mk1)) * rz1;
            __half2 hA = __floats2half2_rn(w0, w1), hB = __floats2half2_rn(w2, w3);
            aw[nt >> 1][(nt & 1) * 2 + 0] = *(uint32_t*)&hA;
            aw[nt >> 1][(nt & 1) * 2 + 1] = *(uint32_t*)&hB;
        }
        #pragma unroll
        for (int g = 0; g < 4; g++) {
            #pragma unroll
            for (int p = 0; p < 4; p++) {
                uint32_t bf[4];
                ldsm4(bf, uV + ((p * 16 + lrB) * LDT + g * 16 + lcB) * 2);
                mma_(o[2 * p],     aw[g], bf[0], bf[1]);
                mma_(o[2 * p + 1], aw[g], bf[2], bf[3]);
            }
        }
        __syncthreads();
    }
    int q0 = b * NN + qb + wid * 16 + (lane >> 2);
    #pragma unroll
    for (int nt = 0; nt < 8; nt++) {
        int c = h * HD + nt * 8 + (lane & 3) * 2;
        float2 r0v = *(const float2*)&g_q32[(size_t)q0 * DD + c];
        float2 r1v = *(const float2*)&g_q32[(size_t)(q0 + 8) * DD + c];
        float2 o0 = {o[nt][0] + r0v.x, o[nt][1] + r0v.y};
        float2 o1 = {o[nt][2] + r1v.x, o[nt][3] + r1v.y};
        *(float2*)&g_o[(size_t)q0 * DD + c] = o0;
        *(float2*)&g_o[(size_t)(q0 + 8) * DD + c] = o1;
    }
}

// ---- LayerNorm ------------------------------------------------------------
__global__ __launch_bounds__(256)
void ln_kernel(const float* __restrict__ gamma, const float* __restrict__ beta,
               float* __restrict__ out, int mode) {
    const int row = (blockIdx.x * blockDim.x + threadIdx.x) >> 5;
    const int lane = threadIdx.x & 31;
    float4 v[4];
    if (mode == 0) {
        const float4* p = (const float4*)(g_o + (size_t)row * DD);
        #pragma unroll
        for (int i = 0; i < 4; i++) v[i] = p[lane + i * 32];
    } else {
        const float4* px = (const float4*)(g_x32 + (size_t)row * DD);
        const float4* py = (const float4*)(g_y32 + (size_t)row * DD);
        #pragma unroll
        for (int i = 0; i < 4; i++) {
            float4 a = px[lane + i * 32], bq = py[lane + i * 32];
            v[i].x = a.x + fmaxf(bq.x, 0.0f); v[i].y = a.y + fmaxf(bq.y, 0.0f);
            v[i].z = a.z + fmaxf(bq.z, 0.0f); v[i].w = a.w + fmaxf(bq.w, 0.0f);
        }
    }
    float s = 0.0f, ss = 0.0f;
    #pragma unroll
    for (int i = 0; i < 4; i++) {
        s  += v[i].x + v[i].y + v[i].z + v[i].w;
        ss += v[i].x*v[i].x + v[i].y*v[i].y + v[i].z*v[i].z + v[i].w*v[i].w;
    }
    #pragma unroll
    for (int off = 16; off > 0; off >>= 1) {
        s  += __shfl_xor_sync(0xFFFFFFFFu, s, off);
        ss += __shfl_xor_sync(0xFFFFFFFFu, ss, off);
    }
    const float mean = s * (1.0f / 512.0f);
    const float var  = ss * (1.0f / 512.0f) - mean * mean;
    const float rstd = rsqrtf(var + 1e-5f);
    #pragma unroll
    for (int i = 0; i < 4; i++) {
        int c0 = (lane + i * 32) * 4;
        float4 g4 = *(const float4*)&gamma[c0];
        float4 b4 = *(const float4*)&beta[c0];
        float4 ov;
        ov.x = (v[i].x - mean) * rstd * g4.x + b4.x;
        ov.y = (v[i].y - mean) * rstd * g4.y + b4.y;
        ov.z = (v[i].z - mean) * rstd * g4.z + b4.z;
        ov.w = (v[i].w - mean) * rstd * g4.w + b4.w;
        if (mode == 0) {
            *(float4*)(g_x32 + (size_t)row * DD + c0) = ov;
            __half2 h0 = __floats2half2_rn(ov.x, ov.y), h1 = __floats2half2_rn(ov.z, ov.w);
            uint2 u = { *(uint32_t*)&h0, *(uint32_t*)&h1 };
            *(uint2*)(g_x16 + (size_t)row * DD + c0) = u;
        } else {
            *(float4*)(out + (size_t)row * DD + c0) = ov;
        }
    }
}

// ---- launch ---------------------------------------------------------------
extern "C" void kernel_launch(void* const* d_in, const int* in_sizes, int n_in,
                              void* d_out, int out_size) {
    (void)in_sizes; (void)n_in; (void)out_size;
    const float* Q   = (const float*)d_in[0];
    const float* K   = (const float*)d_in[1];
    const float* Wq  = (const float*)d_in[2];
    const float* bq  = (const float*)d_in[3];
    const float* Wk  = (const float*)d_in[4];
    const float* bk  = (const float*)d_in[5];
    const float* Wv  = (const float*)d_in[6];
    const float* bv  = (const float*)d_in[7];
    const float* Wo  = (const float*)d_in[8];
    const float* bo  = (const float*)d_in[9];
    const float* g0  = (const float*)d_in[10];
    const float* be0 = (const float*)d_in[11];
    const float* g1  = (const float*)d_in[12];
    const float* be1 = (const float*)d_in[13];
    float* out = (float*)d_out;

    const int cvb = (MR * DD / 4) / 256;
    f2h<<<cvb, 256>>>(Q, 0);
    f2h<<<cvb, 256>>>(K, 1);
    wtr<<<dim3(16, 16), 256>>>(Wq, 0);
    wtr<<<dim3(16, 16), 256>>>(Wk, 1);
    wtr<<<dim3(16, 16), 256>>>(Wv, 2);
    wtr<<<dim3(16, 16), 256>>>(Wo, 3);

    dim3 gp(4, 256);
    gemm_mma<<<gp, 256>>>(bq, 0, 0, 0);           // g_q32 + g_q16
    gemm_mma<<<gp, 256>>>(bk, 1, 1, 1);           // g_k16
    gemm_mma<<<gp, 256>>>(bv, 1, 2, 2);           // g_v16
    vtr<<<dim3(16, HBN), 256>>>();                // g_vt16
    stats_mma<<<dim3(8, HBN), 256>>>();           // g_mx, g_rz
    attn_mma<<<dim3(8, HBN), 256>>>();            // g_o
    ln_kernel<<<MR / 8, 256>>>(g0, be0, out, 0);  // g_x32, g_x16
    gemm_mma<<<gp, 256>>>(bo, 2, 3, 3);           // g_y32
    ln_kernel<<<MR / 8, 256>>>(g1, be1, out, 1);  // out
}

// round 5
// speedup vs baseline: 4.4622x; 1.1497x over previous
#include <cuda_runtime.h>
#include <cuda_fp16.h>
#include <math.h>
#include <stdint.h>

#define BB 32
#define NN 1024
#define DD 512
#define HH 8
#define HD 64
#define MR (BB * NN)
#define HBN (HH * BB)
#define SCALE 0.044194173824159216f
#define ES (SCALE * 1.4426950408889634f)   // fold log2(e): exp(s*SCALE) = 2^(s*ES)
#define LDT 72

// ---- device-global scratch -------------------------------------------------
__device__ float  g_q32[(size_t)MR * DD];
__device__ float  g_o  [(size_t)MR * DD];
__device__ float  g_x32[(size_t)MR * DD];
__device__ float  g_y32[(size_t)MR * DD];
__device__ __half g_x16 [(size_t)MR * DD];
__device__ __half g_qin16[(size_t)MR * DD];
__device__ __half g_kin16[(size_t)MR * DD];
__device__ __half g_q16[(size_t)MR * DD];
__device__ __half g_k16[(size_t)MR * DD];
__device__ __half g_v16[(size_t)MR * DD];
__device__ __half g_vt16[(size_t)MR * DD];   // [(hb*64 + d)][n], pre-scaled by rz
__device__ __half g_wt[4][DD * DD];          // W^T fp16 [n][k]
__device__ float  g_rz[HBN * NN];            // per (hb,k): 1 / sum_q exp(s*SCALE)

// ---- helpers ---------------------------------------------------------------
__device__ __forceinline__ uint32_t s2u(const void* p) {
    uint32_t a;
    asm("{ .reg .u64 t; cvta.to.shared.u64 t, %1; cvt.u32.u64 %0, t; }" : "=r"(a) : "l"(p));
    return a;
}
__device__ __forceinline__ void ldsm4(uint32_t* r, uint32_t a) {
    asm volatile("ldmatrix.sync.aligned.m8n8.x4.shared.b16 {%0,%1,%2,%3}, [%4];"
        : "=r"(r[0]), "=r"(r[1]), "=r"(r[2]), "=r"(r[3]) : "r"(a));
}
__device__ __forceinline__ void mma_(float* c, const uint32_t* a, uint32_t b0, uint32_t b1) {
    asm volatile("mma.sync.aligned.m16n8k16.row.col.f32.f16.f16.f32 "
        "{%0,%1,%2,%3},{%4,%5,%6,%7},{%8,%9},{%0,%1,%2,%3};"
        : "+f"(c[0]), "+f"(c[1]), "+f"(c[2]), "+f"(c[3])
        : "r"(a[0]), "r"(a[1]), "r"(a[2]), "r"(a[3]), "r"(b0), "r"(b1));
}
__device__ __forceinline__ float ex2(float x) {   // MUFU pipe
    float r;
    asm("ex2.approx.f32 %0, %1;" : "=f"(r) : "f"(x));
    return r;
}

// ---- small kernels ---------------------------------------------------------
__global__ __launch_bounds__(256) void f2h(const float* __restrict__ in, int sel) {
    __half* out = sel ? g_kin16 : g_qin16;
    int i = blockIdx.x * 256 + threadIdx.x;
    float4 v = ((const float4*)in)[i];
    __half2 a = __floats2half2_rn(v.x, v.y), b = __floats2half2_rn(v.z, v.w);
    uint2 u = { *(uint32_t*)&a, *(uint32_t*)&b };
    ((uint2*)out)[i] = u;
}

__global__ __launch_bounds__(256) void wtr(const float* __restrict__ W, int widx) {
    __shared__ float t[32][33];
    const int bx = blockIdx.x * 32, by = blockIdx.y * 32;
    const int tx = threadIdx.x & 31, ty = threadIdx.x >> 5;
    __half* Wt = g_wt[widx];
    #pragma unroll
    for (int i = 0; i < 4; i++)
        t[ty + 8 * i][tx] = W[(size_t)(bx + ty + 8 * i) * DD + by + tx];
    __syncthreads();
    #pragma unroll
    for (int i = 0; i < 4; i++)
        Wt[(size_t)(by + ty + 8 * i) * DD + bx + tx] = __float2half_rn(t[tx][ty + 8 * i]);
}

// V transpose + fold per-k 1/Z: g_vt16[(hb*64+d)][n] = rz[hb,n] * v16[b*NN+n][h*64+d]
__global__ __launch_bounds__(256) void vtr() {
    const int hb = blockIdx.y, h = hb >> 5, b = hb & 31, nb = blockIdx.x * 64;
    __shared__ __half t[64][80];
    const int tid = threadIdx.x;
    #pragma unroll
    for (int i = 0; i < 2; i++) {
        int idx = tid + i * 256, r = idx >> 3, cc = (idx & 7) * 8;
        float4 v = *(const float4*)(g_v16 + (size_t)(b * NN + nb + r) * DD + h * HD + cc);
        __half2 rz2 = __float2half2_rn(g_rz[hb * NN + nb + r]);
        __half2* h2 = (__half2*)&v;
        #pragma unroll
        for (int j = 0; j < 4; j++) h2[j] = __hmul2(h2[j], rz2);
        *(float4*)&t[r][cc] = v;
    }
    __syncthreads();
    #pragma unroll
    for (int i = 0; i < 2; i++) {
        int idx = tid + i * 256, d = idx >> 3, nn = (idx & 7) * 8;
        __half o[8];
        #pragma unroll
        for (int u = 0; u < 8; u++) o[u] = t[nn + u][d];
        *(float4*)(g_vt16 + (size_t)(hb * 64 + d) * NN + nb + nn) = *(float4*)o;
    }
}

// ---- dense GEMM: C[M,512] = A16 @ Wt^T + bias (HMMA) -----------------------
__global__ __launch_bounds__(256, 2)
void gemm_mma(const float* __restrict__ bias, int selA, int selW, int selOut) {
    __shared__ __half sA[128 * LDT];
    __shared__ __half sB[128 * LDT];
    const __half* A  = (selA == 0) ? g_qin16 : (selA == 1) ? g_kin16 : g_x16;
    const __half* Bt = g_wt[selW];
    float*  C32 = (selOut == 0) ? g_q32 : (selOut == 3) ? g_y32 : nullptr;
    __half* C16 = (selOut == 0) ? g_q16 : (selOut == 1) ? g_k16 : (selOut == 2) ? g_v16 : nullptr;

    const int tid = threadIdx.x, wid = tid >> 5, lane = tid & 31;
    const int wm = wid & 1, wn = wid >> 1;
    const int bm = blockIdx.y * 128, bn = blockIdx.x * 128;
    const uint32_t uA = s2u(sA), uB = s2u(sB);
    const int lrA = lane & 15, lcA = (lane >> 4) * 8;
    const int lrB = (lane & 7) + ((lane >> 4) << 3), lcB = ((lane >> 3) & 1) * 8;

    float acc[4][4][4];
    #pragma unroll
    for (int i = 0; i < 4; i++)
        #pragma unroll
        for (int j = 0; j < 4; j++)
            #pragma unroll
            for (int k = 0; k < 4; k++) acc[i][j][k] = 0.0f;

    for (int kc = 0; kc < 8; kc++) {
        #pragma unroll
        for (int t = 0; t < 4; t++) {
            int idx = tid + t * 256, row = idx >> 3, c8 = (idx & 7) * 8;
            *(float4*)&sA[row * LDT + c8] = *(const float4*)&A [(size_t)(bm + row) * DD + kc * 64 + c8];
            *(float4*)&sB[row * LDT + c8] = *(const float4*)&Bt[(size_t)(bn + row) * DD + kc * 64 + c8];
        }
        __syncthreads();
        #pragma unroll
        for (int kk = 0; kk < 4; kk++) {
            uint32_t af[4][4];
            #pragma unroll
            for (int mt = 0; mt < 4; mt++)
                ldsm4(af[mt], uA + ((wm * 64 + mt * 16 + lrA) * LDT + kk * 16 + lcA) * 2);
            #pragma unroll
            for (int p = 0; p < 2; p++) {
                uint32_t bf[4];
                ldsm4(bf, uB + ((wn * 32 + p * 16 + lrB) * LDT + kk * 16 + lcB) * 2);
                #pragma unroll
                for (int mt = 0; mt < 4; mt++) {
                    mma_(acc[mt][p * 2],     af[mt], bf[0], bf[1]);
                    mma_(acc[mt][p * 2 + 1], af[mt], bf[2], bf[3]);
                }
            }
        }
        __syncthreads();
    }
    #pragma unroll
    for (int mt = 0; mt < 4; mt++) {
        int r0 = bm + wm * 64 + mt * 16 + (lane >> 2);
        #pragma unroll
        for (int nt = 0; nt < 4; nt++) {
            int c = bn + wn * 32 + nt * 8 + (lane & 3) * 2;
            float2 bb = *(const float2*)&bias[c];
            float d0 = acc[mt][nt][0] + bb.x, d1 = acc[mt][nt][1] + bb.y;
            float d2 = acc[mt][nt][2] + bb.x, d3 = acc[mt][nt][3] + bb.y;
            if (C32) {
                float2 o0 = {d0, d1}, o1 = {d2, d3};
                *(float2*)&C32[(size_t)r0 * DD + c] = o0;
                *(float2*)&C32[(size_t)(r0 + 8) * DD + c] = o1;
            }
            if (C16) {
                __half2 h0 = __floats2half2_rn(d0, d1), h1 = __floats2half2_rn(d2, d3);
                *(__half2*)&C16[(size_t)r0 * DD + c] = h0;
                *(__half2*)&C16[(size_t)(r0 + 8) * DD + c] = h1;
            }
        }
    }
}

// ---- pass 1: per-(hb,k) Z = sum_q exp(s*SCALE) (no max; scores are O(1)) ---
__global__ __launch_bounds__(256, 2)
void stats_mma() {
    __shared__ __half sK[128 * LDT];
    __shared__ __half sQ[128 * LDT];
    const int tid = threadIdx.x, wid = tid >> 5, lane = tid & 31;
    const int hb = blockIdx.y, h = hb >> 5, b = hb & 31, kb = blockIdx.x * 128;
    const uint32_t uK = s2u(sK), uQ = s2u(sQ);
    const int lrA = lane & 15, lcA = (lane >> 4) * 8;
    const int lrB = (lane & 7) + ((lane >> 4) << 3), lcB = ((lane >> 3) & 1) * 8;

    #pragma unroll
    for (int t = 0; t < 4; t++) {
        int idx = tid + t * 256, row = idx >> 3, c8 = (idx & 7) * 8;
        *(float4*)&sK[row * LDT + c8] = *(const float4*)&g_k16[(size_t)(b * NN + kb + row) * DD + h * HD + c8];
    }
    __syncthreads();
    uint32_t af[4][4];
    #pragma unroll
    for (int kk = 0; kk < 4; kk++)
        ldsm4(af[kk], uK + ((wid * 16 + lrA) * LDT + kk * 16 + lcA) * 2);

    float z0 = 0.0f, z1 = 0.0f;
    for (int qc = 0; qc < 8; qc++) {
        #pragma unroll
        for (int t = 0; t < 4; t++) {
            int idx = tid + t * 256, row = idx >> 3, c8 = (idx & 7) * 8;
            *(float4*)&sQ[row * LDT + c8] = *(const float4*)&g_q16[(size_t)(b * NN + qc * 128 + row) * DD + h * HD + c8];
        }
        __syncthreads();
        float s[16][4];
        #pragma unroll
        for (int i = 0; i < 16; i++)
            #pragma unroll
            for (int j = 0; j < 4; j++) s[i][j] = 0.0f;
        #pragma unroll
        for (int kk = 0; kk < 4; kk++) {
            #pragma unroll
            for (int p = 0; p < 8; p++) {
                uint32_t bf[4];
                ldsm4(bf, uQ + ((p * 16 + lrB) * LDT + kk * 16 + lcB) * 2);
                mma_(s[2 * p],     af[kk], bf[0], bf[1]);
                mma_(s[2 * p + 1], af[kk], bf[2], bf[3]);
            }
        }
        #pragma unroll
        for (int nt = 0; nt < 16; nt++) {
            z0 += ex2(s[nt][0] * ES) + ex2(s[nt][1] * ES);
            z1 += ex2(s[nt][2] * ES) + ex2(s[nt][3] * ES);
        }
        __syncthreads();
    }
    z0 += __shfl_xor_sync(0xFFFFFFFFu, z0, 1);
    z0 += __shfl_xor_sync(0xFFFFFFFFu, z0, 2);
    z1 += __shfl_xor_sync(0xFFFFFFFFu, z1, 1);
    z1 += __shfl_xor_sync(0xFFFFFFFFu, z1, 2);
    if ((lane & 3) == 0) {
        int k = kb + wid * 16 + (lane >> 2);
        g_rz[hb * NN + k] = 1.0f / z0;
        g_rz[hb * NN + k + 8] = 1.0f / z1;
    }
}

// ---- pass 2: O = qh + exp(S*SCALE) @ V'  (V' pre-scaled by rz) -------------
__global__ __launch_bounds__(256)
void attn_mma() {
    __shared__ __half sQ[128 * LDT];
    __shared__ __half sK[64 * LDT];
    __shared__ __half sV[64 * LDT];
    const int tid = threadIdx.x, wid = tid >> 5, lane = tid & 31;
    const int hb = blockIdx.y, h = hb >> 5, b = hb & 31, qb = blockIdx.x * 128;
    const uint32_t uQ = s2u(sQ), uK = s2u(sK), uV = s2u(sV);
    const int lrA = lane & 15, lcA = (lane >> 4) * 8;
    const int lrB = (lane & 7) + ((lane >> 4) << 3), lcB = ((lane >> 3) & 1) * 8;

    #pragma unroll
    for (int t = 0; t < 4; t++) {
        int idx = tid + t * 256, row = idx >> 3, c8 = (idx & 7) * 8;
        *(float4*)&sQ[row * LDT + c8] = *(const float4*)&g_q16[(size_t)(b * NN + qb + row) * DD + h * HD + c8];
    }
    __syncthreads();
    uint32_t af[4][4];
    #pragma unroll
    for (int kk = 0; kk < 4; kk++)
        ldsm4(af[kk], uQ + ((wid * 16 + lrA) * LDT + kk * 16 + lcA) * 2);

    float o[8][4];
    #pragma unroll
    for (int i = 0; i < 8; i++)
        #pragma unroll
        for (int j = 0; j < 4; j++) o[i][j] = 0.0f;

    for (int kt = 0; kt < 16; kt++) {
        #pragma unroll
        for (int t = 0; t < 2; t++) {
            int idx = tid + t * 256, row = idx >> 3, c8 = (idx & 7) * 8;
            *(float4*)&sK[row * LDT + c8] = *(const float4*)&g_k16[(size_t)(b * NN + kt * 64 + row) * DD + h * HD + c8];
            *(float4*)&sV[row * LDT + c8] = *(const float4*)&g_vt16[(size_t)(hb * 64 + row) * NN + kt * 64 + c8];
        }
        __syncthreads();

        float s[8][4];
        #pragma unroll
        for (int i = 0; i < 8; i++)
            #pragma unroll
            for (int j = 0; j < 4; j++) s[i][j] = 0.0f;
        #pragma unroll
        for (int kk = 0; kk < 4; kk++) {
            #pragma unroll
            for (int p = 0; p < 4; p++) {
                uint32_t bf[4];
                ldsm4(bf, uK + ((p * 16 + lrB) * LDT + kk * 16 + lcB) * 2);
                mma_(s[2 * p],     af[kk], bf[0], bf[1]);
                mma_(s[2 * p + 1], af[kk], bf[2], bf[3]);
            }
        }
        uint32_t aw[4][4];
        #pragma unroll
        for (int nt = 0; nt < 8; nt++) {
            float w0 = ex2(s[nt][0] * ES);
            float w1 = ex2(s[nt][1] * ES);
            float w2 = ex2(s[nt][2] * ES);
            float w3 = ex2(s[nt][3] * ES);
            __half2 hA = __floats2half2_rn(w0, w1), hB = __floats2half2_rn(w2, w3);
            aw[nt >> 1][(nt & 1) * 2 + 0] = *(uint32_t*)&hA;
            aw[nt >> 1][(nt & 1) * 2 + 1] = *(uint32_t*)&hB;
        }
        #pragma unroll
        for (int g = 0; g < 4; g++) {
            #pragma unroll
            for (int p = 0; p < 4; p++) {
                uint32_t bf[4];
                ldsm4(bf, uV + ((p * 16 + lrB) * LDT + g * 16 + lcB) * 2);
                mma_(o[2 * p],     aw[g], bf[0], bf[1]);
                mma_(o[2 * p + 1], aw[g], bf[2], bf[3]);
            }
        }
        __syncthreads();
    }
    int q0 = b * NN + qb + wid * 16 + (lane >> 2);
    #pragma unroll
    for (int nt = 0; nt < 8; nt++) {
        int c = h * HD + nt * 8 + (lane & 3) * 2;
        float2 r0v = *(const float2*)&g_q32[(size_t)q0 * DD + c];
        float2 r1v = *(const float2*)&g_q32[(size_t)(q0 + 8) * DD + c];
        float2 o0 = {o[nt][0] + r0v.x, o[nt][1] + r0v.y};
        float2 o1 = {o[nt][2] + r1v.x, o[nt][3] + r1v.y};
        *(float2*)&g_o[(size_t)q0 * DD + c] = o0;
        *(float2*)&g_o[(size_t)(q0 + 8) * DD + c] = o1;
    }
}

// ---- LayerNorm -------------------------------------------------------------
__global__ __launch_bounds__(256)
void ln_kernel(const float* __restrict__ gamma, const float* __restrict__ beta,
               float* __restrict__ out, int mode) {
    const int row = (blockIdx.x * blockDim.x + threadIdx.x) >> 5;
    const int lane = threadIdx.x & 31;
    float4 v[4];
    if (mode == 0) {
        const float4* p = (const float4*)(g_o + (size_t)row * DD);
        #pragma unroll
        for (int i = 0; i < 4; i++) v[i] = p[lane + i * 32];
    } else {
        const float4* px = (const float4*)(g_x32 + (size_t)row * DD);
        const float4* py = (const float4*)(g_y32 + (size_t)row * DD);
        #pragma unroll
        for (int i = 0; i < 4; i++) {
            float4 a = px[lane + i * 32], bq = py[lane + i * 32];
            v[i].x = a.x + fmaxf(bq.x, 0.0f); v[i].y = a.y + fmaxf(bq.y, 0.0f);
            v[i].z = a.z + fmaxf(bq.z, 0.0f); v[i].w = a.w + fmaxf(bq.w, 0.0f);
        }
    }
    float s = 0.0f, ss = 0.0f;
    #pragma unroll
    for (int i = 0; i < 4; i++) {
        s  += v[i].x + v[i].y + v[i].z + v[i].w;
        ss += v[i].x*v[i].x + v[i].y*v[i].y + v[i].z*v[i].z + v[i].w*v[i].w;
    }
    #pragma unroll
    for (int off = 16; off > 0; off >>= 1) {
        s  += __shfl_xor_sync(0xFFFFFFFFu, s, off);
        ss += __shfl_xor_sync(0xFFFFFFFFu, ss, off);
    }
    const float mean = s * (1.0f / 512.0f);
    const float var  = ss * (1.0f / 512.0f) - mean * mean;
    const float rstd = rsqrtf(var + 1e-5f);
    #pragma unroll
    for (int i = 0; i < 4; i++) {
        int c0 = (lane + i * 32) * 4;
        float4 g4 = *(const float4*)&gamma[c0];
        float4 b4 = *(const float4*)&beta[c0];
        float4 ov;
        ov.x = (v[i].x - mean) * rstd * g4.x + b4.x;
        ov.y = (v[i].y - mean) * rstd * g4.y + b4.y;
        ov.z = (v[i].z - mean) * rstd * g4.z + b4.z;
        ov.w = (v[i].w - mean) * rstd * g4.w + b4.w;
        if (mode == 0) {
            *(float4*)(g_x32 + (size_t)row * DD + c0) = ov;
            __half2 h0 = __floats2half2_rn(ov.x, ov.y), h1 = __floats2half2_rn(ov.z, ov.w);
            uint2 u = { *(uint32_t*)&h0, *(uint32_t*)&h1 };
            *(uint2*)(g_x16 + (size_t)row * DD + c0) = u;
        } else {
            *(float4*)(out + (size_t)row * DD + c0) = ov;
        }
    }
}

// ---- launch ----------------------------------------------------------------
extern "C" void kernel_launch(void* const* d_in, const int* in_sizes, int n_in,
                              void* d_out, int out_size) {
    (void)in_sizes; (void)n_in; (void)out_size;
    const float* Q   = (const float*)d_in[0];
    const float* K   = (const float*)d_in[1];
    const float* Wq  = (const float*)d_in[2];
    const float* bq  = (const float*)d_in[3];
    const float* Wk  = (const float*)d_in[4];
    const float* bk  = (const float*)d_in[5];
    const float* Wv  = (const float*)d_in[6];
    const float* bv  = (const float*)d_in[7];
    const float* Wo  = (const float*)d_in[8];
    const float* bo  = (const float*)d_in[9];
    const float* g0  = (const float*)d_in[10];
    const float* be0 = (const float*)d_in[11];
    const float* g1  = (const float*)d_in[12];
    const float* be1 = (const float*)d_in[13];
    float* out = (float*)d_out;

    const int cvb = (MR * DD / 4) / 256;
    f2h<<<cvb, 256>>>(Q, 0);
    f2h<<<cvb, 256>>>(K, 1);
    wtr<<<dim3(16, 16), 256>>>(Wq, 0);
    wtr<<<dim3(16, 16), 256>>>(Wk, 1);
    wtr<<<dim3(16, 16), 256>>>(Wv, 2);
    wtr<<<dim3(16, 16), 256>>>(Wo, 3);

    dim3 gp(4, 256);
    gemm_mma<<<gp, 256>>>(bq, 0, 0, 0);           // g_q32 + g_q16
    gemm_mma<<<gp, 256>>>(bk, 1, 1, 1);           // g_k16
    gemm_mma<<<gp, 256>>>(bv, 1, 2, 2);           // g_v16
    stats_mma<<<dim3(8, HBN), 256>>>();           // g_rz
    vtr<<<dim3(16, HBN), 256>>>();                // g_vt16 = rz * V^T
    attn_mma<<<dim3(8, HBN), 256>>>();            // g_o
    ln_kernel<<<MR / 8, 256>>>(g0, be0, out, 0);  // g_x32, g_x16
    gemm_mma<<<gp, 256>>>(bo, 2, 3, 3);           // g_y32
    ln_kernel<<<MR / 8, 256>>>(g1, be1, out, 1);  // out
}

// round 6
// speedup vs baseline: 5.2028x; 1.1660x over previous
#include <cuda_runtime.h>
#include <cuda_fp16.h>
#include <math.h>
#include <stdint.h>

#define BB 32
#define NN 1024
#define DD 512
#define HH 8
#define HD 64
#define MR (BB * NN)
#define HBN (HH * BB)
#define SCALE 0.044194173824159216f
#define ES (SCALE * 1.4426950408889634f)
#define LDT 72

// ---- device-global scratch -------------------------------------------------
__device__ float  g_q32[(size_t)MR * DD];
__device__ float  g_o  [(size_t)MR * DD];
__device__ float  g_x32[(size_t)MR * DD];
__device__ float  g_y32[(size_t)MR * DD];
__device__ __half g_x16 [(size_t)MR * DD];
__device__ __half g_qin16[(size_t)MR * DD];
__device__ __half g_kin16[(size_t)MR * DD];
__device__ __half g_q16[(size_t)MR * DD];
__device__ __half g_k16[(size_t)MR * DD];
__device__ __half g_v16[(size_t)MR * DD];
__device__ __half g_vt16[(size_t)MR * DD];   // [(hb*64 + d)][n], pre-scaled by rz
__device__ __half g_wt[4][DD * DD];          // W^T fp16 [n][k]
__device__ float  g_rz[HBN * NN];

// ---- helpers ---------------------------------------------------------------
__device__ __forceinline__ uint32_t s2u(const void* p) {
    uint32_t a;
    asm("{ .reg .u64 t; cvta.to.shared.u64 t, %1; cvt.u32.u64 %0, t; }" : "=r"(a) : "l"(p));
    return a;
}
__device__ __forceinline__ void ldsm4(uint32_t* r, uint32_t a) {
    asm volatile("ldmatrix.sync.aligned.m8n8.x4.shared.b16 {%0,%1,%2,%3}, [%4];"
        : "=r"(r[0]), "=r"(r[1]), "=r"(r[2]), "=r"(r[3]) : "r"(a));
}
__device__ __forceinline__ void mma_(float* c, const uint32_t* a, uint32_t b0, uint32_t b1) {
    asm volatile("mma.sync.aligned.m16n8k16.row.col.f32.f16.f16.f32 "
        "{%0,%1,%2,%3},{%4,%5,%6,%7},{%8,%9},{%0,%1,%2,%3};"
        : "+f"(c[0]), "+f"(c[1]), "+f"(c[2]), "+f"(c[3])
        : "r"(a[0]), "r"(a[1]), "r"(a[2]), "r"(a[3]), "r"(b0), "r"(b1));
}
__device__ __forceinline__ float ex2(float x) {
    float r;
    asm("ex2.approx.f32 %0, %1;" : "=f"(r) : "f"(x));
    return r;
}
__device__ __forceinline__ void cp16(uint32_t d, const void* s) {
    asm volatile("cp.async.cg.shared.global [%0], [%1], 16;" :: "r"(d), "l"(s) : "memory");
}
#define CPCOMMIT() asm volatile("cp.async.commit_group;" ::: "memory")
#define CPWAIT1()  asm volatile("cp.async.wait_group 1;" ::: "memory")
#define CPWAIT0()  asm volatile("cp.async.wait_group 0;" ::: "memory")

extern __shared__ __half dynsm[];

// ---- small kernels ---------------------------------------------------------
__global__ __launch_bounds__(256) void f2h(const float* __restrict__ in, int sel) {
    __half* out = sel ? g_kin16 : g_qin16;
    int i = blockIdx.x * 256 + threadIdx.x;
    float4 v = ((const float4*)in)[i];
    __half2 a = __floats2half2_rn(v.x, v.y), b = __floats2half2_rn(v.z, v.w);
    uint2 u = { *(uint32_t*)&a, *(uint32_t*)&b };
    ((uint2*)out)[i] = u;
}

__global__ __launch_bounds__(256) void wtr(const float* __restrict__ W, int widx) {
    __shared__ float t[32][33];
    const int bx = blockIdx.x * 32, by = blockIdx.y * 32;
    const int tx = threadIdx.x & 31, ty = threadIdx.x >> 5;
    __half* Wt = g_wt[widx];
    #pragma unroll
    for (int i = 0; i < 4; i++)
        t[ty + 8 * i][tx] = W[(size_t)(bx + ty + 8 * i) * DD + by + tx];
    __syncthreads();
    #pragma unroll
    for (int i = 0; i < 4; i++)
        Wt[(size_t)(by + ty + 8 * i) * DD + bx + tx] = __float2half_rn(t[tx][ty + 8 * i]);
}

__global__ __launch_bounds__(256) void vtr() {
    const int hb = blockIdx.y, h = hb >> 5, b = hb & 31, nb = blockIdx.x * 64;
    __shared__ __half t[64][80];
    const int tid = threadIdx.x;
    #pragma unroll
    for (int i = 0; i < 2; i++) {
        int idx = tid + i * 256, r = idx >> 3, cc = (idx & 7) * 8;
        float4 v = *(const float4*)(g_v16 + (size_t)(b * NN + nb + r) * DD + h * HD + cc);
        __half2 rz2 = __float2half2_rn(g_rz[hb * NN + nb + r]);
        __half2* h2 = (__half2*)&v;
        #pragma unroll
        for (int j = 0; j < 4; j++) h2[j] = __hmul2(h2[j], rz2);
        *(float4*)&t[r][cc] = v;
    }
    __syncthreads();
    #pragma unroll
    for (int i = 0; i < 2; i++) {
        int idx = tid + i * 256, d = idx >> 3, nn = (idx & 7) * 8;
        __half o[8];
        #pragma unroll
        for (int u = 0; u < 8; u++) o[u] = t[nn + u][d];
        *(float4*)(g_vt16 + (size_t)(hb * 64 + d) * NN + nb + nn) = *(float4*)o;
    }
}

// ---- dense GEMM (cp.async double-buffered) ---------------------------------
// dyn smem: A buf0 @0, A buf1 @9216, B buf0 @18432, B buf1 @27648 (halves)
__global__ __launch_bounds__(256, 2)
void gemm_mma(const float* __restrict__ bias, int selA, int selW, int selOut) {
    const __half* A  = (selA == 0) ? g_qin16 : (selA == 1) ? g_kin16 : g_x16;
    const __half* Bt = g_wt[selW];
    float*  C32 = (selOut == 0) ? g_q32 : (selOut == 3) ? g_y32 : nullptr;
    __half* C16 = (selOut == 0) ? g_q16 : (selOut == 1) ? g_k16 : (selOut == 2) ? g_v16 : nullptr;

    const int tid = threadIdx.x, wid = tid >> 5, lane = tid & 31;
    const int wm = wid & 1, wn = wid >> 1;
    const int bm = blockIdx.y * 128, bn = blockIdx.x * 128;
    const uint32_t base = s2u(dynsm);
    const uint32_t uA[2] = { base,             base + 18432 };
    const uint32_t uB[2] = { base + 36864,     base + 36864 + 18432 };
    const int lrA = lane & 15, lcA = (lane >> 4) * 8;
    const int lrB = (lane & 7) + ((lane >> 4) << 3), lcB = ((lane >> 3) & 1) * 8;

    auto issue = [&](int kc, int bf) {
        #pragma unroll
        for (int t = 0; t < 4; t++) {
            int idx = tid + t * 256, row = idx >> 3, c8 = (idx & 7) * 8;
            cp16(uA[bf] + (row * LDT + c8) * 2, &A [(size_t)(bm + row) * DD + kc * 64 + c8]);
            cp16(uB[bf] + (row * LDT + c8) * 2, &Bt[(size_t)(bn + row) * DD + kc * 64 + c8]);
        }
        CPCOMMIT();
    };

    float acc[4][4][4];
    #pragma unroll
    for (int i = 0; i < 4; i++)
        #pragma unroll
        for (int j = 0; j < 4; j++)
            #pragma unroll
            for (int k = 0; k < 4; k++) acc[i][j][k] = 0.0f;

    issue(0, 0);
    for (int kc = 0; kc < 8; kc++) {
        if (kc + 1 < 8) { issue(kc + 1, (kc + 1) & 1); CPWAIT1(); }
        else CPWAIT0();
        __syncthreads();
        const uint32_t cA = uA[kc & 1], cB = uB[kc & 1];
        #pragma unroll
        for (int kk = 0; kk < 4; kk++) {
            uint32_t af[4][4];
            #pragma unroll
            for (int mt = 0; mt < 4; mt++)
                ldsm4(af[mt], cA + ((wm * 64 + mt * 16 + lrA) * LDT + kk * 16 + lcA) * 2);
            #pragma unroll
            for (int p = 0; p < 2; p++) {
                uint32_t bf[4];
                ldsm4(bf, cB + ((wn * 32 + p * 16 + lrB) * LDT + kk * 16 + lcB) * 2);
                #pragma unroll
                for (int mt = 0; mt < 4; mt++) {
                    mma_(acc[mt][p * 2],     af[mt], bf[0], bf[1]);
                    mma_(acc[mt][p * 2 + 1], af[mt], bf[2], bf[3]);
                }
            }
        }
        __syncthreads();
    }
    #pragma unroll
    for (int mt = 0; mt < 4; mt++) {
        int r0 = bm + wm * 64 + mt * 16 + (lane >> 2);
        #pragma unroll
        for (int nt = 0; nt < 4; nt++) {
            int c = bn + wn * 32 + nt * 8 + (lane & 3) * 2;
            float2 bb = *(const float2*)&bias[c];
            float d0 = acc[mt][nt][0] + bb.x, d1 = acc[mt][nt][1] + bb.y;
            float d2 = acc[mt][nt][2] + bb.x, d3 = acc[mt][nt][3] + bb.y;
            if (C32) {
                float2 o0 = {d0, d1}, o1 = {d2, d3};
                *(float2*)&C32[(size_t)r0 * DD + c] = o0;
                *(float2*)&C32[(size_t)(r0 + 8) * DD + c] = o1;
            }
            if (C16) {
                __half2 h0 = __floats2half2_rn(d0, d1), h1 = __floats2half2_rn(d2, d3);
                *(__half2*)&C16[(size_t)r0 * DD + c] = h0;
                *(__half2*)&C16[(size_t)(r0 + 8) * DD + c] = h1;
            }
        }
    }
}

// ---- pass 1: Z_k = sum_q exp(s*SCALE) (cp.async double-buffered Q) ---------
// dyn smem: K @0, Q buf0 @9216, Q buf1 @18432 (halves)
__global__ __launch_bounds__(256, 2)
void stats_mma() {
    const int tid = threadIdx.x, wid = tid >> 5, lane = tid & 31;
    const int hb = blockIdx.y, h = hb >> 5, b = hb & 31, kb = blockIdx.x * 128;
    const uint32_t base = s2u(dynsm);
    const uint32_t uK = base;
    const uint32_t uQ[2] = { base + 18432, base + 36864 };
    const int lrA = lane & 15, lcA = (lane >> 4) * 8;
    const int lrB = (lane & 7) + ((lane >> 4) << 3), lcB = ((lane >> 3) & 1) * 8;

    auto issueQ = [&](int qc, int bf) {
        #pragma unroll
        for (int t = 0; t < 4; t++) {
            int idx = tid + t * 256, row = idx >> 3, c8 = (idx & 7) * 8;
            cp16(uQ[bf] + (row * LDT + c8) * 2,
                 &g_q16[(size_t)(b * NN + qc * 128 + row) * DD + h * HD + c8]);
        }
        CPCOMMIT();
    };

    // K tile (group 0) + Q tile 0 (group 1)
    #pragma unroll
    for (int t = 0; t < 4; t++) {
        int idx = tid + t * 256, row = idx >> 3, c8 = (idx & 7) * 8;
        cp16(uK + (row * LDT + c8) * 2,
             &g_k16[(size_t)(b * NN + kb + row) * DD + h * HD + c8]);
    }
    CPCOMMIT();
    issueQ(0, 0);
    CPWAIT1();                // K ready
    __syncthreads();
    uint32_t af[4][4];
    #pragma unroll
    for (int kk = 0; kk < 4; kk++)
        ldsm4(af[kk], uK + ((wid * 16 + lrA) * LDT + kk * 16 + lcA) * 2);

    float z0 = 0.0f, z1 = 0.0f;
    for (int qc = 0; qc < 8; qc++) {
        if (qc + 1 < 8) { issueQ(qc + 1, (qc + 1) & 1); CPWAIT1(); }
        else CPWAIT0();
        __syncthreads();
        const uint32_t cQ = uQ[qc & 1];
        float s[16][4];
        #pragma unroll
        for (int i = 0; i < 16; i++)
            #pragma unroll
            for (int j = 0; j < 4; j++) s[i][j] = 0.0f;
        #pragma unroll
        for (int kk = 0; kk < 4; kk++) {
            #pragma unroll
            for (int p = 0; p < 8; p++) {
                uint32_t bf[4];
                ldsm4(bf, cQ + ((p * 16 + lrB) * LDT + kk * 16 + lcB) * 2);
                mma_(s[2 * p],     af[kk], bf[0], bf[1]);
                mma_(s[2 * p + 1], af[kk], bf[2], bf[3]);
            }
        }
        #pragma unroll
        for (int nt = 0; nt < 16; nt++) {
            z0 += ex2(s[nt][0] * ES) + ex2(s[nt][1] * ES);
            z1 += ex2(s[nt][2] * ES) + ex2(s[nt][3] * ES);
        }
        __syncthreads();
    }
    z0 += __shfl_xor_sync(0xFFFFFFFFu, z0, 1);
    z0 += __shfl_xor_sync(0xFFFFFFFFu, z0, 2);
    z1 += __shfl_xor_sync(0xFFFFFFFFu, z1, 1);
    z1 += __shfl_xor_sync(0xFFFFFFFFu, z1, 2);
    if ((lane & 3) == 0) {
        int k = kb + wid * 16 + (lane >> 2);
        g_rz[hb * NN + k] = 1.0f / z0;
        g_rz[hb * NN + k + 8] = 1.0f / z1;
    }
}

// ---- pass 2: O = qh + exp(S*SCALE) @ V' (cp.async double-buffered K/V) -----
// dyn smem: Q @0, K buf{0,1} @9216/@13824, V buf{0,1} @18432/@23040 (halves)
__global__ __launch_bounds__(256)
void attn_mma() {
    const int tid = threadIdx.x, wid = tid >> 5, lane = tid & 31;
    const int hb = blockIdx.y, h = hb >> 5, b = hb & 31, qb = blockIdx.x * 128;
    const uint32_t base = s2u(dynsm);
    const uint32_t uQ = base;
    const uint32_t uK[2] = { base + 18432, base + 18432 + 9216 };
    const uint32_t uV[2] = { base + 36864, base + 36864 + 9216 };
    const int lrA = lane & 15, lcA = (lane >> 4) * 8;
    const int lrB = (lane & 7) + ((lane >> 4) << 3), lcB = ((lane >> 3) & 1) * 8;

    auto issueKV = [&](int kt, int bf) {
        #pragma unroll
        for (int t = 0; t < 2; t++) {
            int idx = tid + t * 256, row = idx >> 3, c8 = (idx & 7) * 8;
            cp16(uK[bf] + (row * LDT + c8) * 2,
                 &g_k16[(size_t)(b * NN + kt * 64 + row) * DD + h * HD + c8]);
            cp16(uV[bf] + (row * LDT + c8) * 2,
                 &g_vt16[(size_t)(hb * 64 + row) * NN + kt * 64 + c8]);
        }
        CPCOMMIT();
    };

    // Q tile (group 0) + KV tile 0 (group 1)
    #pragma unroll
    for (int t = 0; t < 4; t++) {
        int idx = tid + t * 256, row = idx >> 3, c8 = (idx & 7) * 8;
        cp16(uQ + (row * LDT + c8) * 2,
             &g_q16[(size_t)(b * NN + qb + row) * DD + h * HD + c8]);
    }
    CPCOMMIT();
    issueKV(0, 0);
    CPWAIT1();                // Q ready
    __syncthreads();
    uint32_t af[4][4];
    #pragma unroll
    for (int kk = 0; kk < 4; kk++)
        ldsm4(af[kk], uQ + ((wid * 16 + lrA) * LDT + kk * 16 + lcA) * 2);

    float o[8][4];
    #pragma unroll
    for (int i = 0; i < 8; i++)
        #pragma unroll
        for (int j = 0; j < 4; j++) o[i][j] = 0.0f;

    for (int kt = 0; kt < 16; kt++) {
        if (kt + 1 < 16) { issueKV(kt + 1, (kt + 1) & 1); CPWAIT1(); }
        else CPWAIT0();
        __syncthreads();
        const uint32_t cK = uK[kt & 1], cV = uV[kt & 1];

        float s[8][4];
        #pragma unroll
        for (int i = 0; i < 8; i++)
            #pragma unroll
            for (int j = 0; j < 4; j++) s[i][j] = 0.0f;
        #pragma unroll
        for (int kk = 0; kk < 4; kk++) {
            #pragma unroll
            for (int p = 0; p < 4; p++) {
                uint32_t bf[4];
                ldsm4(bf, cK + ((p * 16 + lrB) * LDT + kk * 16 + lcB) * 2);
                mma_(s[2 * p],     af[kk], bf[0], bf[1]);
                mma_(s[2 * p + 1], af[kk], bf[2], bf[3]);
            }
        }
        uint32_t aw[4][4];
        #pragma unroll
        for (int nt = 0; nt < 8; nt++) {
            float w0 = ex2(s[nt][0] * ES);
            float w1 = ex2(s[nt][1] * ES);
            float w2 = ex2(s[nt][2] * ES);
            float w3 = ex2(s[nt][3] * ES);
            __half2 hA = __floats2half2_rn(w0, w1), hB = __floats2half2_rn(w2, w3);
            aw[nt >> 1][(nt & 1) * 2 + 0] = *(uint32_t*)&hA;
            aw[nt >> 1][(nt & 1) * 2 + 1] = *(uint32_t*)&hB;
        }
        #pragma unroll
        for (int g = 0; g < 4; g++) {
            #pragma unroll
            for (int p = 0; p < 4; p++) {
                uint32_t bf[4];
                ldsm4(bf, cV + ((p * 16 + lrB) * LDT + g * 16 + lcB) * 2);
                mma_(o[2 * p],     aw[g], bf[0], bf[1]);
                mma_(o[2 * p + 1], aw[g], bf[2], bf[3]);
            }
        }
        __syncthreads();
    }
    int q0 = b * NN + qb + wid * 16 + (lane >> 2);
    #pragma unroll
    for (int nt = 0; nt < 8; nt++) {
        int c = h * HD + nt * 8 + (lane & 3) * 2;
        float2 r0v = *(const float2*)&g_q32[(size_t)q0 * DD + c];
        float2 r1v = *(const float2*)&g_q32[(size_t)(q0 + 8) * DD + c];
        float2 o0 = {o[nt][0] + r0v.x, o[nt][1] + r0v.y};
        float2 o1 = {o[nt][2] + r1v.x, o[nt][3] + r1v.y};
        *(float2*)&g_o[(size_t)q0 * DD + c] = o0;
        *(float2*)&g_o[(size_t)(q0 + 8) * DD + c] = o1;
    }
}

// ---- LayerNorm -------------------------------------------------------------
__global__ __launch_bounds__(256)
void ln_kernel(const float* __restrict__ gamma, const float* __restrict__ beta,
               float* __restrict__ out, int mode) {
    const int row = (blockIdx.x * blockDim.x + threadIdx.x) >> 5;
    const int lane = threadIdx.x & 31;
    float4 v[4];
    if (mode == 0) {
        const float4* p = (const float4*)(g_o + (size_t)row * DD);
        #pragma unroll
        for (int i = 0; i < 4; i++) v[i] = p[lane + i * 32];
    } else {
        const float4* px = (const float4*)(g_x32 + (size_t)row * DD);
        const float4* py = (const float4*)(g_y32 + (size_t)row * DD);
        #pragma unroll
        for (int i = 0; i < 4; i++) {
            float4 a = px[lane + i * 32], bq = py[lane + i * 32];
            v[i].x = a.x + fmaxf(bq.x, 0.0f); v[i].y = a.y + fmaxf(bq.y, 0.0f);
            v[i].z = a.z + fmaxf(bq.z, 0.0f); v[i].w = a.w + fmaxf(bq.w, 0.0f);
        }
    }
    float s = 0.0f, ss = 0.0f;
    #pragma unroll
    for (int i = 0; i < 4; i++) {
        s  += v[i].x + v[i].y + v[i].z + v[i].w;
        ss += v[i].x*v[i].x + v[i].y*v[i].y + v[i].z*v[i].z + v[i].w*v[i].w;
    }
    #pragma unroll
    for (int off = 16; off > 0; off >>= 1) {
        s  += __shfl_xor_sync(0xFFFFFFFFu, s, off);
        ss += __shfl_xor_sync(0xFFFFFFFFu, ss, off);
    }
    const float mean = s * (1.0f / 512.0f);
    const float var  = ss * (1.0f / 512.0f) - mean * mean;
    const float rstd = rsqrtf(var + 1e-5f);
    #pragma unroll
    for (int i = 0; i < 4; i++) {
        int c0 = (lane + i * 32) * 4;
        float4 g4 = *(const float4*)&gamma[c0];
        float4 b4 = *(const float4*)&beta[c0];
        float4 ov;
        ov.x = (v[i].x - mean) * rstd * g4.x + b4.x;
        ov.y = (v[i].y - mean) * rstd * g4.y + b4.y;
        ov.z = (v[i].z - mean) * rstd * g4.z + b4.z;
        ov.w = (v[i].w - mean) * rstd * g4.w + b4.w;
        if (mode == 0) {
            *(float4*)(g_x32 + (size_t)row * DD + c0) = ov;
            __half2 h0 = __floats2half2_rn(ov.x, ov.y), h1 = __floats2half2_rn(ov.z, ov.w);
            uint2 u = { *(uint32_t*)&h0, *(uint32_t*)&h1 };
            *(uint2*)(g_x16 + (size_t)row * DD + c0) = u;
        } else {
            *(float4*)(out + (size_t)row * DD + c0) = ov;
        }
    }
}

// ---- launch ----------------------------------------------------------------
extern "C" void kernel_launch(void* const* d_in, const int* in_sizes, int n_in,
                              void* d_out, int out_size) {
    (void)in_sizes; (void)n_in; (void)out_size;
    const float* Q   = (const float*)d_in[0];
    const float* K   = (const float*)d_in[1];
    const float* Wq  = (const float*)d_in[2];
    const float* bq  = (const float*)d_in[3];
    const float* Wk  = (const float*)d_in[4];
    const float* bk  = (const float*)d_in[5];
    const float* Wv  = (const float*)d_in[6];
    const float* bv  = (const float*)d_in[7];
    const float* Wo  = (const float*)d_in[8];
    const float* bo  = (const float*)d_in[9];
    const float* g0  = (const float*)d_in[10];
    const float* be0 = (const float*)d_in[11];
    const float* g1  = (const float*)d_in[12];
    const float* be1 = (const float*)d_in[13];
    float* out = (float*)d_out;

    const int GEMM_SM  = 4 * 128 * LDT * 2;   // 73728 B
    const int PASS_SM  = 6 * 64 * LDT * 2;    // 55296 B (3 x 128-row-equiv tiles)
    cudaFuncSetAttribute(gemm_mma,  cudaFuncAttributeMaxDynamicSharedMemorySize, GEMM_SM);
    cudaFuncSetAttribute(stats_mma, cudaFuncAttributeMaxDynamicSharedMemorySize, PASS_SM);
    cudaFuncSetAttribute(attn_mma,  cudaFuncAttributeMaxDynamicSharedMemorySize, PASS_SM);

    const int cvb = (MR * DD / 4) / 256;
    f2h<<<cvb, 256>>>(Q, 0);
    f2h<<<cvb, 256>>>(K, 1);
    wtr<<<dim3(16, 16), 256>>>(Wq, 0);
    wtr<<<dim3(16, 16), 256>>>(Wk, 1);
    wtr<<<dim3(16, 16), 256>>>(Wv, 2);
    wtr<<<dim3(16, 16), 256>>>(Wo, 3);

    dim3 gp(4, 256);
    gemm_mma<<<gp, 256, GEMM_SM>>>(bq, 0, 0, 0);            // g_q32 + g_q16
    gemm_mma<<<gp, 256, GEMM_SM>>>(bk, 1, 1, 1);            // g_k16
    gemm_mma<<<gp, 256, GEMM_SM>>>(bv, 1, 2, 2);            // g_v16
    stats_mma<<<dim3(8, HBN), 256, PASS_SM>>>();            // g_rz
    vtr<<<dim3(16, HBN), 256>>>();                          // g_vt16 = rz * V^T
    attn_mma<<<dim3(8, HBN), 256, PASS_SM>>>();             // g_o
    ln_kernel<<<MR / 8, 256>>>(g0, be0, out, 0);            // g_x32, g_x16
    gemm_mma<<<gp, 256, GEMM_SM>>>(bo, 2, 3, 3);            // g_y32
    ln_kernel<<<MR / 8, 256>>>(g1, be1, out, 1);            // out
}

// round 8
// speedup vs baseline: 5.2676x; 1.0125x over previous
#include <cuda_runtime.h>
#include <cuda_fp16.h>
#include <math.h>
#include <stdint.h>

#define BB 32
#define NN 1024
#define DD 512
#define HH 8
#define HD 64
#define MR (BB * NN)
#define HBN (HH * BB)
#define SCALE 0.044194173824159216f
#define ES (SCALE * 1.4426950408889634f)
#define LDT 72
#define TILE_B (128 * LDT * 2)      // 18432 bytes per 128-row tile

// ---- device-global scratch -------------------------------------------------
__device__ float  g_q32[(size_t)MR * DD];
__device__ float  g_o  [(size_t)MR * DD];
__device__ float  g_x32[(size_t)MR * DD];
__device__ float  g_y32[(size_t)MR * DD];
__device__ __half g_x16 [(size_t)MR * DD];
__device__ __half g_qin16[(size_t)MR * DD];
__device__ __half g_kin16[(size_t)MR * DD];
__device__ __half g_q16[(size_t)MR * DD];
__device__ __half g_k16[(size_t)MR * DD];
__device__ __half g_v16[(size_t)MR * DD];
__device__ __half g_vt16[(size_t)MR * DD];   // [(hb*64 + d)][n], pre-scaled by rz
__device__ __half g_wt[4][DD * DD];          // W^T fp16 [n][k]
__device__ float  g_rz[HBN * NN];

// ---- helpers ---------------------------------------------------------------
__device__ __forceinline__ uint32_t s2u(const void* p) {
    uint32_t a;
    asm("{ .reg .u64 t; cvta.to.shared.u64 t, %1; cvt.u32.u64 %0, t; }" : "=r"(a) : "l"(p));
    return a;
}
__device__ __forceinline__ void ldsm4(uint32_t* r, uint32_t a) {
    asm volatile("ldmatrix.sync.aligned.m8n8.x4.shared.b16 {%0,%1,%2,%3}, [%4];"
        : "=r"(r[0]), "=r"(r[1]), "=r"(r[2]), "=r"(r[3]) : "r"(a));
}
__device__ __forceinline__ void mma_(float* c, const uint32_t* a, uint32_t b0, uint32_t b1) {
    asm volatile("mma.sync.aligned.m16n8k16.row.col.f32.f16.f16.f32 "
        "{%0,%1,%2,%3},{%4,%5,%6,%7},{%8,%9},{%0,%1,%2,%3};"
        : "+f"(c[0]), "+f"(c[1]), "+f"(c[2]), "+f"(c[3])
        : "r"(a[0]), "r"(a[1]), "r"(a[2]), "r"(a[3]), "r"(b0), "r"(b1));
}
__device__ __forceinline__ float ex2(float x) {
    float r;
    asm("ex2.approx.f32 %0, %1;" : "=f"(r) : "f"(x));
    return r;
}
__device__ __forceinline__ void cp16(uint32_t d, const void* s) {
    asm volatile("cp.async.cg.shared.global [%0], [%1], 16;" :: "r"(d), "l"(s) : "memory");
}
#define CPCOMMIT() asm volatile("cp.async.commit_group;" ::: "memory")
#define CPWAIT2()  asm volatile("cp.async.wait_group 2;" ::: "memory")
#define CPWAIT1()  asm volatile("cp.async.wait_group 1;" ::: "memory")
#define CPWAIT0()  asm volatile("cp.async.wait_group 0;" ::: "memory")

extern __shared__ __half dynsm[];

// ---- fused elementwise prep ------------------------------------------------
__global__ __launch_bounds__(256) void f2h(const float* __restrict__ Qin,
                                           const float* __restrict__ Kin) {
    const float* in = blockIdx.y ? Kin : Qin;
    __half* out = blockIdx.y ? g_kin16 : g_qin16;
    int i = blockIdx.x * 256 + threadIdx.x;
    float4 v = ((const float4*)in)[i];
    __half2 a = __floats2half2_rn(v.x, v.y), b = __floats2half2_rn(v.z, v.w);
    uint2 u = { *(uint32_t*)&a, *(uint32_t*)&b };
    ((uint2*)out)[i] = u;
}

__global__ __launch_bounds__(256) void wtr(const float* __restrict__ W0,
                                           const float* __restrict__ W1,
                                           const float* __restrict__ W2,
                                           const float* __restrict__ W3) {
    __shared__ float t[32][33];
    const int wz = blockIdx.z;
    const float* W = (wz == 0) ? W0 : (wz == 1) ? W1 : (wz == 2) ? W2 : W3;
    const int bx = blockIdx.x * 32, by = blockIdx.y * 32;
    const int tx = threadIdx.x & 31, ty = threadIdx.x >> 5;
    __half* Wt = g_wt[wz];
    #pragma unroll
    for (int i = 0; i < 4; i++)
        t[ty + 8 * i][tx] = W[(size_t)(bx + ty + 8 * i) * DD + by + tx];
    __syncthreads();
    #pragma unroll
    for (int i = 0; i < 4; i++)
        Wt[(size_t)(by + ty + 8 * i) * DD + bx + tx] = __float2half_rn(t[tx][ty + 8 * i]);
}

__global__ __launch_bounds__(256) void vtr() {
    const int hb = blockIdx.y, h = hb >> 5, b = hb & 31, nb = blockIdx.x * 64;
    __shared__ __half t[64][80];
    const int tid = threadIdx.x;
    #pragma unroll
    for (int i = 0; i < 2; i++) {
        int idx = tid + i * 256, r = idx >> 3, cc = (idx & 7) * 8;
        float4 v = *(const float4*)(g_v16 + (size_t)(b * NN + nb + r) * DD + h * HD + cc);
        __half2 rz2 = __float2half2_rn(g_rz[hb * NN + nb + r]);
        __half2* h2 = (__half2*)&v;
        #pragma unroll
        for (int j = 0; j < 4; j++) h2[j] = __hmul2(h2[j], rz2);
        *(float4*)&t[r][cc] = v;
    }
    __syncthreads();
    #pragma unroll
    for (int i = 0; i < 2; i++) {
        int idx = tid + i * 256, d = idx >> 3, nn = (idx & 7) * 8;
        __half o[8];
        #pragma unroll
        for (int u = 0; u < 8; u++) o[u] = t[nn + u][d];
        *(float4*)(g_vt16 + (size_t)(hb * 64 + d) * NN + nb + nn) = *(float4*)o;
    }
}

// ---- dense GEMM (triple-buffered cp.async, 1 sync/iter) --------------------
// mode 0: blockIdx.z selects QKV projection; mode 1: Wo projection (sel=3)
// dyn smem: A stages @0,18432,36864 ; B stages @55296,73728,92160 (110592 B)
__global__ __launch_bounds__(256, 2)
void gemm_mma(const float* __restrict__ b0, const float* __restrict__ b1,
              const float* __restrict__ b2, int mode) {
    const int sel = mode ? 3 : blockIdx.z;
    const __half* A  = (sel == 0) ? g_qin16 : (sel == 3) ? g_x16 : g_kin16;
    const __half* Bt = g_wt[sel];
    const float* bias = (sel == 1) ? b1 : (sel == 2) ? b2 : b0;
    float*  C32 = (sel == 0) ? g_q32 : (sel == 3) ? g_y32 : nullptr;
    __half* C16 = (sel == 0) ? g_q16 : (sel == 1) ? g_k16 : (sel == 2) ? g_v16 : nullptr;

    const int tid = threadIdx.x, wid = tid >> 5, lane = tid & 31;
    const int wm = wid & 1, wn = wid >> 1;
    const int bm = blockIdx.y * 128, bn = blockIdx.x * 128;
    const uint32_t base = s2u(dynsm);
    const int lrA = lane & 15, lcA = (lane >> 4) * 8;
    const int lrB = (lane & 7) + ((lane >> 4) << 3), lcB = ((lane >> 3) & 1) * 8;

    auto issue = [&](int kc, int st) {
        uint32_t uA = base + st * TILE_B, uB = base + 3 * TILE_B + st * TILE_B;
        #pragma unroll
        for (int t = 0; t < 4; t++) {
            int idx = tid + t * 256, row = idx >> 3, c8 = (idx & 7) * 8;
            cp16(uA + (row * LDT + c8) * 2, &A [(size_t)(bm + row) * DD + kc * 64 + c8]);
            cp16(uB + (row * LDT + c8) * 2, &Bt[(size_t)(bn + row) * DD + kc * 64 + c8]);
        }
        CPCOMMIT();
    };

    float acc[4][4][4];
    #pragma unroll
    for (int i = 0; i < 4; i++)
        #pragma unroll
        for (int j = 0; j < 4; j++)
            #pragma unroll
            for (int k = 0; k < 4; k++) acc[i][j][k] = 0.0f;

    issue(0, 0);
    issue(1, 1);
    for (int kc = 0; kc < 8; kc++) {
        if (kc < 7) CPWAIT1(); else CPWAIT0();
        __syncthreads();
        if (kc + 2 < 8) issue(kc + 2, (kc + 2) % 3);
        const int st = kc % 3;
        const uint32_t cA = base + st * TILE_B, cB = base + 3 * TILE_B + st * TILE_B;
        #pragma unroll
        for (int kk = 0; kk < 4; kk++) {
            uint32_t af[4][4];
            #pragma unroll
            for (int mt = 0; mt < 4; mt++)
                ldsm4(af[mt], cA + ((wm * 64 + mt * 16 + lrA) * LDT + kk * 16 + lcA) * 2);
            #pragma unroll
            for (int p = 0; p < 2; p++) {
                uint32_t bf[4];
                ldsm4(bf, cB + ((wn * 32 + p * 16 + lrB) * LDT + kk * 16 + lcB) * 2);
                #pragma unroll
                for (int mt = 0; mt < 4; mt++) {
                    mma_(acc[mt][p * 2],     af[mt], bf[0], bf[1]);
                    mma_(acc[mt][p * 2 + 1], af[mt], bf[2], bf[3]);
                }
            }
        }
    }
    #pragma unroll
    for (int mt = 0; mt < 4; mt++) {
        int r0 = bm + wm * 64 + mt * 16 + (lane >> 2);
        #pragma unroll
        for (int nt = 0; nt < 4; nt++) {
            int c = bn + wn * 32 + nt * 8 + (lane & 3) * 2;
            float2 bb = *(const float2*)&bias[c];
            float d0 = acc[mt][nt][0] + bb.x, d1 = acc[mt][nt][1] + bb.y;
            float d2 = acc[mt][nt][2] + bb.x, d3 = acc[mt][nt][3] + bb.y;
            if (C32) {
                float2 o0 = {d0, d1}, o1 = {d2, d3};
                *(float2*)&C32[(size_t)r0 * DD + c] = o0;
                *(float2*)&C32[(size_t)(r0 + 8) * DD + c] = o1;
            }
            if (C16) {
                __half2 h0 = __floats2half2_rn(d0, d1), h1 = __floats2half2_rn(d2, d3);
                *(__half2*)&C16[(size_t)r0 * DD + c] = h0;
                *(__half2*)&C16[(size_t)(r0 + 8) * DD + c] = h1;
            }
        }
    }
}

// ---- pass 1: Z_k = sum_q exp(s*SCALE) (triple-buffered Q, 1 sync/iter) -----
// dyn smem: K @0 ; Q stages @18432, 36864, 55296 (73728 B)
__global__ __launch_bounds__(256, 2)
void stats_mma() {
    const int tid = threadIdx.x, wid = tid >> 5, lane = tid & 31;
    const int hb = blockIdx.y, h = hb >> 5, b = hb & 31, kb = blockIdx.x * 128;
    const uint32_t base = s2u(dynsm);
    const uint32_t uK = base;
    const int lrA = lane & 15, lcA = (lane >> 4) * 8;
    const int lrB = (lane & 7) + ((lane >> 4) << 3), lcB = ((lane >> 3) & 1) * 8;

    auto issueQ = [&](int qc, int st) {
        uint32_t uQ = base + (1 + st) * TILE_B;
        #pragma unroll
        for (int t = 0; t < 4; t++) {
            int idx = tid + t * 256, row = idx >> 3, c8 = (idx & 7) * 8;
            cp16(uQ + (row * LDT + c8) * 2,
                 &g_q16[(size_t)(b * NN + qc * 128 + row) * DD + h * HD + c8]);
        }
        CPCOMMIT();
    };

    #pragma unroll
    for (int t = 0; t < 4; t++) {
        int idx = tid + t * 256, row = idx >> 3, c8 = (idx & 7) * 8;
        cp16(uK + (row * LDT + c8) * 2,
             &g_k16[(size_t)(b * NN + kb + row) * DD + h * HD + c8]);
    }
    CPCOMMIT();
    issueQ(0, 0);
    issueQ(1, 1);
    CPWAIT2();                 // K ready
    __syncthreads();
    uint32_t af[4][4];
    #pragma unroll
    for (int kk = 0; kk < 4; kk++)
        ldsm4(af[kk], uK + ((wid * 16 + lrA) * LDT + kk * 16 + lcA) * 2);

    float z0 = 0.0f, z1 = 0.0f;
    for (int qc = 0; qc < 8; qc++) {
        if (qc < 7) CPWAIT1(); else CPWAIT0();
        __syncthreads();
        if (qc + 2 < 8) issueQ(qc + 2, (qc + 2) % 3);
        const uint32_t cQ = base + (1 + qc % 3) * TILE_B;
        float s[16][4];
        #pragma unroll
        for (int i = 0; i < 16; i++)
            #pragma unroll
            for (int j = 0; j < 4; j++) s[i][j] = 0.0f;
        #pragma unroll
        for (int kk = 0; kk < 4; kk++) {
            #pragma unroll
            for (int p = 0; p < 8; p++) {
                uint32_t bf[4];
                ldsm4(bf, cQ + ((p * 16 + lrB) * LDT + kk * 16 + lcB) * 2);
                mma_(s[2 * p],     af[kk], bf[0], bf[1]);
                mma_(s[2 * p + 1], af[kk], bf[2], bf[3]);
            }
        }
        #pragma unroll
        for (int nt = 0; nt < 16; nt++) {
            z0 += ex2(s[nt][0] * ES) + ex2(s[nt][1] * ES);
            z1 += ex2(s[nt][2] * ES) + ex2(s[nt][3] * ES);
        }
    }
    z0 += __shfl_xor_sync(0xFFFFFFFFu, z0, 1);
    z0 += __shfl_xor_sync(0xFFFFFFFFu, z0, 2);
    z1 += __shfl_xor_sync(0xFFFFFFFFu, z1, 1);
    z1 += __shfl_xor_sync(0xFFFFFFFFu, z1, 2);
    if ((lane & 3) == 0) {
        int k = kb + wid * 16 + (lane >> 2);
        g_rz[hb * NN + k] = 1.0f / z0;
        g_rz[hb * NN + k + 8] = 1.0f / z1;
    }
}

// ---- pass 2: O = qh + exp(S*SCALE) @ V' (triple-buffered KV, 1 sync/iter) --
// dyn smem: Q @0 ; KV stages @18432+s*18432 (K then V, 9216 each) (73728 B)
__global__ __launch_bounds__(256, 2)
void attn_mma() {
    const int tid = threadIdx.x, wid = tid >> 5, lane = tid & 31;
    const int hb = blockIdx.y, h = hb >> 5, b = hb & 31, qb = blockIdx.x * 128;
    const uint32_t base = s2u(dynsm);
    const uint32_t uQ = base;
    const int lrA = lane & 15, lcA = (lane >> 4) * 8;
    const int lrB = (lane & 7) + ((lane >> 4) << 3), lcB = ((lane >> 3) & 1) * 8;

    auto issueKV = [&](int kt, int st) {
        uint32_t uK = base + (1 + st) * TILE_B;
        uint32_t uV = uK + TILE_B / 2;
        #pragma unroll
        for (int t = 0; t < 2; t++) {
            int idx = tid + t * 256, row = idx >> 3, c8 = (idx & 7) * 8;
            cp16(uK + (row * LDT + c8) * 2,
                 &g_k16[(size_t)(b * NN + kt * 64 + row) * DD + h * HD + c8]);
            cp16(uV + (row * LDT + c8) * 2,
                 &g_vt16[(size_t)(hb * 64 + row) * NN + kt * 64 + c8]);
        }
        CPCOMMIT();
    };

    #pragma unroll
    for (int t = 0; t < 4; t++) {
        int idx = tid + t * 256, row = idx >> 3, c8 = (idx & 7) * 8;
        cp16(uQ + (row * LDT + c8) * 2,
             &g_q16[(size_t)(b * NN + qb + row) * DD + h * HD + c8]);
    }
    CPCOMMIT();
    issueKV(0, 0);
    issueKV(1, 1);
    CPWAIT2();                 // Q ready
    __syncthreads();
    uint32_t af[4][4];
    #pragma unroll
    for (int kk = 0; kk < 4; kk++)
        ldsm4(af[kk], uQ + ((wid * 16 + lrA) * LDT + kk * 16 + lcA) * 2);

    float o[8][4];
    #pragma unroll
    for (int i = 0; i < 8; i++)
        #pragma unroll
        for (int j = 0; j < 4; j++) o[i][j] = 0.0f;

    for (int kt = 0; kt < 16; kt++) {
        if (kt < 15) CPWAIT1(); else CPWAIT0();
        __syncthreads();
        if (kt + 2 < 16) issueKV(kt + 2, (kt + 2) % 3);
        const uint32_t cK = base + (1 + kt % 3) * TILE_B;
        const uint32_t cV = cK + TILE_B / 2;

        float s[8][4];
        #pragma unroll
        for (int i = 0; i < 8; i++)
            #pragma unroll
            for (int j = 0; j < 4; j++) s[i][j] = 0.0f;
        #pragma unroll
        for (int kk = 0; kk < 4; kk++) {
            #pragma unroll
            for (int p = 0; p < 4; p++) {
                uint32_t bf[4];
                ldsm4(bf, cK + ((p * 16 + lrB) * LDT + kk * 16 + lcB) * 2);
                mma_(s[2 * p],     af[kk], bf[0], bf[1]);
                mma_(s[2 * p + 1], af[kk], bf[2], bf[3]);
            }
        }
        uint32_t aw[4][4];
        #pragma unroll
        for (int nt = 0; nt < 8; nt++) {
            float w0 = ex2(s[nt][0] * ES);
            float w1 = ex2(s[nt][1] * ES);
            float w2 = ex2(s[nt][2] * ES);
            float w3 = ex2(s[nt][3] * ES);
            __half2 hA = __floats2half2_rn(w0, w1), hB = __floats2half2_rn(w2, w3);
            aw[nt >> 1][(nt & 1) * 2 + 0] = *(uint32_t*)&hA;
            aw[nt >> 1][(nt & 1) * 2 + 1] = *(uint32_t*)&hB;
        }
        #pragma unroll
        for (int g = 0; g < 4; g++) {
            #pragma unroll
            for (int p = 0; p < 4; p++) {
                uint32_t bf[4];
                ldsm4(bf, cV + ((p * 16 + lrB) * LDT + g * 16 + lcB) * 2);
                mma_(o[2 * p],     aw[g], bf[0], bf[1]);
                mma_(o[2 * p + 1], aw[g], bf[2], bf[3]);
            }
        }
    }
    int q0 = b * NN + qb + wid * 16 + (lane >> 2);
    #pragma unroll
    for (int nt = 0; nt < 8; nt++) {
        int c = h * HD + nt * 8 + (lane & 3) * 2;
        float2 r0v = *(const float2*)&g_q32[(size_t)q0 * DD + c];
        float2 r1v = *(const float2*)&g_q32[(size_t)(q0 + 8) * DD + c];
        float2 o0 = {o[nt][0] + r0v.x, o[nt][1] + r0v.y};
        float2 o1 = {o[nt][2] + r1v.x, o[nt][3] + r1v.y};
        *(float2*)&g_o[(size_t)q0 * DD + c] = o0;
        *(float2*)&g_o[(size_t)(q0 + 8) * DD + c] = o1;
    }
}

// ---- LayerNorm -------------------------------------------------------------
__global__ __launch_bounds__(256)
void ln_kernel(const float* __restrict__ gamma, const float* __restrict__ beta,
               float* __restrict__ out, int mode) {
    const int row = (blockIdx.x * blockDim.x + threadIdx.x) >> 5;
    const int lane = threadIdx.x & 31;
    float4 v[4];
    if (mode == 0) {
        const float4* p = (const float4*)(g_o + (size_t)row * DD);
        #pragma unroll
        for (int i = 0; i < 4; i++) v[i] = p[lane + i * 32];
    } else {
        const float4* px = (const float4*)(g_x32 + (size_t)row * DD);
        const float4* py = (const float4*)(g_y32 + (size_t)row * DD);
        #pragma unroll
        for (int i = 0; i < 4; i++) {
            float4 a = px[lane + i * 32], bq = py[lane + i * 32];
            v[i].x = a.x + fmaxf(bq.x, 0.0f); v[i].y = a.y + fmaxf(bq.y, 0.0f);
            v[i].z = a.z + fmaxf(bq.z, 0.0f); v[i].w = a.w + fmaxf(bq.w, 0.0f);
        }
    }
    float s = 0.0f, ss = 0.0f;
    #pragma unroll
    for (int i = 0; i < 4; i++) {
        s  += v[i].x + v[i].y + v[i].z + v[i].w;
        ss += v[i].x*v[i].x + v[i].y*v[i].y + v[i].z*v[i].z + v[i].w*v[i].w;
    }
    #pragma unroll
    for (int off = 16; off > 0; off >>= 1) {
        s  += __shfl_xor_sync(0xFFFFFFFFu, s, off);
        ss += __shfl_xor_sync(0xFFFFFFFFu, ss, off);
    }
    const float mean = s * (1.0f / 512.0f);
    const float var  = ss * (1.0f / 512.0f) - mean * mean;
    const float rstd = rsqrtf(var + 1e-5f);
    #pragma unroll
    for (int i = 0; i < 4; i++) {
        int c0 = (lane + i * 32) * 4;
        float4 g4 = *(const float4*)&gamma[c0];
        float4 b4 = *(const float4*)&beta[c0];
        float4 ov;
        ov.x = (v[i].x - mean) * rstd * g4.x + b4.x;
        ov.y = (v[i].y - mean) * rstd * g4.y + b4.y;
        ov.z = (v[i].z - mean) * rstd * g4.z + b4.z;
        ov.w = (v[i].w - mean) * rstd * g4.w + b4.w;
        if (mode == 0) {
            *(float4*)(g_x32 + (size_t)row * DD + c0) = ov;
            __half2 h0 = __floats2half2_rn(ov.x, ov.y), h1 = __floats2half2_rn(ov.z, ov.w);
            uint2 u = { *(uint32_t*)&h0, *(uint32_t*)&h1 };
            *(uint2*)(g_x16 + (size_t)row * DD + c0) = u;
        } else {
            *(float4*)(out + (size_t)row * DD + c0) = ov;
        }
    }
}

// ---- launch ----------------------------------------------------------------
extern "C" void kernel_launch(void* const* d_in, const int* in_sizes, int n_in,
                              void* d_out, int out_size) {
    (void)in_sizes; (void)n_in; (void)out_size;
    const float* Q   = (const float*)d_in[0];
    const float* K   = (const float*)d_in[1];
    const float* Wq  = (const float*)d_in[2];
    const float* bq  = (const float*)d_in[3];
    const float* Wk  = (const float*)d_in[4];
    const float* bk  = (const float*)d_in[5];
    const float* Wv  = (const float*)d_in[6];
    const float* bv  = (const float*)d_in[7];
    const float* Wo  = (const float*)d_in[8];
    const float* bo  = (const float*)d_in[9];
    const float* g0  = (const float*)d_in[10];
    const float* be0 = (const float*)d_in[11];
    const float* g1  = (const float*)d_in[12];
    const float* be1 = (const float*)d_in[13];
    float* out = (float*)d_out;

    const int GEMM_SM = 6 * TILE_B;   // 110592 B
    const int PASS_SM = 4 * TILE_B;   //  73728 B
    cudaFuncSetAttribute(gemm_mma,  cudaFuncAttributeMaxDynamicSharedMemorySize, GEMM_SM);
    cudaFuncSetAttribute(stats_mma, cudaFuncAttributeMaxDynamicSharedMemorySize, PASS_SM);
    cudaFuncSetAttribute(attn_mma,  cudaFuncAttributeMaxDynamicSharedMemorySize, PASS_SM);

    f2h<<<dim3((MR * DD / 4) / 256, 2), 256>>>(Q, K);
    wtr<<<dim3(16, 16, 4), 256>>>(Wq, Wk, Wv, Wo);

    gemm_mma<<<dim3(4, 256, 3), 256, GEMM_SM>>>(bq, bk, bv, 0);  // QKV projections
    stats_mma<<<dim3(8, HBN), 256, PASS_SM>>>();                 // g_rz
    vtr<<<dim3(16, HBN), 256>>>();                               // g_vt16 = rz * V^T
    attn_mma<<<dim3(8, HBN), 256, PASS_SM>>>();                  // g_o
    ln_kernel<<<MR / 8, 256>>>(g0, be0, out, 0);                 // g_x32, g_x16
    gemm_mma<<<dim3(4, 256, 1), 256, GEMM_SM>>>(bo, bo, bo, 1);  // g_y32
    ln_kernel<<<MR / 8, 256>>>(g1, be1, out, 1);                 // out
}

// round 9
// speedup vs baseline: 5.5298x; 1.0498x over previous
#include <cuda_runtime.h>
#include <cuda_fp16.h>
#include <math.h>
#include <stdint.h>

#define BB 32
#define NN 1024
#define DD 512
#define HH 8
#define HD 64
#define MR (BB * NN)
#define HBN (HH * BB)
#define SCALE 0.044194173824159216f
#define ESF (SCALE * 1.4426950408889634f)   // folded into K projection
#define LDT 72
#define TILE_B (128 * LDT * 2)      // 18432 bytes per 128-row tile

// ---- device-global scratch -------------------------------------------------
__device__ float  g_q32[(size_t)MR * DD];
__device__ float  g_o  [(size_t)MR * DD];
__device__ float  g_x32[(size_t)MR * DD];
__device__ float  g_y32[(size_t)MR * DD];
__device__ __half g_x16 [(size_t)MR * DD];
__device__ __half g_qin16[(size_t)MR * DD];
__device__ __half g_kin16[(size_t)MR * DD];
__device__ __half g_q16[(size_t)MR * DD];
__device__ __half g_k16[(size_t)MR * DD];    // pre-scaled by ESF
__device__ __half g_v16[(size_t)MR * DD];
__device__ __half g_vt16[(size_t)MR * DD];   // [(hb*64 + d)][n], pre-scaled by rz
__device__ __half g_wt[4][DD * DD];          // W^T fp16 [n][k]
__device__ float  g_rz[HBN * NN];

// ---- helpers ---------------------------------------------------------------
__device__ __forceinline__ uint32_t s2u(const void* p) {
    uint32_t a;
    asm("{ .reg .u64 t; cvta.to.shared.u64 t, %1; cvt.u32.u64 %0, t; }" : "=r"(a) : "l"(p));
    return a;
}
__device__ __forceinline__ void ldsm4(uint32_t* r, uint32_t a) {
    asm volatile("ldmatrix.sync.aligned.m8n8.x4.shared.b16 {%0,%1,%2,%3}, [%4];"
        : "=r"(r[0]), "=r"(r[1]), "=r"(r[2]), "=r"(r[3]) : "r"(a));
}
__device__ __forceinline__ void mma_(float* c, const uint32_t* a, uint32_t b0, uint32_t b1) {
    asm volatile("mma.sync.aligned.m16n8k16.row.col.f32.f16.f16.f32 "
        "{%0,%1,%2,%3},{%4,%5,%6,%7},{%8,%9},{%0,%1,%2,%3};"
        : "+f"(c[0]), "+f"(c[1]), "+f"(c[2]), "+f"(c[3])
        : "r"(a[0]), "r"(a[1]), "r"(a[2]), "r"(a[3]), "r"(b0), "r"(b1));
}
__device__ __forceinline__ float ex2(float x) {
    float r;
    asm("ex2.approx.f32 %0, %1;" : "=f"(r) : "f"(x));
    return r;
}
__device__ __forceinline__ void cp16(uint32_t d, const void* s) {
    asm volatile("cp.async.cg.shared.global [%0], [%1], 16;" :: "r"(d), "l"(s) : "memory");
}
#define CPCOMMIT() asm volatile("cp.async.commit_group;" ::: "memory")
#define CPWAIT2()  asm volatile("cp.async.wait_group 2;" ::: "memory")
#define CPWAIT1()  asm volatile("cp.async.wait_group 1;" ::: "memory")
#define CPWAIT0()  asm volatile("cp.async.wait_group 0;" ::: "memory")

extern __shared__ __half dynsm[];

// ---- fused elementwise prep ------------------------------------------------
__global__ __launch_bounds__(256) void f2h(const float* __restrict__ Qin,
                                           const float* __restrict__ Kin) {
    const float* in = blockIdx.y ? Kin : Qin;
    __half* out = blockIdx.y ? g_kin16 : g_qin16;
    int i = blockIdx.x * 256 + threadIdx.x;
    float4 v = ((const float4*)in)[i];
    __half2 a = __floats2half2_rn(v.x, v.y), b = __floats2half2_rn(v.z, v.w);
    uint2 u = { *(uint32_t*)&a, *(uint32_t*)&b };
    ((uint2*)out)[i] = u;
}

__global__ __launch_bounds__(256) void wtr(const float* __restrict__ W0,
                                           const float* __restrict__ W1,
                                           const float* __restrict__ W2,
                                           const float* __restrict__ W3) {
    __shared__ float t[32][33];
    const int wz = blockIdx.z;
    const float* W = (wz == 0) ? W0 : (wz == 1) ? W1 : (wz == 2) ? W2 : W3;
    const int bx = blockIdx.x * 32, by = blockIdx.y * 32;
    const int tx = threadIdx.x & 31, ty = threadIdx.x >> 5;
    __half* Wt = g_wt[wz];
    #pragma unroll
    for (int i = 0; i < 4; i++)
        t[ty + 8 * i][tx] = W[(size_t)(bx + ty + 8 * i) * DD + by + tx];
    __syncthreads();
    #pragma unroll
    for (int i = 0; i < 4; i++)
        Wt[(size_t)(by + ty + 8 * i) * DD + bx + tx] = __float2half_rn(t[tx][ty + 8 * i]);
}

__global__ __launch_bounds__(256) void vtr() {
    const int hb = blockIdx.y, h = hb >> 5, b = hb & 31, nb = blockIdx.x * 64;
    __shared__ __half t[64][80];
    const int tid = threadIdx.x;
    #pragma unroll
    for (int i = 0; i < 2; i++) {
        int idx = tid + i * 256, r = idx >> 3, cc = (idx & 7) * 8;
        float4 v = *(const float4*)(g_v16 + (size_t)(b * NN + nb + r) * DD + h * HD + cc);
        __half2 rz2 = __float2half2_rn(g_rz[hb * NN + nb + r]);
        __half2* h2 = (__half2*)&v;
        #pragma unroll
        for (int j = 0; j < 4; j++) h2[j] = __hmul2(h2[j], rz2);
        *(float4*)&t[r][cc] = v;
    }
    __syncthreads();
    #pragma unroll
    for (int i = 0; i < 2; i++) {
        int idx = tid + i * 256, d = idx >> 3, nn = (idx & 7) * 8;
        __half o[8];
        #pragma unroll
        for (int u = 0; u < 8; u++) o[u] = t[nn + u][d];
        *(float4*)(g_vt16 + (size_t)(hb * 64 + d) * NN + nb + nn) = *(float4*)o;
    }
}

// ---- dense GEMM (triple-buffered cp.async, 1 sync/iter) --------------------
__global__ __launch_bounds__(256, 2)
void gemm_mma(const float* __restrict__ b0, const float* __restrict__ b1,
              const float* __restrict__ b2, int mode) {
    const int sel = mode ? 3 : blockIdx.z;
    const __half* A  = (sel == 0) ? g_qin16 : (sel == 3) ? g_x16 : g_kin16;
    const __half* Bt = g_wt[sel];
    const float* bias = (sel == 1) ? b1 : (sel == 2) ? b2 : b0;
    float*  C32 = (sel == 0) ? g_q32 : (sel == 3) ? g_y32 : nullptr;
    __half* C16 = (sel == 0) ? g_q16 : (sel == 1) ? g_k16 : (sel == 2) ? g_v16 : nullptr;
    const float cs = (sel == 1) ? ESF : 1.0f;   // fold softmax scale into K

    const int tid = threadIdx.x, wid = tid >> 5, lane = tid & 31;
    const int wm = wid & 1, wn = wid >> 1;
    const int bm = blockIdx.y * 128, bn = blockIdx.x * 128;
    const uint32_t base = s2u(dynsm);
    const int lrA = lane & 15, lcA = (lane >> 4) * 8;
    const int lrB = (lane & 7) + ((lane >> 4) << 3), lcB = ((lane >> 3) & 1) * 8;

    auto issue = [&](int kc, int st) {
        uint32_t uA = base + st * TILE_B, uB = base + 3 * TILE_B + st * TILE_B;
        #pragma unroll
        for (int t = 0; t < 4; t++) {
            int idx = tid + t * 256, row = idx >> 3, c8 = (idx & 7) * 8;
            cp16(uA + (row * LDT + c8) * 2, &A [(size_t)(bm + row) * DD + kc * 64 + c8]);
            cp16(uB + (row * LDT + c8) * 2, &Bt[(size_t)(bn + row) * DD + kc * 64 + c8]);
        }
        CPCOMMIT();
    };

    float acc[4][4][4];
    #pragma unroll
    for (int i = 0; i < 4; i++)
        #pragma unroll
        for (int j = 0; j < 4; j++)
            #pragma unroll
            for (int k = 0; k < 4; k++) acc[i][j][k] = 0.0f;

    issue(0, 0);
    issue(1, 1);
    for (int kc = 0; kc < 8; kc++) {
        if (kc < 7) CPWAIT1(); else CPWAIT0();
        __syncthreads();
        if (kc + 2 < 8) issue(kc + 2, (kc + 2) % 3);
        const int st = kc % 3;
        const uint32_t cA = base + st * TILE_B, cB = base + 3 * TILE_B + st * TILE_B;
        #pragma unroll
        for (int kk = 0; kk < 4; kk++) {
            uint32_t af[4][4];
            #pragma unroll
            for (int mt = 0; mt < 4; mt++)
                ldsm4(af[mt], cA + ((wm * 64 + mt * 16 + lrA) * LDT + kk * 16 + lcA) * 2);
            #pragma unroll
            for (int p = 0; p < 2; p++) {
                uint32_t bf[4];
                ldsm4(bf, cB + ((wn * 32 + p * 16 + lrB) * LDT + kk * 16 + lcB) * 2);
                #pragma unroll
                for (int mt = 0; mt < 4; mt++) {
                    mma_(acc[mt][p * 2],     af[mt], bf[0], bf[1]);
                    mma_(acc[mt][p * 2 + 1], af[mt], bf[2], bf[3]);
                }
            }
        }
    }
    #pragma unroll
    for (int mt = 0; mt < 4; mt++) {
        int r0 = bm + wm * 64 + mt * 16 + (lane >> 2);
        #pragma unroll
        for (int nt = 0; nt < 4; nt++) {
            int c = bn + wn * 32 + nt * 8 + (lane & 3) * 2;
            float2 bb = *(const float2*)&bias[c];
            float d0 = acc[mt][nt][0] + bb.x, d1 = acc[mt][nt][1] + bb.y;
            float d2 = acc[mt][nt][2] + bb.x, d3 = acc[mt][nt][3] + bb.y;
            if (C32) {
                float2 o0 = {d0, d1}, o1 = {d2, d3};
                *(float2*)&C32[(size_t)r0 * DD + c] = o0;
                *(float2*)&C32[(size_t)(r0 + 8) * DD + c] = o1;
            }
            if (C16) {
                __half2 h0 = __floats2half2_rn(d0 * cs, d1 * cs);
                __half2 h1 = __floats2half2_rn(d2 * cs, d3 * cs);
                *(__half2*)&C16[(size_t)r0 * DD + c] = h0;
                *(__half2*)&C16[(size_t)(r0 + 8) * DD + c] = h1;
            }
        }
    }
}

// ---- pass 1: Z_k = sum_q 2^(s_es) (triple-buffered Q, occ 3, 2 q-batches) --
// dyn smem: K @0 ; Q stages @18432, 36864, 55296 (73728 B)
__global__ __launch_bounds__(256, 3)
void stats_mma() {
    const int tid = threadIdx.x, wid = tid >> 5, lane = tid & 31;
    const int hb = blockIdx.y, h = hb >> 5, b = hb & 31, kb = blockIdx.x * 128;
    const uint32_t base = s2u(dynsm);
    const uint32_t uK = base;
    const int lrA = lane & 15, lcA = (lane >> 4) * 8;
    const int lrB = (lane & 7) + ((lane >> 4) << 3), lcB = ((lane >> 3) & 1) * 8;

    auto issueQ = [&](int qc, int st) {
        uint32_t uQ = base + (1 + st) * TILE_B;
        #pragma unroll
        for (int t = 0; t < 4; t++) {
            int idx = tid + t * 256, row = idx >> 3, c8 = (idx & 7) * 8;
            cp16(uQ + (row * LDT + c8) * 2,
                 &g_q16[(size_t)(b * NN + qc * 128 + row) * DD + h * HD + c8]);
        }
        CPCOMMIT();
    };

    #pragma unroll
    for (int t = 0; t < 4; t++) {
        int idx = tid + t * 256, row = idx >> 3, c8 = (idx & 7) * 8;
        cp16(uK + (row * LDT + c8) * 2,
             &g_k16[(size_t)(b * NN + kb + row) * DD + h * HD + c8]);
    }
    CPCOMMIT();
    issueQ(0, 0);
    issueQ(1, 1);
    CPWAIT2();                 // K ready
    __syncthreads();
    uint32_t af[4][4];
    #pragma unroll
    for (int kk = 0; kk < 4; kk++)
        ldsm4(af[kk], uK + ((wid * 16 + lrA) * LDT + kk * 16 + lcA) * 2);

    float z0 = 0.0f, z1 = 0.0f;
    for (int qc = 0; qc < 8; qc++) {
        if (qc < 7) CPWAIT1(); else CPWAIT0();
        __syncthreads();
        if (qc + 2 < 8) issueQ(qc + 2, (qc + 2) % 3);
        const uint32_t cQ = base + (1 + qc % 3) * TILE_B;
        #pragma unroll
        for (int hlf = 0; hlf < 2; hlf++) {
            float s[8][4];
            #pragma unroll
            for (int i = 0; i < 8; i++)
                #pragma unroll
                for (int j = 0; j < 4; j++) s[i][j] = 0.0f;
            #pragma unroll
            for (int kk = 0; kk < 4; kk++) {
                #pragma unroll
                for (int p = 0; p < 4; p++) {
                    uint32_t bf[4];
                    ldsm4(bf, cQ + (((hlf * 4 + p) * 16 + lrB) * LDT + kk * 16 + lcB) * 2);
                    mma_(s[2 * p],     af[kk], bf[0], bf[1]);
                    mma_(s[2 * p + 1], af[kk], bf[2], bf[3]);
                }
            }
            #pragma unroll
            for (int nt = 0; nt < 8; nt++) {
                z0 += ex2(s[nt][0]) + ex2(s[nt][1]);
                z1 += ex2(s[nt][2]) + ex2(s[nt][3]);
            }
        }
    }
    z0 += __shfl_xor_sync(0xFFFFFFFFu, z0, 1);
    z0 += __shfl_xor_sync(0xFFFFFFFFu, z0, 2);
    z1 += __shfl_xor_sync(0xFFFFFFFFu, z1, 1);
    z1 += __shfl_xor_sync(0xFFFFFFFFu, z1, 2);
    if ((lane & 3) == 0) {
        int k = kb + wid * 16 + (lane >> 2);
        g_rz[hb * NN + k] = 1.0f / z0;
        g_rz[hb * NN + k + 8] = 1.0f / z1;
    }
}

// ---- pass 2: O = qh + 2^(S_es) @ V' (triple-buffered KV, 1 sync/iter) ------
// dyn smem: Q @0 ; KV stages @18432+s*18432 (K then V, 9216 each) (73728 B)
__global__ __launch_bounds__(256, 2)
void attn_mma() {
    const int tid = threadIdx.x, wid = tid >> 5, lane = tid & 31;
    const int hb = blockIdx.y, h = hb >> 5, b = hb & 31, qb = blockIdx.x * 128;
    const uint32_t base = s2u(dynsm);
    const uint32_t uQ = base;
    const int lrA = lane & 15, lcA = (lane >> 4) * 8;
    const int lrB = (lane & 7) + ((lane >> 4) << 3), lcB = ((lane >> 3) & 1) * 8;

    auto issueKV = [&](int kt, int st) {
        uint32_t uK = base + (1 + st) * TILE_B;
        uint32_t uV = uK + TILE_B / 2;
        #pragma unroll
        for (int t = 0; t < 2; t++) {
            int idx = tid + t * 256, row = idx >> 3, c8 = (idx & 7) * 8;
            cp16(uK + (row * LDT + c8) * 2,
                 &g_k16[(size_t)(b * NN + kt * 64 + row) * DD + h * HD + c8]);
            cp16(uV + (row * LDT + c8) * 2,
                 &g_vt16[(size_t)(hb * 64 + row) * NN + kt * 64 + c8]);
        }
        CPCOMMIT();
    };

    #pragma unroll
    for (int t = 0; t < 4; t++) {
        int idx = tid + t * 256, row = idx >> 3, c8 = (idx & 7) * 8;
        cp16(uQ + (row * LDT + c8) * 2,
             &g_q16[(size_t)(b * NN + qb + row) * DD + h * HD + c8]);
    }
    CPCOMMIT();
    issueKV(0, 0);
    issueKV(1, 1);
    CPWAIT2();                 // Q ready
    __syncthreads();
    uint32_t af[4][4];
    #pragma unroll
    for (int kk = 0; kk < 4; kk++)
        ldsm4(af[kk], uQ + ((wid * 16 + lrA) * LDT + kk * 16 + lcA) * 2);

    float o[8][4];
    #pragma unroll
    for (int i = 0; i < 8; i++)
        #pragma unroll
        for (int j = 0; j < 4; j++) o[i][j] = 0.0f;

    for (int kt = 0; kt < 16; kt++) {
        if (kt < 15) CPWAIT1(); else CPWAIT0();
        __syncthreads();
        if (kt + 2 < 16) issueKV(kt + 2, (kt + 2) % 3);
        const uint32_t cK = base + (1 + kt % 3) * TILE_B;
        const uint32_t cV = cK + TILE_B / 2;

        float s[8][4];
        #pragma unroll
        for (int i = 0; i < 8; i++)
            #pragma unroll
            for (int j = 0; j < 4; j++) s[i][j] = 0.0f;
        #pragma unroll
        for (int kk = 0; kk < 4; kk++) {
            #pragma unroll
            for (int p = 0; p < 4; p++) {
                uint32_t bf[4];
                ldsm4(bf, cK + ((p * 16 + lrB) * LDT + kk * 16 + lcB) * 2);
                mma_(s[2 * p],     af[kk], bf[0], bf[1]);
                mma_(s[2 * p + 1], af[kk], bf[2], bf[3]);
            }
        }
        uint32_t aw[4][4];
        #pragma unroll
        for (int nt = 0; nt < 8; nt++) {
            float w0 = ex2(s[nt][0]);
            float w1 = ex2(s[nt][1]);
            float w2 = ex2(s[nt][2]);
            float w3 = ex2(s[nt][3]);
            __half2 hA = __floats2half2_rn(w0, w1), hB = __floats2half2_rn(w2, w3);
            aw[nt >> 1][(nt & 1) * 2 + 0] = *(uint32_t*)&hA;
            aw[nt >> 1][(nt & 1) * 2 + 1] = *(uint32_t*)&hB;
        }
        #pragma unroll
        for (int g = 0; g < 4; g++) {
            #pragma unroll
            for (int p = 0; p < 4; p++) {
                uint32_t bf[4];
                ldsm4(bf, cV + ((p * 16 + lrB) * LDT + g * 16 + lcB) * 2);
                mma_(o[2 * p],     aw[g], bf[0], bf[1]);
                mma_(o[2 * p + 1], aw[g], bf[2], bf[3]);
            }
        }
    }
    int q0 = b * NN + qb + wid * 16 + (lane >> 2);
    #pragma unroll
    for (int nt = 0; nt < 8; nt++) {
        int c = h * HD + nt * 8 + (lane & 3) * 2;
        float2 r0v = *(const float2*)&g_q32[(size_t)q0 * DD + c];
        float2 r1v = *(const float2*)&g_q32[(size_t)(q0 + 8) * DD + c];
        float2 o0 = {o[nt][0] + r0v.x, o[nt][1] + r0v.y};
        float2 o1 = {o[nt][2] + r1v.x, o[nt][3] + r1v.y};
        *(float2*)&g_o[(size_t)q0 * DD + c] = o0;
        *(float2*)&g_o[(size_t)(q0 + 8) * DD + c] = o1;
    }
}

// ---- LayerNorm -------------------------------------------------------------
__global__ __launch_bounds__(256)
void ln_kernel(const float* __restrict__ gamma, const float* __restrict__ beta,
               float* __restrict__ out, int mode) {
    const int row = (blockIdx.x * blockDim.x + threadIdx.x) >> 5;
    const int lane = threadIdx.x & 31;
    float4 v[4];
    if (mode == 0) {
        const float4* p = (const float4*)(g_o + (size_t)row * DD);
        #pragma unroll
        for (int i = 0; i < 4; i++) v[i] = p[lane + i * 32];
    } else {
        const float4* px = (const float4*)(g_x32 + (size_t)row * DD);
        const float4* py = (const float4*)(g_y32 + (size_t)row * DD);
        #pragma unroll
        for (int i = 0; i < 4; i++) {
            float4 a = px[lane + i * 32], bq = py[lane + i * 32];
            v[i].x = a.x + fmaxf(bq.x, 0.0f); v[i].y = a.y + fmaxf(bq.y, 0.0f);
            v[i].z = a.z + fmaxf(bq.z, 0.0f); v[i].w = a.w + fmaxf(bq.w, 0.0f);
        }
    }
    float s = 0.0f, ss = 0.0f;
    #pragma unroll
    for (int i = 0; i < 4; i++) {
        s  += v[i].x + v[i].y + v[i].z + v[i].w;
        ss += v[i].x*v[i].x + v[i].y*v[i].y + v[i].z*v[i].z + v[i].w*v[i].w;
    }
    #pragma unroll
    for (int off = 16; off > 0; off >>= 1) {
        s  += __shfl_xor_sync(0xFFFFFFFFu, s, off);
        ss += __shfl_xor_sync(0xFFFFFFFFu, ss, off);
    }
    const float mean = s * (1.0f / 512.0f);
    const float var  = ss * (1.0f / 512.0f) - mean * mean;
    const float rstd = rsqrtf(var + 1e-5f);
    #pragma unroll
    for (int i = 0; i < 4; i++) {
        int c0 = (lane + i * 32) * 4;
        float4 g4 = *(const float4*)&gamma[c0];
        float4 b4 = *(const float4*)&beta[c0];
        float4 ov;
        ov.x = (v[i].x - mean) * rstd * g4.x + b4.x;
        ov.y = (v[i].y - mean) * rstd * g4.y + b4.y;
        ov.z = (v[i].z - mean) * rstd * g4.z + b4.z;
        ov.w = (v[i].w - mean) * rstd * g4.w + b4.w;
        if (mode == 0) {
            *(float4*)(g_x32 + (size_t)row * DD + c0) = ov;
            __half2 h0 = __floats2half2_rn(ov.x, ov.y), h1 = __floats2half2_rn(ov.z, ov.w);
            uint2 u = { *(uint32_t*)&h0, *(uint32_t*)&h1 };
            *(uint2*)(g_x16 + (size_t)row * DD + c0) = u;
        } else {
            *(float4*)(out + (size_t)row * DD + c0) = ov;
        }
    }
}

// ---- launch ----------------------------------------------------------------
extern "C" void kernel_launch(void* const* d_in, const int* in_sizes, int n_in,
                              void* d_out, int out_size) {
    (void)in_sizes; (void)n_in; (void)out_size;
    const float* Q   = (const float*)d_in[0];
    const float* K   = (const float*)d_in[1];
    const float* Wq  = (const float*)d_in[2];
    const float* bq  = (const float*)d_in[3];
    const float* Wk  = (const float*)d_in[4];
    const float* bk  = (const float*)d_in[5];
    const float* Wv  = (const float*)d_in[6];
    const float* bv  = (const float*)d_in[7];
    const float* Wo  = (const float*)d_in[8];
    const float* bo  = (const float*)d_in[9];
    const float* g0  = (const float*)d_in[10];
    const float* be0 = (const float*)d_in[11];
    const float* g1  = (const float*)d_in[12];
    const float* be1 = (const float*)d_in[13];
    float* out = (float*)d_out;

    const int GEMM_SM = 6 * TILE_B;   // 110592 B
    const int PASS_SM = 4 * TILE_B;   //  73728 B
    cudaFuncSetAttribute(gemm_mma,  cudaFuncAttributeMaxDynamicSharedMemorySize, GEMM_SM);
    cudaFuncSetAttribute(stats_mma, cudaFuncAttributeMaxDynamicSharedMemorySize, PASS_SM);
    cudaFuncSetAttribute(attn_mma,  cudaFuncAttributeMaxDynamicSharedMemorySize, PASS_SM);

    f2h<<<dim3((MR * DD / 4) / 256, 2), 256>>>(Q, K);
    wtr<<<dim3(16, 16, 4), 256>>>(Wq, Wk, Wv, Wo);

    gemm_mma<<<dim3(4, 256, 3), 256, GEMM_SM>>>(bq, bk, bv, 0);  // QKV projections
    stats_mma<<<dim3(8, HBN), 256, PASS_SM>>>();                 // g_rz
    vtr<<<dim3(16, HBN), 256>>>();                               // g_vt16 = rz * V^T
    attn_mma<<<dim3(8, HBN), 256, PASS_SM>>>();                  // g_o
    ln_kernel<<<MR / 8, 256>>>(g0, be0, out, 0);                 // g_x32, g_x16
    gemm_mma<<<dim3(4, 256, 1), 256, GEMM_SM>>>(bo, bo, bo, 1);  // g_y32
    ln_kernel<<<MR / 8, 256>>>(g1, be1, out, 1);                 // out
}

// round 10
// speedup vs baseline: 5.6150x; 1.0154x over previous
#include <cuda_runtime.h>
#include <cuda_fp16.h>
#include <math.h>
#include <stdint.h>

#define BB 32
#define NN 1024
#define DD 512
#define HH 8
#define HD 64
#define MR (BB * NN)
#define HBN (HH * BB)
#define SCALE 0.044194173824159216f
#define ESF (SCALE * 1.4426950408889634f)   // folded into K projection
#define LDT 72
#define TILE_B (128 * LDT * 2)      // 18432 bytes per 128-row tile

// ---- device-global scratch -------------------------------------------------
__device__ float  g_q32[(size_t)MR * DD];
__device__ float  g_o  [(size_t)MR * DD];
__device__ float  g_x32[(size_t)MR * DD];
__device__ float  g_y32[(size_t)MR * DD];
__device__ __half g_x16 [(size_t)MR * DD];
__device__ __half g_qin16[(size_t)MR * DD];
__device__ __half g_kin16[(size_t)MR * DD];
__device__ __half g_q16[(size_t)MR * DD];
__device__ __half g_k16[(size_t)MR * DD];    // pre-scaled by ESF
__device__ __half g_v16[(size_t)MR * DD];
__device__ __half g_vt16[(size_t)MR * DD];   // [(hb*64 + d)][n], pre-scaled by rz
__device__ __half g_wt[4][DD * DD];          // W^T fp16 [n][k]
__device__ float  g_rz[HBN * NN];

// ---- helpers ---------------------------------------------------------------
__device__ __forceinline__ uint32_t s2u(const void* p) {
    uint32_t a;
    asm("{ .reg .u64 t; cvta.to.shared.u64 t, %1; cvt.u32.u64 %0, t; }" : "=r"(a) : "l"(p));
    return a;
}
__device__ __forceinline__ void ldsm4(uint32_t* r, uint32_t a) {
    asm volatile("ldmatrix.sync.aligned.m8n8.x4.shared.b16 {%0,%1,%2,%3}, [%4];"
        : "=r"(r[0]), "=r"(r[1]), "=r"(r[2]), "=r"(r[3]) : "r"(a));
}
__device__ __forceinline__ void mma_(float* c, const uint32_t* a, uint32_t b0, uint32_t b1) {
    asm volatile("mma.sync.aligned.m16n8k16.row.col.f32.f16.f16.f32 "
        "{%0,%1,%2,%3},{%4,%5,%6,%7},{%8,%9},{%0,%1,%2,%3};"
        : "+f"(c[0]), "+f"(c[1]), "+f"(c[2]), "+f"(c[3])
        : "r"(a[0]), "r"(a[1]), "r"(a[2]), "r"(a[3]), "r"(b0), "r"(b1));
}
__device__ __forceinline__ float ex2(float x) {
    float r;
    asm("ex2.approx.f32 %0, %1;" : "=f"(r) : "f"(x));
    return r;
}
__device__ __forceinline__ void cp16(uint32_t d, const void* s) {
    asm volatile("cp.async.cg.shared.global [%0], [%1], 16;" :: "r"(d), "l"(s) : "memory");
}
#define CPCOMMIT() asm volatile("cp.async.commit_group;" ::: "memory")
#define CPWAIT2()  asm volatile("cp.async.wait_group 2;" ::: "memory")
#define CPWAIT1()  asm volatile("cp.async.wait_group 1;" ::: "memory")
#define CPWAIT0()  asm volatile("cp.async.wait_group 0;" ::: "memory")

extern __shared__ __half dynsm[];

// ---- fused elementwise prep ------------------------------------------------
__global__ __launch_bounds__(256) void f2h(const float* __restrict__ Qin,
                                           const float* __restrict__ Kin) {
    const float* in = blockIdx.y ? Kin : Qin;
    __half* out = blockIdx.y ? g_kin16 : g_qin16;
    int i = blockIdx.x * 256 + threadIdx.x;
    float4 v = ((const float4*)in)[i];
    __half2 a = __floats2half2_rn(v.x, v.y), b = __floats2half2_rn(v.z, v.w);
    uint2 u = { *(uint32_t*)&a, *(uint32_t*)&b };
    ((uint2*)out)[i] = u;
}

__global__ __launch_bounds__(256) void wtr(const float* __restrict__ W0,
                                           const float* __restrict__ W1,
                                           const float* __restrict__ W2,
                                           const float* __restrict__ W3) {
    __shared__ float t[32][33];
    const int wz = blockIdx.z;
    const float* W = (wz == 0) ? W0 : (wz == 1) ? W1 : (wz == 2) ? W2 : W3;
    const int bx = blockIdx.x * 32, by = blockIdx.y * 32;
    const int tx = threadIdx.x & 31, ty = threadIdx.x >> 5;
    __half* Wt = g_wt[wz];
    #pragma unroll
    for (int i = 0; i < 4; i++)
        t[ty + 8 * i][tx] = W[(size_t)(bx + ty + 8 * i) * DD + by + tx];
    __syncthreads();
    #pragma unroll
    for (int i = 0; i < 4; i++)
        Wt[(size_t)(by + ty + 8 * i) * DD + bx + tx] = __float2half_rn(t[tx][ty + 8 * i]);
}

__global__ __launch_bounds__(256) void vtr() {
    const int hb = blockIdx.y, h = hb >> 5, b = hb & 31, nb = blockIdx.x * 64;
    __shared__ __half t[64][80];
    const int tid = threadIdx.x;
    #pragma unroll
    for (int i = 0; i < 2; i++) {
        int idx = tid + i * 256, r = idx >> 3, cc = (idx & 7) * 8;
        float4 v = *(const float4*)(g_v16 + (size_t)(b * NN + nb + r) * DD + h * HD + cc);
        __half2 rz2 = __float2half2_rn(g_rz[hb * NN + nb + r]);
        __half2* h2 = (__half2*)&v;
        #pragma unroll
        for (int j = 0; j < 4; j++) h2[j] = __hmul2(h2[j], rz2);
        *(float4*)&t[r][cc] = v;
    }
    __syncthreads();
    #pragma unroll
    for (int i = 0; i < 2; i++) {
        int idx = tid + i * 256, d = idx >> 3, nn = (idx & 7) * 8;
        __half o[8];
        #pragma unroll
        for (int u = 0; u < 8; u++) o[u] = t[nn + u][d];
        *(float4*)(g_vt16 + (size_t)(hb * 64 + d) * NN + nb + nn) = *(float4*)o;
    }
}

// ---- dense GEMM (triple-buffered cp.async, 1 sync/iter) --------------------
__global__ __launch_bounds__(256, 2)
void gemm_mma(const float* __restrict__ b0, const float* __restrict__ b1,
              const float* __restrict__ b2, int mode) {
    const int sel = mode ? 3 : blockIdx.z;
    const __half* A  = (sel == 0) ? g_qin16 : (sel == 3) ? g_x16 : g_kin16;
    const __half* Bt = g_wt[sel];
    const float* bias = (sel == 1) ? b1 : (sel == 2) ? b2 : b0;
    float*  C32 = (sel == 0) ? g_q32 : (sel == 3) ? g_y32 : nullptr;
    __half* C16 = (sel == 0) ? g_q16 : (sel == 1) ? g_k16 : (sel == 2) ? g_v16 : nullptr;
    const float cs = (sel == 1) ? ESF : 1.0f;   // fold softmax scale into K

    const int tid = threadIdx.x, wid = tid >> 5, lane = tid & 31;
    const int wm = wid & 1, wn = wid >> 1;
    const int bm = blockIdx.y * 128, bn = blockIdx.x * 128;
    const uint32_t base = s2u(dynsm);
    const int lrA = lane & 15, lcA = (lane >> 4) * 8;
    const int lrB = (lane & 7) + ((lane >> 4) << 3), lcB = ((lane >> 3) & 1) * 8;

    auto issue = [&](int kc, int st) {
        uint32_t uA = base + st * TILE_B, uB = base + 3 * TILE_B + st * TILE_B;
        #pragma unroll
        for (int t = 0; t < 4; t++) {
            int idx = tid + t * 256, row = idx >> 3, c8 = (idx & 7) * 8;
            cp16(uA + (row * LDT + c8) * 2, &A [(size_t)(bm + row) * DD + kc * 64 + c8]);
            cp16(uB + (row * LDT + c8) * 2, &Bt[(size_t)(bn + row) * DD + kc * 64 + c8]);
        }
        CPCOMMIT();
    };

    float acc[4][4][4];
    #pragma unroll
    for (int i = 0; i < 4; i++)
        #pragma unroll
        for (int j = 0; j < 4; j++)
            #pragma unroll
            for (int k = 0; k < 4; k++) acc[i][j][k] = 0.0f;

    issue(0, 0);
    issue(1, 1);
    for (int kc = 0; kc < 8; kc++) {
        if (kc < 7) CPWAIT1(); else CPWAIT0();
        __syncthreads();
        if (kc + 2 < 8) issue(kc + 2, (kc + 2) % 3);
        const int st = kc % 3;
        const uint32_t cA = base + st * TILE_B, cB = base + 3 * TILE_B + st * TILE_B;
        #pragma unroll
        for (int kk = 0; kk < 4; kk++) {
            uint32_t af[4][4];
            #pragma unroll
            for (int mt = 0; mt < 4; mt++)
                ldsm4(af[mt], cA + ((wm * 64 + mt * 16 + lrA) * LDT + kk * 16 + lcA) * 2);
            #pragma unroll
            for (int p = 0; p < 2; p++) {
                uint32_t bf[4];
                ldsm4(bf, cB + ((wn * 32 + p * 16 + lrB) * LDT + kk * 16 + lcB) * 2);
                #pragma unroll
                for (int mt = 0; mt < 4; mt++) {
                    mma_(acc[mt][p * 2],     af[mt], bf[0], bf[1]);
                    mma_(acc[mt][p * 2 + 1], af[mt], bf[2], bf[3]);
                }
            }
        }
    }
    #pragma unroll
    for (int mt = 0; mt < 4; mt++) {
        int r0 = bm + wm * 64 + mt * 16 + (lane >> 2);
        #pragma unroll
        for (int nt = 0; nt < 4; nt++) {
            int c = bn + wn * 32 + nt * 8 + (lane & 3) * 2;
            float2 bb = *(const float2*)&bias[c];
            float d0 = acc[mt][nt][0] + bb.x, d1 = acc[mt][nt][1] + bb.y;
            float d2 = acc[mt][nt][2] + bb.x, d3 = acc[mt][nt][3] + bb.y;
            if (C32) {
                float2 o0 = {d0, d1}, o1 = {d2, d3};
                *(float2*)&C32[(size_t)r0 * DD + c] = o0;
                *(float2*)&C32[(size_t)(r0 + 8) * DD + c] = o1;
            }
            if (C16) {
                __half2 h0 = __floats2half2_rn(d0 * cs, d1 * cs);
                __half2 h1 = __floats2half2_rn(d2 * cs, d3 * cs);
                *(__half2*)&C16[(size_t)r0 * DD + c] = h0;
                *(__half2*)&C16[(size_t)(r0 + 8) * DD + c] = h1;
            }
        }
    }
}

// ---- pass 1: Z_k = sum_q 2^(s_es) (triple-buffered Q, occ 3) ---------------
// dyn smem: K @0 ; Q stages @18432, 36864, 55296 (73728 B)
__global__ __launch_bounds__(256, 3)
void stats_mma() {
    const int tid = threadIdx.x, wid = tid >> 5, lane = tid & 31;
    const int hb = blockIdx.y, h = hb >> 5, b = hb & 31, kb = blockIdx.x * 128;
    const uint32_t base = s2u(dynsm);
    const uint32_t uK = base;
    const int lrA = lane & 15, lcA = (lane >> 4) * 8;
    const int lrB = (lane & 7) + ((lane >> 4) << 3), lcB = ((lane >> 3) & 1) * 8;

    auto issueQ = [&](int qc, int st) {
        uint32_t uQ = base + (1 + st) * TILE_B;
        #pragma unroll
        for (int t = 0; t < 4; t++) {
            int idx = tid + t * 256, row = idx >> 3, c8 = (idx & 7) * 8;
            cp16(uQ + (row * LDT + c8) * 2,
                 &g_q16[(size_t)(b * NN + qc * 128 + row) * DD + h * HD + c8]);
        }
        CPCOMMIT();
    };

    #pragma unroll
    for (int t = 0; t < 4; t++) {
        int idx = tid + t * 256, row = idx >> 3, c8 = (idx & 7) * 8;
        cp16(uK + (row * LDT + c8) * 2,
             &g_k16[(size_t)(b * NN + kb + row) * DD + h * HD + c8]);
    }
    CPCOMMIT();
    issueQ(0, 0);
    issueQ(1, 1);
    CPWAIT2();                 // K ready
    __syncthreads();
    uint32_t af[4][4];
    #pragma unroll
    for (int kk = 0; kk < 4; kk++)
        ldsm4(af[kk], uK + ((wid * 16 + lrA) * LDT + kk * 16 + lcA) * 2);

    // two partial accumulators each to break the FADD dependency chain
    float z0a = 0.0f, z0b = 0.0f, z1a = 0.0f, z1b = 0.0f;
    for (int qc = 0; qc < 8; qc++) {
        if (qc < 7) CPWAIT1(); else CPWAIT0();
        __syncthreads();
        if (qc + 2 < 8) issueQ(qc + 2, (qc + 2) % 3);
        const uint32_t cQ = base + (1 + qc % 3) * TILE_B;
        #pragma unroll
        for (int hlf = 0; hlf < 2; hlf++) {
            float s[8][4];
            #pragma unroll
            for (int i = 0; i < 8; i++)
                #pragma unroll
                for (int j = 0; j < 4; j++) s[i][j] = 0.0f;
            #pragma unroll
            for (int kk = 0; kk < 4; kk++) {
                #pragma unroll
                for (int p = 0; p < 4; p++) {
                    uint32_t bf[4];
                    ldsm4(bf, cQ + (((hlf * 4 + p) * 16 + lrB) * LDT + kk * 16 + lcB) * 2);
                    mma_(s[2 * p],     af[kk], bf[0], bf[1]);
                    mma_(s[2 * p + 1], af[kk], bf[2], bf[3]);
                }
            }
            #pragma unroll
            for (int nt = 0; nt < 8; nt += 2) {
                z0a += ex2(s[nt][0]) + ex2(s[nt][1]);
                z0b += ex2(s[nt + 1][0]) + ex2(s[nt + 1][1]);
                z1a += ex2(s[nt][2]) + ex2(s[nt][3]);
                z1b += ex2(s[nt + 1][2]) + ex2(s[nt + 1][3]);
            }
        }
    }
    float z0 = z0a + z0b, z1 = z1a + z1b;
    z0 += __shfl_xor_sync(0xFFFFFFFFu, z0, 1);
    z0 += __shfl_xor_sync(0xFFFFFFFFu, z0, 2);
    z1 += __shfl_xor_sync(0xFFFFFFFFu, z1, 1);
    z1 += __shfl_xor_sync(0xFFFFFFFFu, z1, 2);
    if ((lane & 3) == 0) {
        int k = kb + wid * 16 + (lane >> 2);
        g_rz[hb * NN + k] = 1.0f / z0;
        g_rz[hb * NN + k + 8] = 1.0f / z1;
    }
}

// ---- pass 2: O = qh + 2^(S_es) @ V' (interleaved S/exp/PV per g, occ 3) ----
// dyn smem: Q @0 ; KV stages @18432+s*18432 (K then V, 9216 each) (73728 B)
__global__ __launch_bounds__(256, 3)
void attn_mma() {
    const int tid = threadIdx.x, wid = tid >> 5, lane = tid & 31;
    const int hb = blockIdx.y, h = hb >> 5, b = hb & 31, qb = blockIdx.x * 128;
    const uint32_t base = s2u(dynsm);
    const uint32_t uQ = base;
    const int lrA = lane & 15, lcA = (lane >> 4) * 8;
    const int lrB = (lane & 7) + ((lane >> 4) << 3), lcB = ((lane >> 3) & 1) * 8;

    auto issueKV = [&](int kt, int st) {
        uint32_t uK = base + (1 + st) * TILE_B;
        uint32_t uV = uK + TILE_B / 2;
        #pragma unroll
        for (int t = 0; t < 2; t++) {
            int idx = tid + t * 256, row = idx >> 3, c8 = (idx & 7) * 8;
            cp16(uK + (row * LDT + c8) * 2,
                 &g_k16[(size_t)(b * NN + kt * 64 + row) * DD + h * HD + c8]);
            cp16(uV + (row * LDT + c8) * 2,
                 &g_vt16[(size_t)(hb * 64 + row) * NN + kt * 64 + c8]);
        }
        CPCOMMIT();
    };

    #pragma unroll
    for (int t = 0; t < 4; t++) {
        int idx = tid + t * 256, row = idx >> 3, c8 = (idx & 7) * 8;
        cp16(uQ + (row * LDT + c8) * 2,
             &g_q16[(size_t)(b * NN + qb + row) * DD + h * HD + c8]);
    }
    CPCOMMIT();
    issueKV(0, 0);
    issueKV(1, 1);
    CPWAIT2();                 // Q ready
    __syncthreads();
    uint32_t af[4][4];
    #pragma unroll
    for (int kk = 0; kk < 4; kk++)
        ldsm4(af[kk], uQ + ((wid * 16 + lrA) * LDT + kk * 16 + lcA) * 2);

    float o[8][4];
    #pragma unroll
    for (int i = 0; i < 8; i++)
        #pragma unroll
        for (int j = 0; j < 4; j++) o[i][j] = 0.0f;

    for (int kt = 0; kt < 16; kt++) {
        if (kt < 15) CPWAIT1(); else CPWAIT0();
        __syncthreads();
        if (kt + 2 < 16) issueKV(kt + 2, (kt + 2) % 3);
        const uint32_t cK = base + (1 + kt % 3) * TILE_B;
        const uint32_t cV = cK + TILE_B / 2;

        // per 16-wide k-subtile g: S pair -> exp -> PV (keeps live regs small)
        #pragma unroll
        for (int g = 0; g < 4; g++) {
            float s[2][4];
            #pragma unroll
            for (int j = 0; j < 4; j++) { s[0][j] = 0.0f; s[1][j] = 0.0f; }
            #pragma unroll
            for (int kk = 0; kk < 4; kk++) {
                uint32_t bf[4];
                ldsm4(bf, cK + ((g * 16 + lrB) * LDT + kk * 16 + lcB) * 2);
                mma_(s[0], af[kk], bf[0], bf[1]);
                mma_(s[1], af[kk], bf[2], bf[3]);
            }
            uint32_t aw[4];
            {
                __half2 hA = __floats2half2_rn(ex2(s[0][0]), ex2(s[0][1]));
                __half2 hB = __floats2half2_rn(ex2(s[0][2]), ex2(s[0][3]));
                __half2 hC = __floats2half2_rn(ex2(s[1][0]), ex2(s[1][1]));
                __half2 hD = __floats2half2_rn(ex2(s[1][2]), ex2(s[1][3]));
                aw[0] = *(uint32_t*)&hA;
                aw[1] = *(uint32_t*)&hB;
                aw[2] = *(uint32_t*)&hC;
                aw[3] = *(uint32_t*)&hD;
            }
            #pragma unroll
            for (int p = 0; p < 4; p++) {
                uint32_t bf[4];
                ldsm4(bf, cV + ((p * 16 + lrB) * LDT + g * 16 + lcB) * 2);
                mma_(o[2 * p],     aw, bf[0], bf[1]);
                mma_(o[2 * p + 1], aw, bf[2], bf[3]);
            }
        }
    }
    int q0 = b * NN + qb + wid * 16 + (lane >> 2);
    #pragma unroll
    for (int nt = 0; nt < 8; nt++) {
        int c = h * HD + nt * 8 + (lane & 3) * 2;
        float2 r0v = *(const float2*)&g_q32[(size_t)q0 * DD + c];
        float2 r1v = *(const float2*)&g_q32[(size_t)(q0 + 8) * DD + c];
        float2 o0 = {o[nt][0] + r0v.x, o[nt][1] + r0v.y};
        float2 o1 = {o[nt][2] + r1v.x, o[nt][3] + r1v.y};
        *(float2*)&g_o[(size_t)q0 * DD + c] = o0;
        *(float2*)&g_o[(size_t)(q0 + 8) * DD + c] = o1;
    }
}

// ---- LayerNorm -------------------------------------------------------------
__global__ __launch_bounds__(256)
void ln_kernel(const float* __restrict__ gamma, const float* __restrict__ beta,
               float* __restrict__ out, int mode) {
    const int row = (blockIdx.x * blockDim.x + threadIdx.x) >> 5;
    const int lane = threadIdx.x & 31;
    float4 v[4];
    if (mode == 0) {
        const float4* p = (const float4*)(g_o + (size_t)row * DD);
        #pragma unroll
        for (int i = 0; i < 4; i++) v[i] = p[lane + i * 32];
    } else {
        const float4* px = (const float4*)(g_x32 + (size_t)row * DD);
        const float4* py = (const float4*)(g_y32 + (size_t)row * DD);
        #pragma unroll
        for (int i = 0; i < 4; i++) {
            float4 a = px[lane + i * 32], bq = py[lane + i * 32];
            v[i].x = a.x + fmaxf(bq.x, 0.0f); v[i].y = a.y + fmaxf(bq.y, 0.0f);
            v[i].z = a.z + fmaxf(bq.z, 0.0f); v[i].w = a.w + fmaxf(bq.w, 0.0f);
        }
    }
    float s = 0.0f, ss = 0.0f;
    #pragma unroll
    for (int i = 0; i < 4; i++) {
        s  += v[i].x + v[i].y + v[i].z + v[i].w;
        ss += v[i].x*v[i].x + v[i].y*v[i].y + v[i].z*v[i].z + v[i].w*v[i].w;
    }
    #pragma unroll
    for (int off = 16; off > 0; off >>= 1) {
        s  += __shfl_xor_sync(0xFFFFFFFFu, s, off);
        ss += __shfl_xor_sync(0xFFFFFFFFu, ss, off);
    }
    const float mean = s * (1.0f / 512.0f);
    const float var  = ss * (1.0f / 512.0f) - mean * mean;
    const float rstd = rsqrtf(var + 1e-5f);
    #pragma unroll
    for (int i = 0; i < 4; i++) {
        int c0 = (lane + i * 32) * 4;
        float4 g4 = *(const float4*)&gamma[c0];
        float4 b4 = *(const float4*)&beta[c0];
        float4 ov;
        ov.x = (v[i].x - mean) * rstd * g4.x + b4.x;
        ov.y = (v[i].y - mean) * rstd * g4.y + b4.y;
        ov.z = (v[i].z - mean) * rstd * g4.z + b4.z;
        ov.w = (v[i].w - mean) * rstd * g4.w + b4.w;
        if (mode == 0) {
            *(float4*)(g_x32 + (size_t)row * DD + c0) = ov;
            __half2 h0 = __floats2half2_rn(ov.x, ov.y), h1 = __floats2half2_rn(ov.z, ov.w);
            uint2 u = { *(uint32_t*)&h0, *(uint32_t*)&h1 };
            *(uint2*)(g_x16 + (size_t)row * DD + c0) = u;
        } else {
            *(float4*)(out + (size_t)row * DD + c0) = ov;
        }
    }
}

// ---- launch ----------------------------------------------------------------
extern "C" void kernel_launch(void* const* d_in, const int* in_sizes, int n_in,
                              void* d_out, int out_size) {
    (void)in_sizes; (void)n_in; (void)out_size;
    const float* Q   = (const float*)d_in[0];
    const float* K   = (const float*)d_in[1];
    const float* Wq  = (const float*)d_in[2];
    const float* bq  = (const float*)d_in[3];
    const float* Wk  = (const float*)d_in[4];
    const float* bk  = (const float*)d_in[5];
    const float* Wv  = (const float*)d_in[6];
    const float* bv  = (const float*)d_in[7];
    const float* Wo  = (const float*)d_in[8];
    const float* bo  = (const float*)d_in[9];
    const float* g0  = (const float*)d_in[10];
    const float* be0 = (const float*)d_in[11];
    const float* g1  = (const float*)d_in[12];
    const float* be1 = (const float*)d_in[13];
    float* out = (float*)d_out;

    const int GEMM_SM = 6 * TILE_B;   // 110592 B
    const int PASS_SM = 4 * TILE_B;   //  73728 B
    cudaFuncSetAttribute(gemm_mma,  cudaFuncAttributeMaxDynamicSharedMemorySize, GEMM_SM);
    cudaFuncSetAttribute(stats_mma, cudaFuncAttributeMaxDynamicSharedMemorySize, PASS_SM);
    cudaFuncSetAttribute(attn_mma,  cudaFuncAttributeMaxDynamicSharedMemorySize, PASS_SM);

    f2h<<<dim3((MR * DD / 4) / 256, 2), 256>>>(Q, K);
    wtr<<<dim3(16, 16, 4), 256>>>(Wq, Wk, Wv, Wo);

    gemm_mma<<<dim3(4, 256, 3), 256, GEMM_SM>>>(bq, bk, bv, 0);  // QKV projections
    stats_mma<<<dim3(8, HBN), 256, PASS_SM>>>();                 // g_rz
    vtr<<<dim3(16, HBN), 256>>>();                               // g_vt16 = rz * V^T
    attn_mma<<<dim3(8, HBN), 256, PASS_SM>>>();                  // g_o
    ln_kernel<<<MR / 8, 256>>>(g0, be0, out, 0);                 // g_x32, g_x16
    gemm_mma<<<dim3(4, 256, 1), 256, GEMM_SM>>>(bo, bo, bo, 1);  // g_y32
    ln_kernel<<<MR / 8, 256>>>(g1, be1, out, 1);                 // out
}

// round 11
// speedup vs baseline: 5.6917x; 1.0137x over previous
#include <cuda_runtime.h>
#include <cuda_fp16.h>
#include <math.h>
#include <stdint.h>

#define BB 32
#define NN 1024
#define DD 512
#define HH 8
#define HD 64
#define MR (BB * NN)
#define HBN (HH * BB)
#define SCALE 0.044194173824159216f
#define ESF (SCALE * 1.4426950408889634f)   // folded into K projection
#define LDT 72
#define TILE_B (128 * LDT * 2)      // 18432 bytes per 128-row tile

// ---- device-global scratch -------------------------------------------------
__device__ float  g_q32[(size_t)MR * DD];
__device__ float  g_o  [(size_t)MR * DD];
__device__ float  g_x32[(size_t)MR * DD];
__device__ float  g_y32[(size_t)MR * DD];
__device__ __half g_x16 [(size_t)MR * DD];
__device__ __half g_qin16[(size_t)MR * DD];
__device__ __half g_kin16[(size_t)MR * DD];
__device__ __half g_q16[(size_t)MR * DD];
__device__ __half g_k16[(size_t)MR * DD];    // pre-scaled by ESF
__device__ __half g_v16[(size_t)MR * DD];
__device__ __half g_vt16[(size_t)MR * DD];   // [(hb*64 + d)][n], pre-scaled by rz

__device__ __half g_wt[4][DD * DD];          // W^T fp16 [n][k]

// ---- helpers ---------------------------------------------------------------
__device__ __forceinline__ uint32_t s2u(const void* p) {
    uint32_t a;
    asm("{ .reg .u64 t; cvta.to.shared.u64 t, %1; cvt.u32.u64 %0, t; }" : "=r"(a) : "l"(p));
    return a;
}
__device__ __forceinline__ void ldsm4(uint32_t* r, uint32_t a) {
    asm volatile("ldmatrix.sync.aligned.m8n8.x4.shared.b16 {%0,%1,%2,%3}, [%4];"
        : "=r"(r[0]), "=r"(r[1]), "=r"(r[2]), "=r"(r[3]) : "r"(a));
}
__device__ __forceinline__ void mma_(float* c, const uint32_t* a, uint32_t b0, uint32_t b1) {
    asm volatile("mma.sync.aligned.m16n8k16.row.col.f32.f16.f16.f32 "
        "{%0,%1,%2,%3},{%4,%5,%6,%7},{%8,%9},{%0,%1,%2,%3};"
        : "+f"(c[0]), "+f"(c[1]), "+f"(c[2]), "+f"(c[3])
        : "r"(a[0]), "r"(a[1]), "r"(a[2]), "r"(a[3]), "r"(b0), "r"(b1));
}
// packed half2 2^x on the MUFU pipe — halves exp op count
__device__ __forceinline__ uint32_t ex2h2(uint32_t x) {
    uint32_t r;
    asm("ex2.approx.f16x2 %0, %1;" : "=r"(r) : "r"(x));
    return r;
}
__device__ __forceinline__ uint32_t packh2(float a, float b) {
    __half2 h = __floats2half2_rn(a, b);
    return *(uint32_t*)&h;
}
__device__ __forceinline__ void cp16(uint32_t d, const void* s) {
    asm volatile("cp.async.cg.shared.global [%0], [%1], 16;" :: "r"(d), "l"(s) : "memory");
}
#define CPCOMMIT() asm volatile("cp.async.commit_group;" ::: "memory")
#define CPWAIT2()  asm volatile("cp.async.wait_group 2;" ::: "memory")
#define CPWAIT1()  asm volatile("cp.async.wait_group 1;" ::: "memory")
#define CPWAIT0()  asm volatile("cp.async.wait_group 0;" ::: "memory")

extern __shared__ __half dynsm[];

// ---- fused elementwise prep ------------------------------------------------
__global__ __launch_bounds__(256) void f2h(const float* __restrict__ Qin,
                                           const float* __restrict__ Kin) {
    const float* in = blockIdx.y ? Kin : Qin;
    __half* out = blockIdx.y ? g_kin16 : g_qin16;
    int i = blockIdx.x * 256 + threadIdx.x;
    float4 v = ((const float4*)in)[i];
    __half2 a = __floats2half2_rn(v.x, v.y), b = __floats2half2_rn(v.z, v.w);
    uint2 u = { *(uint32_t*)&a, *(uint32_t*)&b };
    ((uint2*)out)[i] = u;
}

__global__ __launch_bounds__(256) void wtr(const float* __restrict__ W0,
                                           const float* __restrict__ W1,
                                           const float* __restrict__ W2,
                                           const float* __restrict__ W3) {
    __shared__ float t[32][33];
    const int wz = blockIdx.z;
    const float* W = (wz == 0) ? W0 : (wz == 1) ? W1 : (wz == 2) ? W2 : W3;
    const int bx = blockIdx.x * 32, by = blockIdx.y * 32;
    const int tx = threadIdx.x & 31, ty = threadIdx.x >> 5;
    __half* Wt = g_wt[wz];
    #pragma unroll
    for (int i = 0; i < 4; i++)
        t[ty + 8 * i][tx] = W[(size_t)(bx + ty + 8 * i) * DD + by + tx];
    __syncthreads();
    #pragma unroll
    for (int i = 0; i < 4; i++)
        Wt[(size_t)(by + ty + 8 * i) * DD + bx + tx] = __float2half_rn(t[tx][ty + 8 * i]);
}

// ---- dense GEMM (triple-buffered cp.async, 1 sync/iter) --------------------
__global__ __launch_bounds__(256, 2)
void gemm_mma(const float* __restrict__ b0, const float* __restrict__ b1,
              const float* __restrict__ b2, int mode) {
    const int sel = mode ? 3 : blockIdx.z;
    const __half* A  = (sel == 0) ? g_qin16 : (sel == 3) ? g_x16 : g_kin16;
    const __half* Bt = g_wt[sel];
    const float* bias = (sel == 1) ? b1 : (sel == 2) ? b2 : b0;
    float*  C32 = (sel == 0) ? g_q32 : (sel == 3) ? g_y32 : nullptr;
    __half* C16 = (sel == 0) ? g_q16 : (sel == 1) ? g_k16 : (sel == 2) ? g_v16 : nullptr;
    const float cs = (sel == 1) ? ESF : 1.0f;   // fold softmax scale into K

    const int tid = threadIdx.x, wid = tid >> 5, lane = tid & 31;
    const int wm = wid & 1, wn = wid >> 1;
    const int bm = blockIdx.y * 128, bn = blockIdx.x * 128;
    const uint32_t base = s2u(dynsm);
    const int lrA = lane & 15, lcA = (lane >> 4) * 8;
    const int lrB = (lane & 7) + ((lane >> 4) << 3), lcB = ((lane >> 3) & 1) * 8;

    auto issue = [&](int kc, int st) {
        uint32_t uA = base + st * TILE_B, uB = base + 3 * TILE_B + st * TILE_B;
        #pragma unroll
        for (int t = 0; t < 4; t++) {
            int idx = tid + t * 256, row = idx >> 3, c8 = (idx & 7) * 8;
            cp16(uA + (row * LDT + c8) * 2, &A [(size_t)(bm + row) * DD + kc * 64 + c8]);
            cp16(uB + (row * LDT + c8) * 2, &Bt[(size_t)(bn + row) * DD + kc * 64 + c8]);
        }
        CPCOMMIT();
    };

    float acc[4][4][4];
    #pragma unroll
    for (int i = 0; i < 4; i++)
        #pragma unroll
        for (int j = 0; j < 4; j++)
            #pragma unroll
            for (int k = 0; k < 4; k++) acc[i][j][k] = 0.0f;

    issue(0, 0);
    issue(1, 1);
    for (int kc = 0; kc < 8; kc++) {
        if (kc < 7) CPWAIT1(); else CPWAIT0();
        __syncthreads();
        if (kc + 2 < 8) issue(kc + 2, (kc + 2) % 3);
        const int st = kc % 3;
        const uint32_t cA = base + st * TILE_B, cB = base + 3 * TILE_B + st * TILE_B;
        #pragma unroll
        for (int kk = 0; kk < 4; kk++) {
            uint32_t af[4][4];
            #pragma unroll
            for (int mt = 0; mt < 4; mt++)
                ldsm4(af[mt], cA + ((wm * 64 + mt * 16 + lrA) * LDT + kk * 16 + lcA) * 2);
            #pragma unroll
            for (int p = 0; p < 2; p++) {
                uint32_t bf[4];
                ldsm4(bf, cB + ((wn * 32 + p * 16 + lrB) * LDT + kk * 16 + lcB) * 2);
                #pragma unroll
                for (int mt = 0; mt < 4; mt++) {
                    mma_(acc[mt][p * 2],     af[mt], bf[0], bf[1]);
                    mma_(acc[mt][p * 2 + 1], af[mt], bf[2], bf[3]);
                }
            }
        }
    }
    #pragma unroll
    for (int mt = 0; mt < 4; mt++) {
        int r0 = bm + wm * 64 + mt * 16 + (lane >> 2);
        #pragma unroll
        for (int nt = 0; nt < 4; nt++) {
            int c = bn + wn * 32 + nt * 8 + (lane & 3) * 2;
            float2 bb = *(const float2*)&bias[c];
            float d0 = acc[mt][nt][0] + bb.x, d1 = acc[mt][nt][1] + bb.y;
            float d2 = acc[mt][nt][2] + bb.x, d3 = acc[mt][nt][3] + bb.y;
            if (C32) {
                float2 o0 = {d0, d1}, o1 = {d2, d3};
                *(float2*)&C32[(size_t)r0 * DD + c] = o0;
                *(float2*)&C32[(size_t)(r0 + 8) * DD + c] = o1;
            }
            if (C16) {
                __half2 h0 = __floats2half2_rn(d0 * cs, d1 * cs);
                __half2 h1 = __floats2half2_rn(d2 * cs, d3 * cs);
                *(__half2*)&C16[(size_t)r0 * DD + c] = h0;
                *(__half2*)&C16[(size_t)(r0 + 8) * DD + c] = h1;
            }
        }
    }
}

// ---- pass 1: Z_k = sum_q 2^(s_es) + fused V-scale/transpose epilogue -------
// dyn smem: K @0 ; Q stages @18432, 36864, 55296 (73728 B)
// epilogue reuses Q stage0 as transpose buffer, stage1 as rz[128]
__global__ __launch_bounds__(256, 3)
void stats_mma() {
    const int tid = threadIdx.x, wid = tid >> 5, lane = tid & 31;
    const int hb = blockIdx.y, h = hb >> 5, b = hb & 31, kb = blockIdx.x * 128;
    const uint32_t base = s2u(dynsm);
    const uint32_t uK = base;
    const int lrA = lane & 15, lcA = (lane >> 4) * 8;
    const int lrB = (lane & 7) + ((lane >> 4) << 3), lcB = ((lane >> 3) & 1) * 8;

    auto issueQ = [&](int qc, int st) {
        uint32_t uQ = base + (1 + st) * TILE_B;
        #pragma unroll
        for (int t = 0; t < 4; t++) {
            int idx = tid + t * 256, row = idx >> 3, c8 = (idx & 7) * 8;
            cp16(uQ + (row * LDT + c8) * 2,
                 &g_q16[(size_t)(b * NN + qc * 128 + row) * DD + h * HD + c8]);
        }
        CPCOMMIT();
    };

    #pragma unroll
    for (int t = 0; t < 4; t++) {
        int idx = tid + t * 256, row = idx >> 3, c8 = (idx & 7) * 8;
        cp16(uK + (row * LDT + c8) * 2,
             &g_k16[(size_t)(b * NN + kb + row) * DD + h * HD + c8]);
    }
    CPCOMMIT();
    issueQ(0, 0);
    issueQ(1, 1);
    CPWAIT2();                 // K ready
    __syncthreads();
    uint32_t af[4][4];
    #pragma unroll
    for (int kk = 0; kk < 4; kk++)
        ldsm4(af[kk], uK + ((wid * 16 + lrA) * LDT + kk * 16 + lcA) * 2);

    float z0a = 0.0f, z0b = 0.0f, z1a = 0.0f, z1b = 0.0f;
    for (int qc = 0; qc < 8; qc++) {
        if (qc < 7) CPWAIT1(); else CPWAIT0();
        __syncthreads();
        if (qc + 2 < 8) issueQ(qc + 2, (qc + 2) % 3);
        const uint32_t cQ = base + (1 + qc % 3) * TILE_B;
        #pragma unroll
        for (int hlf = 0; hlf < 2; hlf++) {
            float s[8][4];
            #pragma unroll
            for (int i = 0; i < 8; i++)
                #pragma unroll
                for (int j = 0; j < 4; j++) s[i][j] = 0.0f;
            #pragma unroll
            for (int kk = 0; kk < 4; kk++) {
                #pragma unroll
                for (int p = 0; p < 4; p++) {
                    uint32_t bf[4];
                    ldsm4(bf, cQ + (((hlf * 4 + p) * 16 + lrB) * LDT + kk * 16 + lcB) * 2);
                    mma_(s[2 * p],     af[kk], bf[0], bf[1]);
                    mma_(s[2 * p + 1], af[kk], bf[2], bf[3]);
                }
            }
            #pragma unroll
            for (int nt = 0; nt < 8; nt += 2) {
                uint32_t e0 = ex2h2(packh2(s[nt][0],     s[nt][1]));
                uint32_t e1 = ex2h2(packh2(s[nt + 1][0], s[nt + 1][1]));
                uint32_t e2 = ex2h2(packh2(s[nt][2],     s[nt][3]));
                uint32_t e3 = ex2h2(packh2(s[nt + 1][2], s[nt + 1][3]));
                float2 f0 = __half22float2(*(__half2*)&e0);
                float2 f1 = __half22float2(*(__half2*)&e1);
                float2 f2 = __half22float2(*(__half2*)&e2);
                float2 f3 = __half22float2(*(__half2*)&e3);
                z0a += f0.x + f0.y;
                z0b += f1.x + f1.y;
                z1a += f2.x + f2.y;
                z1b += f3.x + f3.y;
            }
        }
    }
    float z0 = z0a + z0b, z1 = z1a + z1b;
    z0 += __shfl_xor_sync(0xFFFFFFFFu, z0, 1);
    z0 += __shfl_xor_sync(0xFFFFFFFFu, z0, 2);
    z1 += __shfl_xor_sync(0xFFFFFFFFu, z1, 1);
    z1 += __shfl_xor_sync(0xFFFFFFFFu, z1, 2);

    // ---- fused vtr epilogue: g_vt16[(hb*64+d)][kb+k] = rz_k * v16[k][d] ----
    float* srz = (float*)((char*)dynsm + 2 * TILE_B);        // 512 B
    __half (*t)[80] = (__half(*)[80])((char*)dynsm + TILE_B); // 10240 B
    if ((lane & 3) == 0) {
        int kloc = wid * 16 + (lane >> 2);
        srz[kloc] = 1.0f / z0;
        srz[kloc + 8] = 1.0f / z1;
    }
    __syncthreads();
    #pragma unroll
    for (int half_ = 0; half_ < 2; half_++) {
        const int r0 = half_ * 64;
        #pragma unroll
        for (int i = 0; i < 2; i++) {
            int idx = tid + i * 256, r = idx >> 3, cc = (idx & 7) * 8;
            float4 v = *(const float4*)(g_v16 + (size_t)(b * NN + kb + r0 + r) * DD + h * HD + cc);
            __half2 rz2 = __float2half2_rn(srz[r0 + r]);
            __half2* h2 = (__half2*)&v;
            #pragma unroll
            for (int j = 0; j < 4; j++) h2[j] = __hmul2(h2[j], rz2);
            *(float4*)&t[r][cc] = v;
        }
        __syncthreads();
        #pragma unroll
        for (int i = 0; i < 2; i++) {
            int idx = tid + i * 256, d = idx >> 3, nn = (idx & 7) * 8;
            __half o[8];
            #pragma unroll
            for (int u = 0; u < 8; u++) o[u] = t[nn + u][d];
            *(float4*)(g_vt16 + (size_t)(hb * 64 + d) * NN + kb + r0 + nn) = *(float4*)o;
        }
        __syncthreads();
    }
}

// ---- pass 2: O = qh + 2^(S_es) @ V' (f16x2 exp, occ 3) ---------------------
// dyn smem: Q @0 ; KV stages @18432+s*18432 (K then V, 9216 each) (73728 B)
__global__ __launch_bounds__(256, 3)
void attn_mma() {
    const int tid = threadIdx.x, wid = tid >> 5, lane = tid & 31;
    const int hb = blockIdx.y, h = hb >> 5, b = hb & 31, qb = blockIdx.x * 128;
    const uint32_t base = s2u(dynsm);
    const uint32_t uQ = base;
    const int lrA = lane & 15, lcA = (lane >> 4) * 8;
    const int lrB = (lane & 7) + ((lane >> 4) << 3), lcB = ((lane >> 3) & 1) * 8;

    auto issueKV = [&](int kt, int st) {
        uint32_t uK = base + (1 + st) * TILE_B;
        uint32_t uV = uK + TILE_B / 2;
        #pragma unroll
        for (int t = 0; t < 2; t++) {
            int idx = tid + t * 256, row = idx >> 3, c8 = (idx & 7) * 8;
            cp16(uK + (row * LDT + c8) * 2,
                 &g_k16[(size_t)(b * NN + kt * 64 + row) * DD + h * HD + c8]);
            cp16(uV + (row * LDT + c8) * 2,
                 &g_vt16[(size_t)(hb * 64 + row) * NN + kt * 64 + c8]);
        }
        CPCOMMIT();
    };

    #pragma unroll
    for (int t = 0; t < 4; t++) {
        int idx = tid + t * 256, row = idx >> 3, c8 = (idx & 7) * 8;
        cp16(uQ + (row * LDT + c8) * 2,
             &g_q16[(size_t)(b * NN + qb + row) * DD + h * HD + c8]);
    }
    CPCOMMIT();
    issueKV(0, 0);
    issueKV(1, 1);
    CPWAIT2();                 // Q ready
    __syncthreads();
    uint32_t af[4][4];
    #pragma unroll
    for (int kk = 0; kk < 4; kk++)
        ldsm4(af[kk], uQ + ((wid * 16 + lrA) * LDT + kk * 16 + lcA) * 2);

    float o[8][4];
    #pragma unroll
    for (int i = 0; i < 8; i++)
        #pragma unroll
        for (int j = 0; j < 4; j++) o[i][j] = 0.0f;

    for (int kt = 0; kt < 16; kt++) {
        if (kt < 15) CPWAIT1(); else CPWAIT0();
        __syncthreads();
        if (kt + 2 < 16) issueKV(kt + 2, (kt + 2) % 3);
        const uint32_t cK = base + (1 + kt % 3) * TILE_B;
        const uint32_t cV = cK + TILE_B / 2;

        #pragma unroll
        for (int g = 0; g < 4; g++) {
            float s[2][4];
            #pragma unroll
            for (int j = 0; j < 4; j++) { s[0][j] = 0.0f; s[1][j] = 0.0f; }
            #pragma unroll
            for (int kk = 0; kk < 4; kk++) {
                uint32_t bf[4];
                ldsm4(bf, cK + ((g * 16 + lrB) * LDT + kk * 16 + lcB) * 2);
                mma_(s[0], af[kk], bf[0], bf[1]);
                mma_(s[1], af[kk], bf[2], bf[3]);
            }
            uint32_t aw[4];
            aw[0] = ex2h2(packh2(s[0][0], s[0][1]));
            aw[1] = ex2h2(packh2(s[0][2], s[0][3]));
            aw[2] = ex2h2(packh2(s[1][0], s[1][1]));
            aw[3] = ex2h2(packh2(s[1][2], s[1][3]));
            #pragma unroll
            for (int p = 0; p < 4; p++) {
                uint32_t bf[4];
                ldsm4(bf, cV + ((p * 16 + lrB) * LDT + g * 16 + lcB) * 2);
                mma_(o[2 * p],     aw, bf[0], bf[1]);
                mma_(o[2 * p + 1], aw, bf[2], bf[3]);
            }
        }
    }
    int q0 = b * NN + qb + wid * 16 + (lane >> 2);
    #pragma unroll
    for (int nt = 0; nt < 8; nt++) {
        int c = h * HD + nt * 8 + (lane & 3) * 2;
        float2 r0v = *(const float2*)&g_q32[(size_t)q0 * DD + c];
        float2 r1v = *(const float2*)&g_q32[(size_t)(q0 + 8) * DD + c];
        float2 o0 = {o[nt][0] + r0v.x, o[nt][1] + r0v.y};
        float2 o1 = {o[nt][2] + r1v.x, o[nt][3] + r1v.y};
        *(float2*)&g_o[(size_t)q0 * DD + c] = o0;
        *(float2*)&g_o[(size_t)(q0 + 8) * DD + c] = o1;
    }
}

// ---- LayerNorm -------------------------------------------------------------
__global__ __launch_bounds__(256)
void ln_kernel(const float* __restrict__ gamma, const float* __restrict__ beta,
               float* __restrict__ out, int mode) {
    const int row = (blockIdx.x * blockDim.x + threadIdx.x) >> 5;
    const int lane = threadIdx.x & 31;
    float4 v[4];
    if (mode == 0) {
        const float4* p = (const float4*)(g_o + (size_t)row * DD);
        #pragma unroll
        for (int i = 0; i < 4; i++) v[i] = p[lane + i * 32];
    } else {
        const float4* px = (const float4*)(g_x32 + (size_t)row * DD);
        const float4* py = (const float4*)(g_y32 + (size_t)row * DD);
        #pragma unroll
        for (int i = 0; i < 4; i++) {
            float4 a = px[lane + i * 32], bq = py[lane + i * 32];
            v[i].x = a.x + fmaxf(bq.x, 0.0f); v[i].y = a.y + fmaxf(bq.y, 0.0f);
            v[i].z = a.z + fmaxf(bq.z, 0.0f); v[i].w = a.w + fmaxf(bq.w, 0.0f);
        }
    }
    float s = 0.0f, ss = 0.0f;
    #pragma unroll
    for (int i = 0; i < 4; i++) {
        s  += v[i].x + v[i].y + v[i].z + v[i].w;
        ss += v[i].x*v[i].x + v[i].y*v[i].y + v[i].z*v[i].z + v[i].w*v[i].w;
    }
    #pragma unroll
    for (int off = 16; off > 0; off >>= 1) {
        s  += __shfl_xor_sync(0xFFFFFFFFu, s, off);
        ss += __shfl_xor_sync(0xFFFFFFFFu, ss, off);
    }
    const float mean = s * (1.0f / 512.0f);
    const float var  = ss * (1.0f / 512.0f) - mean * mean;
    const float rstd = rsqrtf(var + 1e-5f);
    #pragma unroll
    for (int i = 0; i < 4; i++) {
        int c0 = (lane + i * 32) * 4;
        float4 g4 = *(const float4*)&gamma[c0];
        float4 b4 = *(const float4*)&beta[c0];
        float4 ov;
        ov.x = (v[i].x - mean) * rstd * g4.x + b4.x;
        ov.y = (v[i].y - mean) * rstd * g4.y + b4.y;
        ov.z = (v[i].z - mean) * rstd * g4.z + b4.z;
        ov.w = (v[i].w - mean) * rstd * g4.w + b4.w;
        if (mode == 0) {
            *(float4*)(g_x32 + (size_t)row * DD + c0) = ov;
            __half2 h0 = __floats2half2_rn(ov.x, ov.y), h1 = __floats2half2_rn(ov.z, ov.w);
            uint2 u = { *(uint32_t*)&h0, *(uint32_t*)&h1 };
            *(uint2*)(g_x16 + (size_t)row * DD + c0) = u;
        } else {
            *(float4*)(out + (size_t)row * DD + c0) = ov;
        }
    }
}

// ---- launch ----------------------------------------------------------------
extern "C" void kernel_launch(void* const* d_in, const int* in_sizes, int n_in,
                              void* d_out, int out_size) {
    (void)in_sizes; (void)n_in; (void)out_size;
    const float* Q   = (const float*)d_in[0];
    const float* K   = (const float*)d_in[1];
    const float* Wq  = (const float*)d_in[2];
    const float* bq  = (const float*)d_in[3];
    const float* Wk  = (const float*)d_in[4];
    const float* bk  = (const float*)d_in[5];
    const float* Wv  = (const float*)d_in[6];
    const float* bv  = (const float*)d_in[7];
    const float* Wo  = (const float*)d_in[8];
    const float* bo  = (const float*)d_in[9];
    const float* g0  = (const float*)d_in[10];
    const float* be0 = (const float*)d_in[11];
    const float* g1  = (const float*)d_in[12];
    const float* be1 = (const float*)d_in[13];
    float* out = (float*)d_out;

    const int GEMM_SM = 6 * TILE_B;   // 110592 B
    const int PASS_SM = 4 * TILE_B;   //  73728 B
    cudaFuncSetAttribute(gemm_mma,  cudaFuncAttributeMaxDynamicSharedMemorySize, GEMM_SM);
    cudaFuncSetAttribute(stats_mma, cudaFuncAttributeMaxDynamicSharedMemorySize, PASS_SM);
    cudaFuncSetAttribute(attn_mma,  cudaFuncAttributeMaxDynamicSharedMemorySize, PASS_SM);

    f2h<<<dim3((MR * DD / 4) / 256, 2), 256>>>(Q, K);
    wtr<<<dim3(16, 16, 4), 256>>>(Wq, Wk, Wv, Wo);

    gemm_mma<<<dim3(4, 256, 3), 256, GEMM_SM>>>(bq, bk, bv, 0);  // QKV projections
    stats_mma<<<dim3(8, HBN), 256, PASS_SM>>>();                 // rz + g_vt16 fused
    attn_mma<<<dim3(8, HBN), 256, PASS_SM>>>();                  // g_o
    ln_kernel<<<MR / 8, 256>>>(g0, be0, out, 0);                 // g_x32, g_x16
    gemm_mma<<<dim3(4, 256, 1), 256, GEMM_SM>>>(bo, bo, bo, 1);  // g_y32
    ln_kernel<<<MR / 8, 256>>>(g1, be1, out, 1);                 // out
}

// round 12
// speedup vs baseline: 5.7164x; 1.0043x over previous
#include <cuda_runtime.h>
#include <cuda_fp16.h>
#include <math.h>
#include <stdint.h>

#define BB 32
#define NN 1024
#define DD 512
#define HH 8
#define HD 64
#define MR (BB * NN)
#define HBN (HH * BB)
#define SCALE 0.044194173824159216f
#define ESF (SCALE * 1.4426950408889634f)   // folded into K projection
#define LDT 72
#define TILE_B (128 * LDT * 2)      // 18432 bytes per 128-row tile
#define KV_STG (9216 + 9216 + 256)  // K tile + V tile + lrz[64]

// ---- device-global scratch -------------------------------------------------
__device__ float  g_q32[(size_t)MR * DD];
__device__ float  g_o  [(size_t)MR * DD];
__device__ float  g_x32[(size_t)MR * DD];
__device__ float  g_y32[(size_t)MR * DD];
__device__ __half g_x16 [(size_t)MR * DD];
__device__ __half g_qin16[(size_t)MR * DD];
__device__ __half g_kin16[(size_t)MR * DD];
__device__ __half g_q16[(size_t)MR * DD];
__device__ __half g_k16[(size_t)MR * DD];    // pre-scaled by ESF
__device__ __half g_v16[(size_t)MR * DD];
__device__ __half g_wt[4][DD * DD];          // W^T fp16 [n][k]
__device__ float  g_rz[HBN * NN];            // per (hb,k): -log2(Z_k)

// ---- helpers ---------------------------------------------------------------
__device__ __forceinline__ uint32_t s2u(const void* p) {
    uint32_t a;
    asm("{ .reg .u64 t; cvta.to.shared.u64 t, %1; cvt.u32.u64 %0, t; }" : "=r"(a) : "l"(p));
    return a;
}
__device__ __forceinline__ void ldsm4(uint32_t* r, uint32_t a) {
    asm volatile("ldmatrix.sync.aligned.m8n8.x4.shared.b16 {%0,%1,%2,%3}, [%4];"
        : "=r"(r[0]), "=r"(r[1]), "=r"(r[2]), "=r"(r[3]) : "r"(a));
}
__device__ __forceinline__ void ldsm4t(uint32_t* r, uint32_t a) {
    asm volatile("ldmatrix.sync.aligned.m8n8.x4.trans.shared.b16 {%0,%1,%2,%3}, [%4];"
        : "=r"(r[0]), "=r"(r[1]), "=r"(r[2]), "=r"(r[3]) : "r"(a));
}
__device__ __forceinline__ void mma_(float* c, const uint32_t* a, uint32_t b0, uint32_t b1) {
    asm volatile("mma.sync.aligned.m16n8k16.row.col.f32.f16.f16.f32 "
        "{%0,%1,%2,%3},{%4,%5,%6,%7},{%8,%9},{%0,%1,%2,%3};"
        : "+f"(c[0]), "+f"(c[1]), "+f"(c[2]), "+f"(c[3])
        : "r"(a[0]), "r"(a[1]), "r"(a[2]), "r"(a[3]), "r"(b0), "r"(b1));
}
__device__ __forceinline__ uint32_t ex2h2(uint32_t x) {
    uint32_t r;
    asm("ex2.approx.f16x2 %0, %1;" : "=r"(r) : "r"(x));
    return r;
}
__device__ __forceinline__ uint32_t packh2(float a, float b) {
    __half2 h = __floats2half2_rn(a, b);
    return *(uint32_t*)&h;
}
__device__ __forceinline__ void cp16(uint32_t d, const void* s) {
    asm volatile("cp.async.cg.shared.global [%0], [%1], 16;" :: "r"(d), "l"(s) : "memory");
}
#define CPCOMMIT() asm volatile("cp.async.commit_group;" ::: "memory")
#define CPWAIT2()  asm volatile("cp.async.wait_group 2;" ::: "memory")
#define CPWAIT1()  asm volatile("cp.async.wait_group 1;" ::: "memory")
#define CPWAIT0()  asm volatile("cp.async.wait_group 0;" ::: "memory")

extern __shared__ __half dynsm[];

// ---- fused elementwise prep ------------------------------------------------
__global__ __launch_bounds__(256) void f2h(const float* __restrict__ Qin,
                                           const float* __restrict__ Kin) {
    const float* in = blockIdx.y ? Kin : Qin;
    __half* out = blockIdx.y ? g_kin16 : g_qin16;
    int i = blockIdx.x * 256 + threadIdx.x;
    float4 v = ((const float4*)in)[i];
    __half2 a = __floats2half2_rn(v.x, v.y), b = __floats2half2_rn(v.z, v.w);
    uint2 u = { *(uint32_t*)&a, *(uint32_t*)&b };
    ((uint2*)out)[i] = u;
}

__global__ __launch_bounds__(256) void wtr(const float* __restrict__ W0,
                                           const float* __restrict__ W1,
                                           const float* __restrict__ W2,
                                           const float* __restrict__ W3) {
    __shared__ float t[32][33];
    const int wz = blockIdx.z;
    const float* W = (wz == 0) ? W0 : (wz == 1) ? W1 : (wz == 2) ? W2 : W3;
    const int bx = blockIdx.x * 32, by = blockIdx.y * 32;
    const int tx = threadIdx.x & 31, ty = threadIdx.x >> 5;
    __half* Wt = g_wt[wz];
    #pragma unroll
    for (int i = 0; i < 4; i++)
        t[ty + 8 * i][tx] = W[(size_t)(bx + ty + 8 * i) * DD + by + tx];
    __syncthreads();
    #pragma unroll
    for (int i = 0; i < 4; i++)
        Wt[(size_t)(by + ty + 8 * i) * DD + bx + tx] = __float2half_rn(t[tx][ty + 8 * i]);
}

// ---- dense GEMM (triple-buffered cp.async, 1 sync/iter) --------------------
__global__ __launch_bounds__(256, 2)
void gemm_mma(const float* __restrict__ b0, const float* __restrict__ b1,
              const float* __restrict__ b2, int mode) {
    const int sel = mode ? 3 : blockIdx.z;
    const __half* A  = (sel == 0) ? g_qin16 : (sel == 3) ? g_x16 : g_kin16;
    const __half* Bt = g_wt[sel];
    const float* bias = (sel == 1) ? b1 : (sel == 2) ? b2 : b0;
    float*  C32 = (sel == 0) ? g_q32 : (sel == 3) ? g_y32 : nullptr;
    __half* C16 = (sel == 0) ? g_q16 : (sel == 1) ? g_k16 : (sel == 2) ? g_v16 : nullptr;
    const float cs = (sel == 1) ? ESF : 1.0f;

    const int tid = threadIdx.x, wid = tid >> 5, lane = tid & 31;
    const int wm = wid & 1, wn = wid >> 1;
    const int bm = blockIdx.y * 128, bn = blockIdx.x * 128;
    const uint32_t base = s2u(dynsm);
    const int lrA = lane & 15, lcA = (lane >> 4) * 8;
    const int lrB = (lane & 7) + ((lane >> 4) << 3), lcB = ((lane >> 3) & 1) * 8;

    auto issue = [&](int kc, int st) {
        uint32_t uA = base + st * TILE_B, uB = base + 3 * TILE_B + st * TILE_B;
        #pragma unroll
        for (int t = 0; t < 4; t++) {
            int idx = tid + t * 256, row = idx >> 3, c8 = (idx & 7) * 8;
            cp16(uA + (row * LDT + c8) * 2, &A [(size_t)(bm + row) * DD + kc * 64 + c8]);
            cp16(uB + (row * LDT + c8) * 2, &Bt[(size_t)(bn + row) * DD + kc * 64 + c8]);
        }
        CPCOMMIT();
    };

    float acc[4][4][4];
    #pragma unroll
    for (int i = 0; i < 4; i++)
        #pragma unroll
        for (int j = 0; j < 4; j++)
            #pragma unroll
            for (int k = 0; k < 4; k++) acc[i][j][k] = 0.0f;

    issue(0, 0);
    issue(1, 1);
    for (int kc = 0; kc < 8; kc++) {
        if (kc < 7) CPWAIT1(); else CPWAIT0();
        __syncthreads();
        if (kc + 2 < 8) issue(kc + 2, (kc + 2) % 3);
        const int st = kc % 3;
        const uint32_t cA = base + st * TILE_B, cB = base + 3 * TILE_B + st * TILE_B;
        #pragma unroll
        for (int kk = 0; kk < 4; kk++) {
            uint32_t af[4][4];
            #pragma unroll
            for (int mt = 0; mt < 4; mt++)
                ldsm4(af[mt], cA + ((wm * 64 + mt * 16 + lrA) * LDT + kk * 16 + lcA) * 2);
            #pragma unroll
            for (int p = 0; p < 2; p++) {
                uint32_t bf[4];
                ldsm4(bf, cB + ((wn * 32 + p * 16 + lrB) * LDT + kk * 16 + lcB) * 2);
                #pragma unroll
                for (int mt = 0; mt < 4; mt++) {
                    mma_(acc[mt][p * 2],     af[mt], bf[0], bf[1]);
                    mma_(acc[mt][p * 2 + 1], af[mt], bf[2], bf[3]);
                }
            }
        }
    }
    #pragma unroll
    for (int mt = 0; mt < 4; mt++) {
        int r0 = bm + wm * 64 + mt * 16 + (lane >> 2);
        #pragma unroll
        for (int nt = 0; nt < 4; nt++) {
            int c = bn + wn * 32 + nt * 8 + (lane & 3) * 2;
            float2 bb = *(const float2*)&bias[c];
            float d0 = acc[mt][nt][0] + bb.x, d1 = acc[mt][nt][1] + bb.y;
            float d2 = acc[mt][nt][2] + bb.x, d3 = acc[mt][nt][3] + bb.y;
            if (C32) {
                float2 o0 = {d0, d1}, o1 = {d2, d3};
                *(float2*)&C32[(size_t)r0 * DD + c] = o0;
                *(float2*)&C32[(size_t)(r0 + 8) * DD + c] = o1;
            }
            if (C16) {
                __half2 h0 = __floats2half2_rn(d0 * cs, d1 * cs);
                __half2 h1 = __floats2half2_rn(d2 * cs, d3 * cs);
                *(__half2*)&C16[(size_t)r0 * DD + c] = h0;
                *(__half2*)&C16[(size_t)(r0 + 8) * DD + c] = h1;
            }
        }
    }
}

// ---- pass 1: lrz_k = -log2( sum_q 2^(s_es) ) -------------------------------
// dyn smem: K @0 ; Q stages @18432, 36864, 55296 (73728 B)
__global__ __launch_bounds__(256, 3)
void stats_mma() {
    const int tid = threadIdx.x, wid = tid >> 5, lane = tid & 31;
    const int hb = blockIdx.y, h = hb >> 5, b = hb & 31, kb = blockIdx.x * 128;
    const uint32_t base = s2u(dynsm);
    const uint32_t uK = base;
    const int lrA = lane & 15, lcA = (lane >> 4) * 8;
    const int lrB = (lane & 7) + ((lane >> 4) << 3), lcB = ((lane >> 3) & 1) * 8;

    auto issueQ = [&](int qc, int st) {
        uint32_t uQ = base + (1 + st) * TILE_B;
        #pragma unroll
        for (int t = 0; t < 4; t++) {
            int idx = tid + t * 256, row = idx >> 3, c8 = (idx & 7) * 8;
            cp16(uQ + (row * LDT + c8) * 2,
                 &g_q16[(size_t)(b * NN + qc * 128 + row) * DD + h * HD + c8]);
        }
        CPCOMMIT();
    };

    #pragma unroll
    for (int t = 0; t < 4; t++) {
        int idx = tid + t * 256, row = idx >> 3, c8 = (idx & 7) * 8;
        cp16(uK + (row * LDT + c8) * 2,
             &g_k16[(size_t)(b * NN + kb + row) * DD + h * HD + c8]);
    }
    CPCOMMIT();
    issueQ(0, 0);
    issueQ(1, 1);
    CPWAIT2();
    __syncthreads();
    uint32_t af[4][4];
    #pragma unroll
    for (int kk = 0; kk < 4; kk++)
        ldsm4(af[kk], uK + ((wid * 16 + lrA) * LDT + kk * 16 + lcA) * 2);

    float z0a = 0.0f, z0b = 0.0f, z1a = 0.0f, z1b = 0.0f;
    for (int qc = 0; qc < 8; qc++) {
        if (qc < 7) CPWAIT1(); else CPWAIT0();
        __syncthreads();
        if (qc + 2 < 8) issueQ(qc + 2, (qc + 2) % 3);
        const uint32_t cQ = base + (1 + qc % 3) * TILE_B;
        #pragma unroll
        for (int hlf = 0; hlf < 2; hlf++) {
            float s[8][4];
            #pragma unroll
            for (int i = 0; i < 8; i++)
                #pragma unroll
                for (int j = 0; j < 4; j++) s[i][j] = 0.0f;
            #pragma unroll
            for (int kk = 0; kk < 4; kk++) {
                #pragma unroll
                for (int p = 0; p < 4; p++) {
                    uint32_t bf[4];
                    ldsm4(bf, cQ + (((hlf * 4 + p) * 16 + lrB) * LDT + kk * 16 + lcB) * 2);
                    mma_(s[2 * p],     af[kk], bf[0], bf[1]);
                    mma_(s[2 * p + 1], af[kk], bf[2], bf[3]);
                }
            }
            #pragma unroll
            for (int nt = 0; nt < 8; nt += 2) {
                uint32_t e0 = ex2h2(packh2(s[nt][0],     s[nt][1]));
                uint32_t e1 = ex2h2(packh2(s[nt + 1][0], s[nt + 1][1]));
                uint32_t e2 = ex2h2(packh2(s[nt][2],     s[nt][3]));
                uint32_t e3 = ex2h2(packh2(s[nt + 1][2], s[nt + 1][3]));
                float2 f0 = __half22float2(*(__half2*)&e0);
                float2 f1 = __half22float2(*(__half2*)&e1);
                float2 f2 = __half22float2(*(__half2*)&e2);
                float2 f3 = __half22float2(*(__half2*)&e3);
                z0a += f0.x + f0.y;
                z0b += f1.x + f1.y;
                z1a += f2.x + f2.y;
                z1b += f3.x + f3.y;
            }
        }
    }
    float z0 = z0a + z0b, z1 = z1a + z1b;
    z0 += __shfl_xor_sync(0xFFFFFFFFu, z0, 1);
    z0 += __shfl_xor_sync(0xFFFFFFFFu, z0, 2);
    z1 += __shfl_xor_sync(0xFFFFFFFFu, z1, 1);
    z1 += __shfl_xor_sync(0xFFFFFFFFu, z1, 2);
    if ((lane & 3) == 0) {
        int k = kb + wid * 16 + (lane >> 2);
        g_rz[hb * NN + k] = -__log2f(z0);
        g_rz[hb * NN + k + 8] = -__log2f(z1);
    }
}

// ---- pass 2: O = qh + 2^(S_es + lrz_k) @ V (ldsm.trans, no V transpose) ----
// dyn smem: Q @0 ; KV stages @18432+st*KV_STG (K 9216, V 9216, lrz 256)
__global__ __launch_bounds__(256, 3)
void attn_mma() {
    const int tid = threadIdx.x, wid = tid >> 5, lane = tid & 31;
    const int hb = blockIdx.y, h = hb >> 5, b = hb & 31, qb = blockIdx.x * 128;
    const uint32_t base = s2u(dynsm);
    const uint32_t uQ = base;
    const int lrA = lane & 15, lcA = (lane >> 4) * 8;
    const int lrB = (lane & 7) + ((lane >> 4) << 3), lcB = ((lane >> 3) & 1) * 8;
    // V trans-ldsm lane mapping: rows = k, cols = d
    const int lrV = (lane & 7) + (((lane >> 3) & 1) << 3);  // k within 16
    const int lcV = ((lane >> 4) & 1) * 8;                  // d within 16

    auto issueKV = [&](int kt, int st) {
        uint32_t uK = base + TILE_B + st * KV_STG;
        uint32_t uV = uK + 9216;
        uint32_t uL = uK + 18432;
        #pragma unroll
        for (int t = 0; t < 2; t++) {
            int idx = tid + t * 256, row = idx >> 3, c8 = (idx & 7) * 8;
            cp16(uK + (row * LDT + c8) * 2,
                 &g_k16[(size_t)(b * NN + kt * 64 + row) * DD + h * HD + c8]);
            cp16(uV + (row * LDT + c8) * 2,
                 &g_v16[(size_t)(b * NN + kt * 64 + row) * DD + h * HD + c8]);
        }
        if (tid < 16)
            cp16(uL + tid * 16, &g_rz[hb * NN + kt * 64 + tid * 4]);
        CPCOMMIT();
    };

    #pragma unroll
    for (int t = 0; t < 4; t++) {
        int idx = tid + t * 256, row = idx >> 3, c8 = (idx & 7) * 8;
        cp16(uQ + (row * LDT + c8) * 2,
             &g_q16[(size_t)(b * NN + qb + row) * DD + h * HD + c8]);
    }
    CPCOMMIT();
    issueKV(0, 0);
    issueKV(1, 1);
    CPWAIT2();
    __syncthreads();
    uint32_t af[4][4];
    #pragma unroll
    for (int kk = 0; kk < 4; kk++)
        ldsm4(af[kk], uQ + ((wid * 16 + lrA) * LDT + kk * 16 + lcA) * 2);

    float o[8][4];
    #pragma unroll
    for (int i = 0; i < 8; i++)
        #pragma unroll
        for (int j = 0; j < 4; j++) o[i][j] = 0.0f;

    for (int kt = 0; kt < 16; kt++) {
        if (kt < 15) CPWAIT1(); else CPWAIT0();
        __syncthreads();
        if (kt + 2 < 16) issueKV(kt + 2, (kt + 2) % 3);
        const int st = kt % 3;
        const uint32_t cK = base + TILE_B + st * KV_STG;
        const uint32_t cV = cK + 9216;
        const float* sL = (const float*)((char*)dynsm + TILE_B + st * KV_STG + 18432);

        #pragma unroll
        for (int g = 0; g < 4; g++) {
            float s[2][4];
            #pragma unroll
            for (int j = 0; j < 4; j++) { s[0][j] = 0.0f; s[1][j] = 0.0f; }
            #pragma unroll
            for (int kk = 0; kk < 4; kk++) {
                uint32_t bf[4];
                ldsm4(bf, cK + ((g * 16 + lrB) * LDT + kk * 16 + lcB) * 2);
                mma_(s[0], af[kk], bf[0], bf[1]);
                mma_(s[1], af[kk], bf[2], bf[3]);
            }
            float2 lo = *(const float2*)&sL[g * 16 + (lane & 3) * 2];
            float2 hi = *(const float2*)&sL[g * 16 + 8 + (lane & 3) * 2];
            uint32_t aw[4];
            aw[0] = ex2h2(packh2(s[0][0] + lo.x, s[0][1] + lo.y));
            aw[1] = ex2h2(packh2(s[0][2] + lo.x, s[0][3] + lo.y));
            aw[2] = ex2h2(packh2(s[1][0] + hi.x, s[1][1] + hi.y));
            aw[3] = ex2h2(packh2(s[1][2] + hi.x, s[1][3] + hi.y));
            #pragma unroll
            for (int p = 0; p < 4; p++) {
                uint32_t bf[4];
                ldsm4t(bf, cV + ((g * 16 + lrV) * LDT + p * 16 + lcV) * 2);
                mma_(o[2 * p],     aw, bf[0], bf[1]);
                mma_(o[2 * p + 1], aw, bf[2], bf[3]);
            }
        }
    }
    int q0 = b * NN + qb + wid * 16 + (lane >> 2);
    #pragma unroll
    for (int nt = 0; nt < 8; nt++) {
        int c = h * HD + nt * 8 + (lane & 3) * 2;
        float2 r0v = *(const float2*)&g_q32[(size_t)q0 * DD + c];
        float2 r1v = *(const float2*)&g_q32[(size_t)(q0 + 8) * DD + c];
        float2 o0 = {o[nt][0] + r0v.x, o[nt][1] + r0v.y};
        float2 o1 = {o[nt][2] + r1v.x, o[nt][3] + r1v.y};
        *(float2*)&g_o[(size_t)q0 * DD + c] = o0;
        *(float2*)&g_o[(size_t)(q0 + 8) * DD + c] = o1;
    }
}

// ---- LayerNorm -------------------------------------------------------------
__global__ __launch_bounds__(256)
void ln_kernel(const float* __restrict__ gamma, const float* __restrict__ beta,
               float* __restrict__ out, int mode) {
    const int row = (blockIdx.x * blockDim.x + threadIdx.x) >> 5;
    const int lane = threadIdx.x & 31;
    float4 v[4];
    if (mode == 0) {
        const float4* p = (const float4*)(g_o + (size_t)row * DD);
        #pragma unroll
        for (int i = 0; i < 4; i++) v[i] = p[lane + i * 32];
    } else {
        const float4* px = (const float4*)(g_x32 + (size_t)row * DD);
        const float4* py = (const float4*)(g_y32 + (size_t)row * DD);
        #pragma unroll
        for (int i = 0; i < 4; i++) {
            float4 a = px[lane + i * 32], bq = py[lane + i * 32];
            v[i].x = a.x + fmaxf(bq.x, 0.0f); v[i].y = a.y + fmaxf(bq.y, 0.0f);
            v[i].z = a.z + fmaxf(bq.z, 0.0f); v[i].w = a.w + fmaxf(bq.w, 0.0f);
        }
    }
    float s = 0.0f, ss = 0.0f;
    #pragma unroll
    for (int i = 0; i < 4; i++) {
        s  += v[i].x + v[i].y + v[i].z + v[i].w;
        ss += v[i].x*v[i].x + v[i].y*v[i].y + v[i].z*v[i].z + v[i].w*v[i].w;
    }
    #pragma unroll
    for (int off = 16; off > 0; off >>= 1) {
        s  += __shfl_xor_sync(0xFFFFFFFFu, s, off);
        ss += __shfl_xor_sync(0xFFFFFFFFu, ss, off);
    }
    const float mean = s * (1.0f / 512.0f);
    const float var  = ss * (1.0f / 512.0f) - mean * mean;
    const float rstd = rsqrtf(var + 1e-5f);
    #pragma unroll
    for (int i = 0; i < 4; i++) {
        int c0 = (lane + i * 32) * 4;
        float4 g4 = *(const float4*)&gamma[c0];
        float4 b4 = *(const float4*)&beta[c0];
        float4 ov;
        ov.x = (v[i].x - mean) * rstd * g4.x + b4.x;
        ov.y = (v[i].y - mean) * rstd * g4.y + b4.y;
        ov.z = (v[i].z - mean) * rstd * g4.z + b4.z;
        ov.w = (v[i].w - mean) * rstd * g4.w + b4.w;
        if (mode == 0) {
            *(float4*)(g_x32 + (size_t)row * DD + c0) = ov;
            __half2 h0 = __floats2half2_rn(ov.x, ov.y), h1 = __floats2half2_rn(ov.z, ov.w);
            uint2 u = { *(uint32_t*)&h0, *(uint32_t*)&h1 };
            *(uint2*)(g_x16 + (size_t)row * DD + c0) = u;
        } else {
            *(float4*)(out + (size_t)row * DD + c0) = ov;
        }
    }
}

// ---- launch ----------------------------------------------------------------
extern "C" void kernel_launch(void* const* d_in, const int* in_sizes, int n_in,
                              void* d_out, int out_size) {
    (void)in_sizes; (void)n_in; (void)out_size;
    const float* Q   = (const float*)d_in[0];
    const float* K   = (const float*)d_in[1];
    const float* Wq  = (const float*)d_in[2];
    const float* bq  = (const float*)d_in[3];
    const float* Wk  = (const float*)d_in[4];
    const float* bk  = (const float*)d_in[5];
    const float* Wv  = (const float*)d_in[6];
    const float* bv  = (const float*)d_in[7];
    const float* Wo  = (const float*)d_in[8];
    const float* bo  = (const float*)d_in[9];
    const float* g0  = (const float*)d_in[10];
    const float* be0 = (const float*)d_in[11];
    const float* g1  = (const float*)d_in[12];
    const float* be1 = (const float*)d_in[13];
    float* out = (float*)d_out;

    const int GEMM_SM  = 6 * TILE_B;               // 110592 B
    const int STATS_SM = 4 * TILE_B;               //  73728 B
    const int ATTN_SM  = TILE_B + 3 * KV_STG;      //  74496 B
    cudaFuncSetAttribute(gemm_mma,  cudaFuncAttributeMaxDynamicSharedMemorySize, GEMM_SM);
    cudaFuncSetAttribute(stats_mma, cudaFuncAttributeMaxDynamicSharedMemorySize, STATS_SM);
    cudaFuncSetAttribute(attn_mma,  cudaFuncAttributeMaxDynamicSharedMemorySize, ATTN_SM);

    f2h<<<dim3((MR * DD / 4) / 256, 2), 256>>>(Q, K);
    wtr<<<dim3(16, 16, 4), 256>>>(Wq, Wk, Wv, Wo);

    gemm_mma<<<dim3(4, 256, 3), 256, GEMM_SM>>>(bq, bk, bv, 0);  // QKV projections
    stats_mma<<<dim3(8, HBN), 256, STATS_SM>>>();                // lrz
    attn_mma<<<dim3(8, HBN), 256, ATTN_SM>>>();                  // g_o
    ln_kernel<<<MR / 8, 256>>>(g0, be0, out, 0);                 // g_x32, g_x16
    gemm_mma<<<dim3(4, 256, 1), 256, GEMM_SM>>>(bo, bo, bo, 1);  // g_y32
    ln_kernel<<<MR / 8, 256>>>(g1, be1, out, 1);                 // out
}